// round 1
// baseline (speedup 1.0000x reference)
#include <cuda_runtime.h>
#include <cuda_bf16.h>
#include <math.h>

// Problem constants
#define BATCH 2
#define SEQ   2048
#define DMODEL 1024
#define NHEADS 16
#define NKV    4
#define HDIM   64
#define ROWS   (BATCH * SEQ)          // 4096
#define DKV    (NKV * HDIM)           // 256

// ---------------- scratch (static __device__, no allocation) ----------------
__device__ float g_Q[ROWS * DMODEL];   // 16.8 MB
__device__ float g_K[ROWS * DKV];      // 4.2 MB
__device__ float g_V[ROWS * DKV];      // 4.2 MB
__device__ float g_A[ROWS * DMODEL];   // attention output, 16.8 MB

// ---------------- SGEMM: C[M,N] = A[M,K] @ B[K,N], tiles 128x128x8 ----------
__global__ __launch_bounds__(256) void sgemm128(const float* __restrict__ A,
                                                const float* __restrict__ B,
                                                float* __restrict__ C,
                                                int M, int N, int K) {
    __shared__ float As[8][128];   // A stored transposed: As[k][row]
    __shared__ float Bs[8][128];

    const int t = threadIdx.x;
    const int rowBase = blockIdx.y * 128;
    const int colBase = blockIdx.x * 128;
    const int tr = (t / 16) * 8;   // thread's row offset in tile
    const int tc = (t % 16) * 8;   // thread's col offset in tile

    // global-load assignments
    const int ar = t >> 1;             // 0..127
    const int ak = (t & 1) * 4;        // 0 or 4
    const int br = t >> 5;             // 0..7
    const int bc = (t & 31) * 4;       // 0..124

    float acc[8][8];
#pragma unroll
    for (int i = 0; i < 8; i++)
#pragma unroll
        for (int j = 0; j < 8; j++) acc[i][j] = 0.f;

    for (int k0 = 0; k0 < K; k0 += 8) {
        float4 av = *reinterpret_cast<const float4*>(
            &A[(size_t)(rowBase + ar) * K + k0 + ak]);
        float4 bv = *reinterpret_cast<const float4*>(
            &B[(size_t)(k0 + br) * N + colBase + bc]);
        As[ak + 0][ar] = av.x;
        As[ak + 1][ar] = av.y;
        As[ak + 2][ar] = av.z;
        As[ak + 3][ar] = av.w;
        *reinterpret_cast<float4*>(&Bs[br][bc]) = bv;
        __syncthreads();

#pragma unroll
        for (int k = 0; k < 8; k++) {
            float4 a0 = *reinterpret_cast<const float4*>(&As[k][tr]);
            float4 a1 = *reinterpret_cast<const float4*>(&As[k][tr + 4]);
            float4 b0 = *reinterpret_cast<const float4*>(&Bs[k][tc]);
            float4 b1 = *reinterpret_cast<const float4*>(&Bs[k][tc + 4]);
            float a[8] = {a0.x, a0.y, a0.z, a0.w, a1.x, a1.y, a1.z, a1.w};
            float b[8] = {b0.x, b0.y, b0.z, b0.w, b1.x, b1.y, b1.z, b1.w};
#pragma unroll
            for (int i = 0; i < 8; i++)
#pragma unroll
                for (int j = 0; j < 8; j++) acc[i][j] += a[i] * b[j];
        }
        __syncthreads();
    }

#pragma unroll
    for (int i = 0; i < 8; i++) {
        float* crow = &C[(size_t)(rowBase + tr + i) * N + colBase + tc];
        float4 o0 = make_float4(acc[i][0], acc[i][1], acc[i][2], acc[i][3]);
        float4 o1 = make_float4(acc[i][4], acc[i][5], acc[i][6], acc[i][7]);
        *reinterpret_cast<float4*>(crow) = o0;
        *reinterpret_cast<float4*>(crow + 4) = o1;
    }
}

// ---------------- RoPE (in place), optional output scale --------------------
// buf layout: [B*S, headsPerRow*64]; rotate pairs (j, j+32) within each head.
__global__ void rope_kernel(float* __restrict__ buf, int headsPerRow,
                            const int* __restrict__ offset_ptr, float scale,
                            int total) {
    int idx = blockIdx.x * blockDim.x + threadIdx.x;
    if (idx >= total) return;
    int j = idx & 31;
    int h = (idx >> 5) % headsPerRow;
    int row = idx / (32 * headsPerRow);     // b*SEQ + s
    int s = row & (SEQ - 1);
    int pos = s + offset_ptr[0];
    float inv = powf(10000.0f, -(float)j / 32.0f);
    float ang = (float)pos * inv;
    float c = cosf(ang), sn = sinf(ang);
    float* p = buf + (size_t)row * (headsPerRow * HDIM) + h * HDIM + j;
    float a = p[0];
    float b = p[32];
    p[0]  = (a * c - b * sn) * scale;
    p[32] = (b * c + a * sn) * scale;
}

// ---------------- Flash attention (causal, GQA) ------------------------------
// grid: (SEQ/64, NHEADS, BATCH), 256 threads.
// Q already scaled by 1/sqrt(HDIM).
#define ATTN_SMEM_FLOATS (64*65 + 64*64 + 64*64 + 64*65 + 256 + 256 + 64 + 64 + 64)
#define ATTN_SMEM_BYTES  (ATTN_SMEM_FLOATS * 4)

__global__ __launch_bounds__(256) void attn_kernel(const float* __restrict__ Q,
                                                   const float* __restrict__ K,
                                                   const float* __restrict__ V,
                                                   float* __restrict__ O) {
    extern __shared__ float sm[];
    float* sQ     = sm;                 // [64][65]
    float* sK     = sQ + 64 * 65;       // [64][64]
    float* sV     = sK + 64 * 64;       // [64][64]
    float* sS     = sV + 64 * 64;       // [64][65]
    float* sPmax  = sS + 64 * 65;       // [4][64]
    float* sPsum  = sPmax + 256;        // [4][64]
    float* sAlpha = sPsum + 256;        // [64]
    float* sM     = sAlpha + 64;        // [64]
    float* sL     = sM + 64;            // [64]

    const int qt = blockIdx.x;
    const int h  = blockIdx.y;
    const int b  = blockIdx.z;
    const int hkv = h >> 2;             // repeat_interleave: head h uses kv h/4
    const int t  = threadIdx.x;
    const int r  = t & 63;              // q-row within tile
    const int cb = t >> 6;              // 0..3: 16-col / 16-dim group
    const int q0 = qt * 64;

    const float* Qbase = Q + ((size_t)b * SEQ) * DMODEL + (size_t)h * HDIM;
    const float* Kbase = K + ((size_t)b * SEQ) * DKV + (size_t)hkv * HDIM;
    const float* Vbase = V + ((size_t)b * SEQ) * DKV + (size_t)hkv * HDIM;

    // stage Q tile, then pull this thread's q row into registers
    for (int i = t; i < 64 * 64; i += 256) {
        int rr = i >> 6, dd = i & 63;
        sQ[rr * 65 + dd] = Qbase[(size_t)(q0 + rr) * DMODEL + dd];
    }
    __syncthreads();

    float qreg[64];
#pragma unroll
    for (int d = 0; d < 64; d++) qreg[d] = sQ[r * 65 + d];

    float acc[16];
#pragma unroll
    for (int i = 0; i < 16; i++) acc[i] = 0.f;
    float m_old = -1e30f, lsum = 0.f;   // live in threads t<64 only

    const float4* sK4 = reinterpret_cast<const float4*>(sK);
    const float4* sV4 = reinterpret_cast<const float4*>(sV);

    for (int kt = 0; kt <= qt; kt++) {
        const int k0 = kt * 64;
        for (int i = t; i < 64 * 64; i += 256) {
            int rr = i >> 6, dd = i & 63;
            sK[rr * 64 + dd] = Kbase[(size_t)(k0 + rr) * DKV + dd];
            sV[rr * 64 + dd] = Vbase[(size_t)(k0 + rr) * DKV + dd];
        }
        __syncthreads();

        // ---- scores: each thread does 1 row x 16 cols, q in regs, K broadcast
        float localmax = -1e30f;
#pragma unroll
        for (int cc = 0; cc < 16; cc++) {
            int c = cb * 16 + cc;
            float s = 0.f;
#pragma unroll
            for (int d4 = 0; d4 < 16; d4++) {
                float4 kv = sK4[c * 16 + d4];
                s += qreg[d4 * 4 + 0] * kv.x;
                s += qreg[d4 * 4 + 1] * kv.y;
                s += qreg[d4 * 4 + 2] * kv.z;
                s += qreg[d4 * 4 + 3] * kv.w;
            }
            if (k0 + c > q0 + r) s = -1e30f;   // causal mask
            sS[r * 65 + c] = s;
            localmax = fmaxf(localmax, s);
        }
        sPmax[cb * 64 + r] = localmax;
        __syncthreads();

        // ---- per-row online-softmax state update (threads t<64)
        if (t < 64) {
            float mt = fmaxf(fmaxf(sPmax[r], sPmax[64 + r]),
                             fmaxf(sPmax[128 + r], sPmax[192 + r]));
            float m_new = fmaxf(m_old, mt);
            float alpha = __expf(m_old - m_new);
            sAlpha[r] = alpha;
            sM[r] = m_new;
            m_old = m_new;
            lsum *= alpha;
        }
        __syncthreads();

        // ---- exponentiate + partial row sums (all threads)
        float mrow = sM[r];
        float lpart = 0.f;
#pragma unroll
        for (int cc = 0; cc < 16; cc++) {
            int c = cb * 16 + cc;
            float e = __expf(sS[r * 65 + c] - mrow);
            sS[r * 65 + c] = e;
            lpart += e;
        }
        sPsum[cb * 64 + r] = lpart;
        __syncthreads();

        if (t < 64)
            lsum += sPsum[r] + sPsum[64 + r] + sPsum[128 + r] + sPsum[192 + r];

        // ---- accumulate P @ V : thread owns row r, dims [cb*16, cb*16+16)
        float alpha = sAlpha[r];
#pragma unroll
        for (int i = 0; i < 16; i++) acc[i] *= alpha;
#pragma unroll 4
        for (int c = 0; c < 64; c++) {
            float p = sS[r * 65 + c];
            float4 v0 = sV4[c * 16 + cb * 4 + 0];
            float4 v1 = sV4[c * 16 + cb * 4 + 1];
            float4 v2 = sV4[c * 16 + cb * 4 + 2];
            float4 v3 = sV4[c * 16 + cb * 4 + 3];
            acc[0]  += p * v0.x; acc[1]  += p * v0.y;
            acc[2]  += p * v0.z; acc[3]  += p * v0.w;
            acc[4]  += p * v1.x; acc[5]  += p * v1.y;
            acc[6]  += p * v1.z; acc[7]  += p * v1.w;
            acc[8]  += p * v2.x; acc[9]  += p * v2.y;
            acc[10] += p * v2.z; acc[11] += p * v2.w;
            acc[12] += p * v3.x; acc[13] += p * v3.y;
            acc[14] += p * v3.z; acc[15] += p * v3.w;
        }
        __syncthreads();   // before next tile overwrites sK/sV/sS
    }

    if (t < 64) sL[r] = lsum;
    __syncthreads();
    float inv_l = 1.0f / sL[r];

    // write to attention buffer in [B,S,H*Dh] layout (ready for O projection)
    float* Ob = O + ((size_t)b * SEQ + q0 + r) * DMODEL + h * HDIM + cb * 16;
#pragma unroll
    for (int i = 0; i < 4; i++) {
        float4 o = make_float4(acc[i * 4 + 0] * inv_l, acc[i * 4 + 1] * inv_l,
                               acc[i * 4 + 2] * inv_l, acc[i * 4 + 3] * inv_l);
        *reinterpret_cast<float4*>(Ob + i * 4) = o;
    }
}

// ---------------- launch ----------------------------------------------------
extern "C" void kernel_launch(void* const* d_in, const int* in_sizes, int n_in,
                              void* d_out, int out_size) {
    (void)in_sizes; (void)n_in; (void)out_size;
    const float* x  = (const float*)d_in[0];
    const float* Wq = (const float*)d_in[1];
    const float* Wk = (const float*)d_in[2];
    const float* Wv = (const float*)d_in[3];
    const float* Wo = (const float*)d_in[4];
    const int* poff = (const int*)d_in[5];
    float* out = (float*)d_out;

    float *Qb, *Kb, *Vb, *Ab;
    cudaGetSymbolAddress((void**)&Qb, g_Q);
    cudaGetSymbolAddress((void**)&Kb, g_K);
    cudaGetSymbolAddress((void**)&Vb, g_V);
    cudaGetSymbolAddress((void**)&Ab, g_A);

    // projections
    sgemm128<<<dim3(DMODEL / 128, ROWS / 128), 256>>>(x, Wq, Qb, ROWS, DMODEL, DMODEL);
    sgemm128<<<dim3(DKV / 128,    ROWS / 128), 256>>>(x, Wk, Kb, ROWS, DKV,    DMODEL);
    sgemm128<<<dim3(DKV / 128,    ROWS / 128), 256>>>(x, Wv, Vb, ROWS, DKV,    DMODEL);

    // RoPE (scale 1/sqrt(64) folded into Q)
    {
        int totQ = ROWS * NHEADS * 32;
        int totK = ROWS * NKV * 32;
        rope_kernel<<<(totQ + 255) / 256, 256>>>(Qb, NHEADS, poff, 0.125f, totQ);
        rope_kernel<<<(totK + 255) / 256, 256>>>(Kb, NKV, poff, 1.0f, totK);
    }

    // attention
    cudaFuncSetAttribute(attn_kernel, cudaFuncAttributeMaxDynamicSharedMemorySize,
                         ATTN_SMEM_BYTES);
    attn_kernel<<<dim3(SEQ / 64, NHEADS, BATCH), 256, ATTN_SMEM_BYTES>>>(Qb, Kb, Vb, Ab);

    // output projection
    sgemm128<<<dim3(DMODEL / 128, ROWS / 128), 256>>>(Ab, Wo, out, ROWS, DMODEL, DMODEL);
}

// round 3
// speedup vs baseline: 1.3958x; 1.3958x over previous
#include <cuda_runtime.h>
#include <cuda_bf16.h>
#include <math.h>
#include <cstdint>

// Problem constants
#define BATCH 2
#define SEQ   2048
#define DMODEL 1024
#define NHEADS 16
#define NKV    4
#define HDIM   64
#define ROWS   (BATCH * SEQ)          // 4096
#define DKV    (NKV * HDIM)           // 256
#define KDIM   1024

// ---------------- scratch (static __device__, no allocation) ----------------
__device__ float g_Q[ROWS * DMODEL];
__device__ float g_K[ROWS * DKV];
__device__ float g_V[ROWS * DKV];
__device__ float g_A[ROWS * DMODEL];
__device__ __nv_bfloat16 g_xhi[ROWS * DMODEL];     // also reused for attn-out split
__device__ __nv_bfloat16 g_xlo[ROWS * DMODEL];
__device__ __nv_bfloat16 g_wq_hi[DMODEL * KDIM];   // transposed weights [N,K]
__device__ __nv_bfloat16 g_wq_lo[DMODEL * KDIM];
__device__ __nv_bfloat16 g_wk_hi[DKV * KDIM];
__device__ __nv_bfloat16 g_wk_lo[DKV * KDIM];
__device__ __nv_bfloat16 g_wv_hi[DKV * KDIM];
__device__ __nv_bfloat16 g_wv_lo[DKV * KDIM];
__device__ __nv_bfloat16 g_wo_hi[DMODEL * KDIM];
__device__ __nv_bfloat16 g_wo_lo[DMODEL * KDIM];

__device__ __forceinline__ uint32_t smem_u32(const void* p) {
    uint32_t a;
    asm("{ .reg .u64 t; cvta.to.shared.u64 t, %1; cvt.u32.u64 %0, t; }"
        : "=r"(a) : "l"(p));
    return a;
}
#define SMEM_SWIZZLE_128B(off) ((off) ^ (((off) >> 3) & 0x70))

// ldmatrix x4 (four 8x8 b16 matrices)
__device__ __forceinline__ void ldsm_x4(uint32_t& r0, uint32_t& r1,
                                        uint32_t& r2, uint32_t& r3,
                                        uint32_t addr) {
    asm volatile("ldmatrix.sync.aligned.m8n8.x4.shared.b16 {%0,%1,%2,%3}, [%4];"
                 : "=r"(r0), "=r"(r1), "=r"(r2), "=r"(r3) : "r"(addr));
}

// mma m16n8k16 bf16 -> f32
__device__ __forceinline__ void mma16816(float* c, const uint32_t* a,
                                         const uint32_t* b) {
    asm volatile(
        "mma.sync.aligned.m16n8k16.row.col.f32.bf16.bf16.f32 "
        "{%0,%1,%2,%3}, {%4,%5,%6,%7}, {%8,%9}, {%0,%1,%2,%3};"
        : "+f"(c[0]), "+f"(c[1]), "+f"(c[2]), "+f"(c[3])
        : "r"(a[0]), "r"(a[1]), "r"(a[2]), "r"(a[3]), "r"(b[0]), "r"(b[1]));
}

// ---------------- split fp32 -> bf16 hi/lo (elementwise, vectorized) --------
__global__ void split_kernel(const float* __restrict__ x,
                             __nv_bfloat16* __restrict__ hi,
                             __nv_bfloat16* __restrict__ lo, int n4) {
    int i = blockIdx.x * blockDim.x + threadIdx.x;
    if (i >= n4) return;
    float4 v = reinterpret_cast<const float4*>(x)[i];
    __nv_bfloat16 h0 = __float2bfloat16(v.x), h1 = __float2bfloat16(v.y);
    __nv_bfloat16 h2 = __float2bfloat16(v.z), h3 = __float2bfloat16(v.w);
    __nv_bfloat16 l0 = __float2bfloat16(v.x - __bfloat162float(h0));
    __nv_bfloat16 l1 = __float2bfloat16(v.y - __bfloat162float(h1));
    __nv_bfloat16 l2 = __float2bfloat16(v.z - __bfloat162float(h2));
    __nv_bfloat16 l3 = __float2bfloat16(v.w - __bfloat162float(h3));
    __nv_bfloat162* hp = reinterpret_cast<__nv_bfloat162*>(hi) + 2 * i;
    __nv_bfloat162* lp = reinterpret_cast<__nv_bfloat162*>(lo) + 2 * i;
    hp[0] = __nv_bfloat162(h0, h1); hp[1] = __nv_bfloat162(h2, h3);
    lp[0] = __nv_bfloat162(l0, l1); lp[1] = __nv_bfloat162(l2, l3);
}

// ---------------- transpose + split: W[K,N] -> Wt_hi/lo[N,K] ----------------
__global__ void transpose_split(const float* __restrict__ W,
                                __nv_bfloat16* __restrict__ hi,
                                __nv_bfloat16* __restrict__ lo,
                                int K, int N) {
    __shared__ float tile[32][33];
    int kb = blockIdx.y * 32, nb = blockIdx.x * 32;
    int tx = threadIdx.x, ty = threadIdx.y;   // 32 x 8
    for (int i = ty; i < 32; i += 8)
        tile[i][tx] = W[(size_t)(kb + i) * N + nb + tx];
    __syncthreads();
    for (int i = ty; i < 32; i += 8) {
        float v = tile[tx][i];
        __nv_bfloat16 h = __float2bfloat16(v);
        __nv_bfloat16 l = __float2bfloat16(v - __bfloat162float(h));
        size_t o = (size_t)(nb + i) * K + kb + tx;
        hi[o] = h;
        lo[o] = l;
    }
}

// ---------------- mma.sync split-bf16 GEMM -----------------------------------
// C[M,N] = A[M,K] @ B^T with A[M,K] hi/lo, B[N,K] hi/lo (row-major each).
// CTA 128x128, 8 warps (4 m x 2 n), warp tile 32x64, k-chunk 64.
#define GEMM_SMEM_BYTES (64 * 1024 + 1024)

__global__ __launch_bounds__(256, 1) void gemm_mma3(
    const __nv_bfloat16* __restrict__ Ahi, const __nv_bfloat16* __restrict__ Alo,
    const __nv_bfloat16* __restrict__ Bhi, const __nv_bfloat16* __restrict__ Blo,
    float* __restrict__ C, int Ncols) {
    extern __shared__ char dsm[];
    const int t = threadIdx.x;
    const int wid = t >> 5;
    const int lid = t & 31;
    const int warp_m = wid & 3;        // 0..3  -> 32-row slice
    const int warp_n = wid >> 2;       // 0..1  -> 64-col slice
    const int rowBase = blockIdx.y * 128;
    const int colBase = blockIdx.x * 128;

    uint32_t base = (smem_u32(dsm) + 1023u) & ~1023u;
    char* sm = dsm + (base - smem_u32(dsm));
    char* sAhi = sm;
    char* sAlo = sm + 16384;
    char* sBhi = sm + 32768;
    char* sBlo = sm + 49152;

    float acc[2][8][4];
#pragma unroll
    for (int mb = 0; mb < 2; mb++)
#pragma unroll
        for (int nb = 0; nb < 8; nb++)
#pragma unroll
            for (int q = 0; q < 4; q++) acc[mb][nb][q] = 0.f;

    // per-thread ldmatrix address patterns (within a 128x64 bf16 tile, 128B rows)
    const int a_row = (lid & 15);               // + mb*16 + warp_m*32
    const int a_colB = (lid >> 4) * 16;         // + s*32
    const int b_rowl = ((lid >> 4) << 3) + (lid & 7);  // + p*16 + warp_n*64
    const int b_colB = ((lid >> 3) & 1) * 16;   // + s*32

    for (int ch = 0; ch < KDIM / 64; ch++) {
        const int k0 = ch * 64;
        // stage 4 tiles of [128 x 64 bf16], SW128-swizzled 16B stores
#pragma unroll
        for (int ii = 0; ii < 4; ii++) {
            int i = t + ii * 256;          // 0..1023
            int row = i >> 3;
            int kk = (i & 7) * 8;
            uint32_t sw = SMEM_SWIZZLE_128B((uint32_t)(row * 128 + kk * 2));
            size_t aoff = (size_t)(rowBase + row) * KDIM + k0 + kk;
            size_t boff = (size_t)(colBase + row) * KDIM + k0 + kk;
            *reinterpret_cast<float4*>(sAhi + sw) =
                *reinterpret_cast<const float4*>(Ahi + aoff);
            *reinterpret_cast<float4*>(sAlo + sw) =
                *reinterpret_cast<const float4*>(Alo + aoff);
            *reinterpret_cast<float4*>(sBhi + sw) =
                *reinterpret_cast<const float4*>(Bhi + boff);
            *reinterpret_cast<float4*>(sBlo + sw) =
                *reinterpret_cast<const float4*>(Blo + boff);
        }
        __syncthreads();

#pragma unroll
        for (int s = 0; s < 4; s++) {
            uint32_t ahi[2][4], alo[2][4], bhi[8][2], blo[8][2];
            // A fragments: two m16 blocks, hi & lo
#pragma unroll
            for (int mb = 0; mb < 2; mb++) {
                int row = warp_m * 32 + mb * 16 + a_row;
                uint32_t off = (uint32_t)(row * 128 + a_colB + s * 32);
                uint32_t sw = SMEM_SWIZZLE_128B(off);
                ldsm_x4(ahi[mb][0], ahi[mb][1], ahi[mb][2], ahi[mb][3],
                        smem_u32(sAhi) + sw);
                ldsm_x4(alo[mb][0], alo[mb][1], alo[mb][2], alo[mb][3],
                        smem_u32(sAlo) + sw);
            }
            // B fragments: 8 n8 blocks in 4 x4-loads, hi & lo
#pragma unroll
            for (int p = 0; p < 4; p++) {
                int row = warp_n * 64 + p * 16 + b_rowl;
                uint32_t off = (uint32_t)(row * 128 + b_colB + s * 32);
                uint32_t sw = SMEM_SWIZZLE_128B(off);
                ldsm_x4(bhi[2 * p][0], bhi[2 * p][1], bhi[2 * p + 1][0],
                        bhi[2 * p + 1][1], smem_u32(sBhi) + sw);
                ldsm_x4(blo[2 * p][0], blo[2 * p][1], blo[2 * p + 1][0],
                        blo[2 * p + 1][1], smem_u32(sBlo) + sw);
            }
#pragma unroll
            for (int nb = 0; nb < 8; nb++) {
#pragma unroll
                for (int mb = 0; mb < 2; mb++) {
                    mma16816(acc[mb][nb], ahi[mb], bhi[nb]);
                    mma16816(acc[mb][nb], ahi[mb], blo[nb]);
                    mma16816(acc[mb][nb], alo[mb], bhi[nb]);
                }
            }
        }
        __syncthreads();
    }

    // epilogue: c0,c1 -> (row g, col q*2..+1); c2,c3 -> row g+8
    const int g = lid >> 2;
    const int q = lid & 3;
#pragma unroll
    for (int mb = 0; mb < 2; mb++) {
#pragma unroll
        for (int nb = 0; nb < 8; nb++) {
            int row = rowBase + warp_m * 32 + mb * 16 + g;
            int col = colBase + warp_n * 64 + nb * 8 + q * 2;
            *reinterpret_cast<float2*>(&C[(size_t)row * Ncols + col]) =
                make_float2(acc[mb][nb][0], acc[mb][nb][1]);
            *reinterpret_cast<float2*>(&C[(size_t)(row + 8) * Ncols + col]) =
                make_float2(acc[mb][nb][2], acc[mb][nb][3]);
        }
    }
}

// ---------------- RoPE (in place), optional output scale --------------------
__global__ void rope_kernel(float* __restrict__ buf, int headsPerRow,
                            const int* __restrict__ offset_ptr, float scale,
                            int total) {
    int idx = blockIdx.x * blockDim.x + threadIdx.x;
    if (idx >= total) return;
    int j = idx & 31;
    int h = (idx >> 5) % headsPerRow;
    int row = idx / (32 * headsPerRow);
    int s = row & (SEQ - 1);
    int pos = s + offset_ptr[0];
    float inv = powf(10000.0f, -(float)j / 32.0f);
    float ang = (float)pos * inv;
    float c = cosf(ang), sn = sinf(ang);
    float* p = buf + (size_t)row * (headsPerRow * HDIM) + h * HDIM + j;
    float a = p[0];
    float b = p[32];
    p[0]  = (a * c - b * sn) * scale;
    p[32] = (b * c + a * sn) * scale;
}

// ---------------- Flash attention (causal, GQA) ------------------------------
#define ATTN_SMEM_FLOATS (64*65 + 64*64 + 64*64 + 64*65 + 256 + 256 + 64 + 64 + 64)
#define ATTN_SMEM_BYTES  (ATTN_SMEM_FLOATS * 4)

__global__ __launch_bounds__(256) void attn_kernel(const float* __restrict__ Q,
                                                   const float* __restrict__ K,
                                                   const float* __restrict__ V,
                                                   float* __restrict__ O) {
    extern __shared__ float smf[];
    float* sQ     = smf;
    float* sK     = sQ + 64 * 65;
    float* sV     = sK + 64 * 64;
    float* sS     = sV + 64 * 64;
    float* sPmax  = sS + 64 * 65;
    float* sPsum  = sPmax + 256;
    float* sAlpha = sPsum + 256;
    float* sM     = sAlpha + 64;
    float* sL     = sM + 64;

    const int qt = blockIdx.x;
    const int h  = blockIdx.y;
    const int b  = blockIdx.z;
    const int hkv = h >> 2;
    const int t  = threadIdx.x;
    const int r  = t & 63;
    const int cb = t >> 6;
    const int q0 = qt * 64;

    const float* Qbase = Q + ((size_t)b * SEQ) * DMODEL + (size_t)h * HDIM;
    const float* Kbase = K + ((size_t)b * SEQ) * DKV + (size_t)hkv * HDIM;
    const float* Vbase = V + ((size_t)b * SEQ) * DKV + (size_t)hkv * HDIM;

    for (int i = t; i < 64 * 64; i += 256) {
        int rr = i >> 6, dd = i & 63;
        sQ[rr * 65 + dd] = Qbase[(size_t)(q0 + rr) * DMODEL + dd];
    }
    __syncthreads();

    float qreg[64];
#pragma unroll
    for (int d = 0; d < 64; d++) qreg[d] = sQ[r * 65 + d];

    float acc[16];
#pragma unroll
    for (int i = 0; i < 16; i++) acc[i] = 0.f;
    float m_old = -1e30f, lsum = 0.f;

    const float4* sK4 = reinterpret_cast<const float4*>(sK);
    const float4* sV4 = reinterpret_cast<const float4*>(sV);

    for (int kt = 0; kt <= qt; kt++) {
        const int k0 = kt * 64;
        for (int i = t; i < 64 * 64; i += 256) {
            int rr = i >> 6, dd = i & 63;
            sK[rr * 64 + dd] = Kbase[(size_t)(k0 + rr) * DKV + dd];
            sV[rr * 64 + dd] = Vbase[(size_t)(k0 + rr) * DKV + dd];
        }
        __syncthreads();

        float localmax = -1e30f;
#pragma unroll
        for (int cc = 0; cc < 16; cc++) {
            int c = cb * 16 + cc;
            float s = 0.f;
#pragma unroll
            for (int d4 = 0; d4 < 16; d4++) {
                float4 kv = sK4[c * 16 + d4];
                s += qreg[d4 * 4 + 0] * kv.x;
                s += qreg[d4 * 4 + 1] * kv.y;
                s += qreg[d4 * 4 + 2] * kv.z;
                s += qreg[d4 * 4 + 3] * kv.w;
            }
            if (k0 + c > q0 + r) s = -1e30f;
            sS[r * 65 + c] = s;
            localmax = fmaxf(localmax, s);
        }
        sPmax[cb * 64 + r] = localmax;
        __syncthreads();

        if (t < 64) {
            float mt = fmaxf(fmaxf(sPmax[r], sPmax[64 + r]),
                             fmaxf(sPmax[128 + r], sPmax[192 + r]));
            float m_new = fmaxf(m_old, mt);
            float alpha = __expf(m_old - m_new);
            sAlpha[r] = alpha;
            sM[r] = m_new;
            m_old = m_new;
            lsum *= alpha;
        }
        __syncthreads();

        float mrow = sM[r];
        float lpart = 0.f;
#pragma unroll
        for (int cc = 0; cc < 16; cc++) {
            int c = cb * 16 + cc;
            float e = __expf(sS[r * 65 + c] - mrow);
            sS[r * 65 + c] = e;
            lpart += e;
        }
        sPsum[cb * 64 + r] = lpart;
        __syncthreads();

        if (t < 64)
            lsum += sPsum[r] + sPsum[64 + r] + sPsum[128 + r] + sPsum[192 + r];

        float alpha = sAlpha[r];
#pragma unroll
        for (int i = 0; i < 16; i++) acc[i] *= alpha;
#pragma unroll 4
        for (int c = 0; c < 64; c++) {
            float p = sS[r * 65 + c];
            float4 v0 = sV4[c * 16 + cb * 4 + 0];
            float4 v1 = sV4[c * 16 + cb * 4 + 1];
            float4 v2 = sV4[c * 16 + cb * 4 + 2];
            float4 v3 = sV4[c * 16 + cb * 4 + 3];
            acc[0]  += p * v0.x; acc[1]  += p * v0.y;
            acc[2]  += p * v0.z; acc[3]  += p * v0.w;
            acc[4]  += p * v1.x; acc[5]  += p * v1.y;
            acc[6]  += p * v1.z; acc[7]  += p * v1.w;
            acc[8]  += p * v2.x; acc[9]  += p * v2.y;
            acc[10] += p * v2.z; acc[11] += p * v2.w;
            acc[12] += p * v3.x; acc[13] += p * v3.y;
            acc[14] += p * v3.z; acc[15] += p * v3.w;
        }
        __syncthreads();
    }

    if (t < 64) sL[r] = lsum;
    __syncthreads();
    float inv_l = 1.0f / sL[r];

    float* Ob = O + ((size_t)b * SEQ + q0 + r) * DMODEL + h * HDIM + cb * 16;
#pragma unroll
    for (int i = 0; i < 4; i++) {
        float4 o = make_float4(acc[i * 4 + 0] * inv_l, acc[i * 4 + 1] * inv_l,
                               acc[i * 4 + 2] * inv_l, acc[i * 4 + 3] * inv_l);
        *reinterpret_cast<float4*>(Ob + i * 4) = o;
    }
}

// ---------------- launch ----------------------------------------------------
extern "C" void kernel_launch(void* const* d_in, const int* in_sizes, int n_in,
                              void* d_out, int out_size) {
    (void)in_sizes; (void)n_in; (void)out_size;
    const float* x  = (const float*)d_in[0];
    const float* Wq = (const float*)d_in[1];
    const float* Wk = (const float*)d_in[2];
    const float* Wv = (const float*)d_in[3];
    const float* Wo = (const float*)d_in[4];
    const int* poff = (const int*)d_in[5];
    float* out = (float*)d_out;

    float *Qb, *Kb, *Vb, *Ab;
    __nv_bfloat16 *xhi, *xlo, *wqh, *wql, *wkh, *wkl, *wvh, *wvl, *woh, *wol;
    cudaGetSymbolAddress((void**)&Qb, g_Q);
    cudaGetSymbolAddress((void**)&Kb, g_K);
    cudaGetSymbolAddress((void**)&Vb, g_V);
    cudaGetSymbolAddress((void**)&Ab, g_A);
    cudaGetSymbolAddress((void**)&xhi, g_xhi);
    cudaGetSymbolAddress((void**)&xlo, g_xlo);
    cudaGetSymbolAddress((void**)&wqh, g_wq_hi);
    cudaGetSymbolAddress((void**)&wql, g_wq_lo);
    cudaGetSymbolAddress((void**)&wkh, g_wk_hi);
    cudaGetSymbolAddress((void**)&wkl, g_wk_lo);
    cudaGetSymbolAddress((void**)&wvh, g_wv_hi);
    cudaGetSymbolAddress((void**)&wvl, g_wv_lo);
    cudaGetSymbolAddress((void**)&woh, g_wo_hi);
    cudaGetSymbolAddress((void**)&wol, g_wo_lo);

    cudaFuncSetAttribute(gemm_mma3, cudaFuncAttributeMaxDynamicSharedMemorySize,
                         GEMM_SMEM_BYTES);
    cudaFuncSetAttribute(attn_kernel, cudaFuncAttributeMaxDynamicSharedMemorySize,
                         ATTN_SMEM_BYTES);

    // split x, transpose+split weights
    split_kernel<<<(ROWS * DMODEL / 4 + 255) / 256, 256>>>(x, xhi, xlo, ROWS * DMODEL / 4);
    transpose_split<<<dim3(DMODEL / 32, KDIM / 32), dim3(32, 8)>>>(Wq, wqh, wql, KDIM, DMODEL);
    transpose_split<<<dim3(DKV / 32,    KDIM / 32), dim3(32, 8)>>>(Wk, wkh, wkl, KDIM, DKV);
    transpose_split<<<dim3(DKV / 32,    KDIM / 32), dim3(32, 8)>>>(Wv, wvh, wvl, KDIM, DKV);
    transpose_split<<<dim3(DMODEL / 32, KDIM / 32), dim3(32, 8)>>>(Wo, woh, wol, KDIM, DMODEL);

    // projections (tensor cores via mma.sync)
    gemm_mma3<<<dim3(DMODEL / 128, ROWS / 128), 256, GEMM_SMEM_BYTES>>>(
        xhi, xlo, wqh, wql, Qb, DMODEL);
    gemm_mma3<<<dim3(DKV / 128, ROWS / 128), 256, GEMM_SMEM_BYTES>>>(
        xhi, xlo, wkh, wkl, Kb, DKV);
    gemm_mma3<<<dim3(DKV / 128, ROWS / 128), 256, GEMM_SMEM_BYTES>>>(
        xhi, xlo, wvh, wvl, Vb, DKV);

    // RoPE (1/sqrt(64) folded into Q)
    {
        int totQ = ROWS * NHEADS * 32;
        int totK = ROWS * NKV * 32;
        rope_kernel<<<(totQ + 255) / 256, 256>>>(Qb, NHEADS, poff, 0.125f, totQ);
        rope_kernel<<<(totK + 255) / 256, 256>>>(Kb, NKV, poff, 1.0f, totK);
    }

    // attention
    attn_kernel<<<dim3(SEQ / 64, NHEADS, BATCH), 256, ATTN_SMEM_BYTES>>>(Qb, Kb, Vb, Ab);

    // split attention output, O projection
    split_kernel<<<(ROWS * DMODEL / 4 + 255) / 256, 256>>>(Ab, xhi, xlo, ROWS * DMODEL / 4);
    gemm_mma3<<<dim3(DMODEL / 128, ROWS / 128), 256, GEMM_SMEM_BYTES>>>(
        xhi, xlo, woh, wol, out, DMODEL);
}

// round 5
// speedup vs baseline: 2.9200x; 2.0921x over previous
#include <cuda_runtime.h>
#include <cuda_bf16.h>
#include <math.h>
#include <cstdint>

// Problem constants
#define BATCH 2
#define SEQ   2048
#define DMODEL 1024
#define NHEADS 16
#define NKV    4
#define HDIM   64
#define ROWS   (BATCH * SEQ)          // 4096
#define DKV    (NKV * HDIM)           // 256
#define KDIM   1024

// ---------------- scratch (static __device__, no allocation) ----------------
__device__ float g_Q[ROWS * DMODEL];
__device__ float g_K[ROWS * DKV];
__device__ float g_V[ROWS * DKV];
__device__ float g_A[ROWS * DMODEL];
__device__ __nv_bfloat16 g_xhi[ROWS * DMODEL];
__device__ __nv_bfloat16 g_xlo[ROWS * DMODEL];
__device__ __nv_bfloat16 g_Khi[ROWS * DKV];
__device__ __nv_bfloat16 g_Klo[ROWS * DKV];
__device__ __nv_bfloat16 g_Vhi[ROWS * DKV];
__device__ __nv_bfloat16 g_Vlo[ROWS * DKV];
__device__ __nv_bfloat16 g_wq_hi[DMODEL * KDIM];
__device__ __nv_bfloat16 g_wq_lo[DMODEL * KDIM];
__device__ __nv_bfloat16 g_wk_hi[DKV * KDIM];
__device__ __nv_bfloat16 g_wk_lo[DKV * KDIM];
__device__ __nv_bfloat16 g_wv_hi[DKV * KDIM];
__device__ __nv_bfloat16 g_wv_lo[DKV * KDIM];
__device__ __nv_bfloat16 g_wo_hi[DMODEL * KDIM];
__device__ __nv_bfloat16 g_wo_lo[DMODEL * KDIM];

__device__ __forceinline__ uint32_t smem_u32(const void* p) {
    uint32_t a;
    asm("{ .reg .u64 t; cvta.to.shared.u64 t, %1; cvt.u32.u64 %0, t; }"
        : "=r"(a) : "l"(p));
    return a;
}
#define SMEM_SWIZZLE_128B(off) ((off) ^ (((off) >> 3) & 0x70))

__device__ __forceinline__ void ldsm_x4(uint32_t& r0, uint32_t& r1,
                                        uint32_t& r2, uint32_t& r3,
                                        uint32_t addr) {
    asm volatile("ldmatrix.sync.aligned.m8n8.x4.shared.b16 {%0,%1,%2,%3}, [%4];"
                 : "=r"(r0), "=r"(r1), "=r"(r2), "=r"(r3) : "r"(addr));
}
__device__ __forceinline__ void ldsm_x4_t(uint32_t& r0, uint32_t& r1,
                                          uint32_t& r2, uint32_t& r3,
                                          uint32_t addr) {
    asm volatile("ldmatrix.sync.aligned.m8n8.x4.trans.shared.b16 {%0,%1,%2,%3}, [%4];"
                 : "=r"(r0), "=r"(r1), "=r"(r2), "=r"(r3) : "r"(addr));
}
__device__ __forceinline__ void mma16816(float* c, const uint32_t* a,
                                         const uint32_t* b) {
    asm volatile(
        "mma.sync.aligned.m16n8k16.row.col.f32.bf16.bf16.f32 "
        "{%0,%1,%2,%3}, {%4,%5,%6,%7}, {%8,%9}, {%0,%1,%2,%3};"
        : "+f"(c[0]), "+f"(c[1]), "+f"(c[2]), "+f"(c[3])
        : "r"(a[0]), "r"(a[1]), "r"(a[2]), "r"(a[3]), "r"(b[0]), "r"(b[1]));
}
__device__ __forceinline__ uint32_t packbf(float lo, float hi) {
    __nv_bfloat162 t = __floats2bfloat162_rn(lo, hi);   // .x -> low 16 bits
    return *reinterpret_cast<uint32_t*>(&t);
}
__device__ __forceinline__ float bfres(float c) {
    return c - __bfloat162float(__float2bfloat16(c));
}

// ---------------- split fp32 -> bf16 hi/lo -----------------------------------
__global__ void split_kernel(const float* __restrict__ x,
                             __nv_bfloat16* __restrict__ hi,
                             __nv_bfloat16* __restrict__ lo, int n4) {
    int i = blockIdx.x * blockDim.x + threadIdx.x;
    if (i >= n4) return;
    float4 v = reinterpret_cast<const float4*>(x)[i];
    __nv_bfloat16 h0 = __float2bfloat16(v.x), h1 = __float2bfloat16(v.y);
    __nv_bfloat16 h2 = __float2bfloat16(v.z), h3 = __float2bfloat16(v.w);
    __nv_bfloat16 l0 = __float2bfloat16(v.x - __bfloat162float(h0));
    __nv_bfloat16 l1 = __float2bfloat16(v.y - __bfloat162float(h1));
    __nv_bfloat16 l2 = __float2bfloat16(v.z - __bfloat162float(h2));
    __nv_bfloat16 l3 = __float2bfloat16(v.w - __bfloat162float(h3));
    __nv_bfloat162* hp = reinterpret_cast<__nv_bfloat162*>(hi) + 2 * i;
    __nv_bfloat162* lp = reinterpret_cast<__nv_bfloat162*>(lo) + 2 * i;
    hp[0] = __nv_bfloat162(h0, h1); hp[1] = __nv_bfloat162(h2, h3);
    lp[0] = __nv_bfloat162(l0, l1); lp[1] = __nv_bfloat162(l2, l3);
}

// ---------------- transpose + split: W[K,N] -> Wt_hi/lo[N,K] ----------------
__global__ void transpose_split(const float* __restrict__ W,
                                __nv_bfloat16* __restrict__ hi,
                                __nv_bfloat16* __restrict__ lo,
                                int K, int N) {
    __shared__ float tile[32][33];
    int kb = blockIdx.y * 32, nb = blockIdx.x * 32;
    int tx = threadIdx.x, ty = threadIdx.y;
    for (int i = ty; i < 32; i += 8)
        tile[i][tx] = W[(size_t)(kb + i) * N + nb + tx];
    __syncthreads();
    for (int i = ty; i < 32; i += 8) {
        float v = tile[tx][i];
        __nv_bfloat16 h = __float2bfloat16(v);
        __nv_bfloat16 l = __float2bfloat16(v - __bfloat162float(h));
        size_t o = (size_t)(nb + i) * K + kb + tx;
        hi[o] = h;
        lo[o] = l;
    }
}

// ---------------- mma.sync split-bf16 GEMM -----------------------------------
#define GEMM_SMEM_BYTES (64 * 1024 + 1024)

__global__ __launch_bounds__(256, 1) void gemm_mma3(
    const __nv_bfloat16* __restrict__ Ahi, const __nv_bfloat16* __restrict__ Alo,
    const __nv_bfloat16* __restrict__ Bhi, const __nv_bfloat16* __restrict__ Blo,
    float* __restrict__ C, int Ncols) {
    extern __shared__ char dsm[];
    const int t = threadIdx.x;
    const int wid = t >> 5;
    const int lid = t & 31;
    const int warp_m = wid & 3;
    const int warp_n = wid >> 2;
    const int rowBase = blockIdx.y * 128;
    const int colBase = blockIdx.x * 128;

    uint32_t base = (smem_u32(dsm) + 1023u) & ~1023u;
    char* sm = dsm + (base - smem_u32(dsm));
    char* sAhi = sm;
    char* sAlo = sm + 16384;
    char* sBhi = sm + 32768;
    char* sBlo = sm + 49152;

    float acc[2][8][4];
#pragma unroll
    for (int mb = 0; mb < 2; mb++)
#pragma unroll
        for (int nb = 0; nb < 8; nb++)
#pragma unroll
            for (int q = 0; q < 4; q++) acc[mb][nb][q] = 0.f;

    const int a_row = (lid & 15);
    const int a_colB = (lid >> 4) * 16;
    const int b_rowl = ((lid >> 4) << 3) + (lid & 7);
    const int b_colB = ((lid >> 3) & 1) * 16;

    for (int ch = 0; ch < KDIM / 64; ch++) {
        const int k0 = ch * 64;
#pragma unroll
        for (int ii = 0; ii < 4; ii++) {
            int i = t + ii * 256;
            int row = i >> 3;
            int kk = (i & 7) * 8;
            uint32_t sw = SMEM_SWIZZLE_128B((uint32_t)(row * 128 + kk * 2));
            size_t aoff = (size_t)(rowBase + row) * KDIM + k0 + kk;
            size_t boff = (size_t)(colBase + row) * KDIM + k0 + kk;
            *reinterpret_cast<float4*>(sAhi + sw) =
                *reinterpret_cast<const float4*>(Ahi + aoff);
            *reinterpret_cast<float4*>(sAlo + sw) =
                *reinterpret_cast<const float4*>(Alo + aoff);
            *reinterpret_cast<float4*>(sBhi + sw) =
                *reinterpret_cast<const float4*>(Bhi + boff);
            *reinterpret_cast<float4*>(sBlo + sw) =
                *reinterpret_cast<const float4*>(Blo + boff);
        }
        __syncthreads();

#pragma unroll
        for (int s = 0; s < 4; s++) {
            uint32_t ahi[2][4], alo[2][4], bhi[8][2], blo[8][2];
#pragma unroll
            for (int mb = 0; mb < 2; mb++) {
                int row = warp_m * 32 + mb * 16 + a_row;
                uint32_t off = (uint32_t)(row * 128 + a_colB + s * 32);
                uint32_t sw = SMEM_SWIZZLE_128B(off);
                ldsm_x4(ahi[mb][0], ahi[mb][1], ahi[mb][2], ahi[mb][3],
                        smem_u32(sAhi) + sw);
                ldsm_x4(alo[mb][0], alo[mb][1], alo[mb][2], alo[mb][3],
                        smem_u32(sAlo) + sw);
            }
#pragma unroll
            for (int p = 0; p < 4; p++) {
                int row = warp_n * 64 + p * 16 + b_rowl;
                uint32_t off = (uint32_t)(row * 128 + b_colB + s * 32);
                uint32_t sw = SMEM_SWIZZLE_128B(off);
                ldsm_x4(bhi[2 * p][0], bhi[2 * p][1], bhi[2 * p + 1][0],
                        bhi[2 * p + 1][1], smem_u32(sBhi) + sw);
                ldsm_x4(blo[2 * p][0], blo[2 * p][1], blo[2 * p + 1][0],
                        blo[2 * p + 1][1], smem_u32(sBlo) + sw);
            }
#pragma unroll
            for (int nb = 0; nb < 8; nb++) {
#pragma unroll
                for (int mb = 0; mb < 2; mb++) {
                    mma16816(acc[mb][nb], ahi[mb], bhi[nb]);
                    mma16816(acc[mb][nb], ahi[mb], blo[nb]);
                    mma16816(acc[mb][nb], alo[mb], bhi[nb]);
                }
            }
        }
        __syncthreads();
    }

    const int g = lid >> 2;
    const int q = lid & 3;
#pragma unroll
    for (int mb = 0; mb < 2; mb++) {
#pragma unroll
        for (int nb = 0; nb < 8; nb++) {
            int row = rowBase + warp_m * 32 + mb * 16 + g;
            int col = colBase + warp_n * 64 + nb * 8 + q * 2;
            *reinterpret_cast<float2*>(&C[(size_t)row * Ncols + col]) =
                make_float2(acc[mb][nb][0], acc[mb][nb][1]);
            *reinterpret_cast<float2*>(&C[(size_t)(row + 8) * Ncols + col]) =
                make_float2(acc[mb][nb][2], acc[mb][nb][3]);
        }
    }
}

// ---------------- RoPE (in place) --------------------------------------------
__global__ void rope_kernel(float* __restrict__ buf, int headsPerRow,
                            const int* __restrict__ offset_ptr, float scale,
                            int total) {
    int idx = blockIdx.x * blockDim.x + threadIdx.x;
    if (idx >= total) return;
    int j = idx & 31;
    int h = (idx >> 5) % headsPerRow;
    int row = idx / (32 * headsPerRow);
    int s = row & (SEQ - 1);
    int pos = s + offset_ptr[0];
    float inv = powf(10000.0f, -(float)j / 32.0f);
    float ang = (float)pos * inv;
    float c = cosf(ang), sn = sinf(ang);
    float* p = buf + (size_t)row * (headsPerRow * HDIM) + h * HDIM + j;
    float a = p[0];
    float b = p[32];
    p[0]  = (a * c - b * sn) * scale;
    p[32] = (b * c + a * sn) * scale;
}

// ---------------- tensor-core flash attention (causal, GQA) ------------------
// CTA: 128 q-rows x 1 head. 8 warps, warp = m16 slice. K-tile 64.
#define ATTN2_SMEM (65536 + 1024)

__global__ __launch_bounds__(256, 1) void attn_mma(
    const float* __restrict__ Q,
    const __nv_bfloat16* __restrict__ Khi, const __nv_bfloat16* __restrict__ Klo,
    const __nv_bfloat16* __restrict__ Vhi, const __nv_bfloat16* __restrict__ Vlo,
    float* __restrict__ O) {
    extern __shared__ char dsm[];
    uint32_t base = (smem_u32(dsm) + 1023u) & ~1023u;
    char* sm = dsm + (base - smem_u32(dsm));
    char* sQhi = sm;
    char* sQlo = sm + 16384;
    char* sKhi = sm + 32768;
    char* sKlo = sm + 40960;
    char* sVhi = sm + 49152;
    char* sVlo = sm + 57344;

    const int qt = (int)gridDim.x - 1 - (int)blockIdx.x;   // heavy CTAs first
    const int h  = blockIdx.y;
    const int b  = blockIdx.z;
    const int hkv = h >> 2;
    const int t  = threadIdx.x;
    const int wid = t >> 5;
    const int lid = t & 31;
    const int g = lid >> 2;
    const int qd = lid & 3;
    const int q0 = qt * 128;

    // ---- stage Q tile [128 x 64] fp32 -> hi/lo bf16, swizzled
    // 128 rows x 8 chunks of 16B = 1024 items (each item: one 16B hi + 16B lo)
    const float* Qbase = Q + (((size_t)b * SEQ + q0) * NHEADS + h) * HDIM;
#pragma unroll
    for (int ii = 0; ii < 4; ii++) {
        int idx = t + ii * 256;            // 0..1023
        int row = idx >> 3;
        int ch = idx & 7;                  // 8-dim chunk
        const float4* src = reinterpret_cast<const float4*>(
            Qbase + (size_t)row * NHEADS * HDIM + ch * 8);
        float4 v0 = src[0], v1 = src[1];
        uint32_t hpk[4], lpk[4];
        hpk[0] = packbf(v0.x, v0.y); hpk[1] = packbf(v0.z, v0.w);
        hpk[2] = packbf(v1.x, v1.y); hpk[3] = packbf(v1.z, v1.w);
        lpk[0] = packbf(bfres(v0.x), bfres(v0.y));
        lpk[1] = packbf(bfres(v0.z), bfres(v0.w));
        lpk[2] = packbf(bfres(v1.x), bfres(v1.y));
        lpk[3] = packbf(bfres(v1.z), bfres(v1.w));
        uint32_t sw = SMEM_SWIZZLE_128B((uint32_t)(row * 128 + ch * 16));
        *reinterpret_cast<uint4*>(sQhi + sw) = make_uint4(hpk[0], hpk[1], hpk[2], hpk[3]);
        *reinterpret_cast<uint4*>(sQlo + sw) = make_uint4(lpk[0], lpk[1], lpk[2], lpk[3]);
    }
    __syncthreads();

    // ---- Q fragments in registers (held across all k-tiles)
    uint32_t qh[4][4], ql[4][4];
    {
        int arow = wid * 16 + (lid & 15);
        int acolB = (lid >> 4) * 16;
#pragma unroll
        for (int s = 0; s < 4; s++) {
            uint32_t sw = SMEM_SWIZZLE_128B((uint32_t)(arow * 128 + acolB + s * 32));
            ldsm_x4(qh[s][0], qh[s][1], qh[s][2], qh[s][3], smem_u32(sQhi) + sw);
            ldsm_x4(ql[s][0], ql[s][1], ql[s][2], ql[s][3], smem_u32(sQlo) + sw);
        }
    }

    float o[8][4];
#pragma unroll
    for (int nb = 0; nb < 8; nb++)
#pragma unroll
        for (int q = 0; q < 4; q++) o[nb][q] = 0.f;
    float m0 = -1e30f, m1 = -1e30f, l0 = 0.f, l1 = 0.f;

    const size_t kvbase = ((size_t)b * SEQ) * DKV + (size_t)hkv * HDIM;
    const int ntiles = 2 * qt + 2;

    for (int kt = 0; kt < ntiles; kt++) {
        const int k0 = kt * 64;
        // ---- stage K/V hi/lo tiles [64 x 64]: 64 rows x 8 chunks = 512 items
#pragma unroll
        for (int ii = 0; ii < 2; ii++) {
            int idx = t + ii * 256;        // 0..511
            int row = idx >> 3;
            int ch = idx & 7;
            uint32_t sw = SMEM_SWIZZLE_128B((uint32_t)(row * 128 + ch * 16));
            size_t gl = kvbase + (size_t)(k0 + row) * DKV + ch * 8;
            *reinterpret_cast<uint4*>(sKhi + sw) = *reinterpret_cast<const uint4*>(Khi + gl);
            *reinterpret_cast<uint4*>(sKlo + sw) = *reinterpret_cast<const uint4*>(Klo + gl);
            *reinterpret_cast<uint4*>(sVhi + sw) = *reinterpret_cast<const uint4*>(Vhi + gl);
            *reinterpret_cast<uint4*>(sVlo + sw) = *reinterpret_cast<const uint4*>(Vlo + gl);
        }
        __syncthreads();

        // ---- S = Q K^T (3-term split)
        float sacc[8][4];
#pragma unroll
        for (int nb = 0; nb < 8; nb++)
#pragma unroll
            for (int q = 0; q < 4; q++) sacc[nb][q] = 0.f;

        {
            int brow = ((lid >> 4) << 3) + (lid & 7);
            int bcolB = ((lid >> 3) & 1) * 16;
#pragma unroll
            for (int s = 0; s < 4; s++) {
                uint32_t kh[8][2], kl[8][2];
#pragma unroll
                for (int p = 0; p < 4; p++) {
                    uint32_t sw = SMEM_SWIZZLE_128B(
                        (uint32_t)((p * 16 + brow) * 128 + bcolB + s * 32));
                    ldsm_x4(kh[2 * p][0], kh[2 * p][1], kh[2 * p + 1][0],
                            kh[2 * p + 1][1], smem_u32(sKhi) + sw);
                    ldsm_x4(kl[2 * p][0], kl[2 * p][1], kl[2 * p + 1][0],
                            kl[2 * p + 1][1], smem_u32(sKlo) + sw);
                }
#pragma unroll
                for (int nb = 0; nb < 8; nb++) {
                    mma16816(sacc[nb], qh[s], kh[nb]);
                    mma16816(sacc[nb], qh[s], kl[nb]);
                    mma16816(sacc[nb], ql[s], kh[nb]);
                }
            }
        }

        // ---- causal mask (only diagonal tiles)
        if (kt >= 2 * qt) {
            int rowa = q0 + wid * 16 + g;
#pragma unroll
            for (int nb = 0; nb < 8; nb++) {
                int col = k0 + nb * 8 + qd * 2;
                if (col > rowa)     sacc[nb][0] = -1e30f;
                if (col + 1 > rowa) sacc[nb][1] = -1e30f;
                if (col > rowa + 8)     sacc[nb][2] = -1e30f;
                if (col + 1 > rowa + 8) sacc[nb][3] = -1e30f;
            }
        }

        // ---- online softmax (register, quad shfl)
        {
            float mx0 = -1e30f, mx1 = -1e30f;
#pragma unroll
            for (int nb = 0; nb < 8; nb++) {
                mx0 = fmaxf(mx0, fmaxf(sacc[nb][0], sacc[nb][1]));
                mx1 = fmaxf(mx1, fmaxf(sacc[nb][2], sacc[nb][3]));
            }
            mx0 = fmaxf(mx0, __shfl_xor_sync(0xffffffff, mx0, 1));
            mx0 = fmaxf(mx0, __shfl_xor_sync(0xffffffff, mx0, 2));
            mx1 = fmaxf(mx1, __shfl_xor_sync(0xffffffff, mx1, 1));
            mx1 = fmaxf(mx1, __shfl_xor_sync(0xffffffff, mx1, 2));
            float mn0 = fmaxf(m0, mx0), mn1 = fmaxf(m1, mx1);
            float al0 = __expf(m0 - mn0), al1 = __expf(m1 - mn1);
            m0 = mn0; m1 = mn1;
            l0 *= al0; l1 *= al1;
            float la0 = 0.f, la1 = 0.f;
#pragma unroll
            for (int nb = 0; nb < 8; nb++) {
                sacc[nb][0] = __expf(sacc[nb][0] - mn0);
                sacc[nb][1] = __expf(sacc[nb][1] - mn0);
                sacc[nb][2] = __expf(sacc[nb][2] - mn1);
                sacc[nb][3] = __expf(sacc[nb][3] - mn1);
                la0 += sacc[nb][0] + sacc[nb][1];
                la1 += sacc[nb][2] + sacc[nb][3];
                o[nb][0] *= al0; o[nb][1] *= al0;
                o[nb][2] *= al1; o[nb][3] *= al1;
            }
            l0 += la0; l1 += la1;
        }

        // ---- pack P hi/lo as A-fragments (16 keys per j)
        uint32_t ph[4][4], pl[4][4];
#pragma unroll
        for (int j = 0; j < 4; j++) {
            float* c = sacc[2 * j];
            float* d = sacc[2 * j + 1];
            ph[j][0] = packbf(c[0], c[1]);
            ph[j][1] = packbf(c[2], c[3]);
            ph[j][2] = packbf(d[0], d[1]);
            ph[j][3] = packbf(d[2], d[3]);
            pl[j][0] = packbf(bfres(c[0]), bfres(c[1]));
            pl[j][1] = packbf(bfres(c[2]), bfres(c[3]));
            pl[j][2] = packbf(bfres(d[0]), bfres(d[1]));
            pl[j][3] = packbf(bfres(d[2]), bfres(d[3]));
        }

        // ---- O += P V (3-term split), V via ldmatrix.trans
        {
            int vrow = (lid & 15);
            int vcolB = (lid >> 4) * 16;
#pragma unroll
            for (int j = 0; j < 4; j++) {
                uint32_t vh[8][2], vl[8][2];
#pragma unroll
                for (int dj = 0; dj < 4; dj++) {
                    uint32_t sw = SMEM_SWIZZLE_128B(
                        (uint32_t)((j * 16 + vrow) * 128 + dj * 32 + vcolB));
                    ldsm_x4_t(vh[2 * dj][0], vh[2 * dj][1], vh[2 * dj + 1][0],
                              vh[2 * dj + 1][1], smem_u32(sVhi) + sw);
                    ldsm_x4_t(vl[2 * dj][0], vl[2 * dj][1], vl[2 * dj + 1][0],
                              vl[2 * dj + 1][1], smem_u32(sVlo) + sw);
                }
#pragma unroll
                for (int nb = 0; nb < 8; nb++) {
                    mma16816(o[nb], ph[j], vh[nb]);
                    mma16816(o[nb], ph[j], vl[nb]);
                    mma16816(o[nb], pl[j], vh[nb]);
                }
            }
        }
        __syncthreads();
    }

    // ---- finalize: reduce l across quad, normalize, write [B,S,H*Dh]
    l0 += __shfl_xor_sync(0xffffffff, l0, 1);
    l0 += __shfl_xor_sync(0xffffffff, l0, 2);
    l1 += __shfl_xor_sync(0xffffffff, l1, 1);
    l1 += __shfl_xor_sync(0xffffffff, l1, 2);
    float inv0 = 1.0f / l0, inv1 = 1.0f / l1;

    int rowa = q0 + wid * 16 + g;
    float* Oa = O + (((size_t)b * SEQ + rowa) * NHEADS + h) * HDIM;
    float* Ob = O + (((size_t)b * SEQ + rowa + 8) * NHEADS + h) * HDIM;
#pragma unroll
    for (int nb = 0; nb < 8; nb++) {
        int col = nb * 8 + qd * 2;
        *reinterpret_cast<float2*>(Oa + col) =
            make_float2(o[nb][0] * inv0, o[nb][1] * inv0);
        *reinterpret_cast<float2*>(Ob + col) =
            make_float2(o[nb][2] * inv1, o[nb][3] * inv1);
    }
}

// ---------------- launch ------------------------------------------------------
extern "C" void kernel_launch(void* const* d_in, const int* in_sizes, int n_in,
                              void* d_out, int out_size) {
    (void)in_sizes; (void)n_in; (void)out_size;
    const float* x  = (const float*)d_in[0];
    const float* Wq = (const float*)d_in[1];
    const float* Wk = (const float*)d_in[2];
    const float* Wv = (const float*)d_in[3];
    const float* Wo = (const float*)d_in[4];
    const int* poff = (const int*)d_in[5];
    float* out = (float*)d_out;

    float *Qb, *Kb, *Vb, *Ab;
    __nv_bfloat16 *xhi, *xlo, *khi, *klo, *vhi, *vlo;
    __nv_bfloat16 *wqh, *wql, *wkh, *wkl, *wvh, *wvl, *woh, *wol;
    cudaGetSymbolAddress((void**)&Qb, g_Q);
    cudaGetSymbolAddress((void**)&Kb, g_K);
    cudaGetSymbolAddress((void**)&Vb, g_V);
    cudaGetSymbolAddress((void**)&Ab, g_A);
    cudaGetSymbolAddress((void**)&xhi, g_xhi);
    cudaGetSymbolAddress((void**)&xlo, g_xlo);
    cudaGetSymbolAddress((void**)&khi, g_Khi);
    cudaGetSymbolAddress((void**)&klo, g_Klo);
    cudaGetSymbolAddress((void**)&vhi, g_Vhi);
    cudaGetSymbolAddress((void**)&vlo, g_Vlo);
    cudaGetSymbolAddress((void**)&wqh, g_wq_hi);
    cudaGetSymbolAddress((void**)&wql, g_wq_lo);
    cudaGetSymbolAddress((void**)&wkh, g_wk_hi);
    cudaGetSymbolAddress((void**)&wkl, g_wk_lo);
    cudaGetSymbolAddress((void**)&wvh, g_wv_hi);
    cudaGetSymbolAddress((void**)&wvl, g_wv_lo);
    cudaGetSymbolAddress((void**)&woh, g_wo_hi);
    cudaGetSymbolAddress((void**)&wol, g_wo_lo);

    cudaFuncSetAttribute(gemm_mma3, cudaFuncAttributeMaxDynamicSharedMemorySize,
                         GEMM_SMEM_BYTES);
    cudaFuncSetAttribute(attn_mma, cudaFuncAttributeMaxDynamicSharedMemorySize,
                         ATTN2_SMEM);

    // split x, transpose+split weights
    split_kernel<<<(ROWS * DMODEL / 4 + 255) / 256, 256>>>(x, xhi, xlo, ROWS * DMODEL / 4);
    transpose_split<<<dim3(DMODEL / 32, KDIM / 32), dim3(32, 8)>>>(Wq, wqh, wql, KDIM, DMODEL);
    transpose_split<<<dim3(DKV / 32,    KDIM / 32), dim3(32, 8)>>>(Wk, wkh, wkl, KDIM, DKV);
    transpose_split<<<dim3(DKV / 32,    KDIM / 32), dim3(32, 8)>>>(Wv, wvh, wvl, KDIM, DKV);
    transpose_split<<<dim3(DMODEL / 32, KDIM / 32), dim3(32, 8)>>>(Wo, woh, wol, KDIM, DMODEL);

    // projections (tensor cores)
    gemm_mma3<<<dim3(DMODEL / 128, ROWS / 128), 256, GEMM_SMEM_BYTES>>>(
        xhi, xlo, wqh, wql, Qb, DMODEL);
    gemm_mma3<<<dim3(DKV / 128, ROWS / 128), 256, GEMM_SMEM_BYTES>>>(
        xhi, xlo, wkh, wkl, Kb, DKV);
    gemm_mma3<<<dim3(DKV / 128, ROWS / 128), 256, GEMM_SMEM_BYTES>>>(
        xhi, xlo, wvh, wvl, Vb, DKV);

    // RoPE (1/sqrt(64) folded into Q)
    {
        int totQ = ROWS * NHEADS * 32;
        int totK = ROWS * NKV * 32;
        rope_kernel<<<(totQ + 255) / 256, 256>>>(Qb, NHEADS, poff, 0.125f, totQ);
        rope_kernel<<<(totK + 255) / 256, 256>>>(Kb, NKV, poff, 1.0f, totK);
    }

    // split K/V to bf16 hi/lo for tensor-core attention
    split_kernel<<<(ROWS * DKV / 4 + 255) / 256, 256>>>(Kb, khi, klo, ROWS * DKV / 4);
    split_kernel<<<(ROWS * DKV / 4 + 255) / 256, 256>>>(Vb, vhi, vlo, ROWS * DKV / 4);

    // attention (tensor cores)
    attn_mma<<<dim3(SEQ / 128, NHEADS, BATCH), 256, ATTN2_SMEM>>>(
        Qb, khi, klo, vhi, vlo, Ab);

    // split attention output, O projection
    split_kernel<<<(ROWS * DMODEL / 4 + 255) / 256, 256>>>(Ab, xhi, xlo, ROWS * DMODEL / 4);
    gemm_mma3<<<dim3(DMODEL / 128, ROWS / 128), 256, GEMM_SMEM_BYTES>>>(
        xhi, xlo, woh, wol, out, DMODEL);
}

// round 6
// speedup vs baseline: 3.3772x; 1.1566x over previous
#include <cuda_runtime.h>
#include <cuda_bf16.h>
#include <math.h>
#include <cstdint>

// Problem constants
#define BATCH 2
#define SEQ   2048
#define DMODEL 1024
#define NHEADS 16
#define NKV    4
#define HDIM   64
#define ROWS   (BATCH * SEQ)          // 4096
#define DKV    (NKV * HDIM)           // 256
#define KDIM   1024
#define NQKV   (DMODEL + 2 * DKV)     // 1536

// ---------------- scratch (static __device__, no allocation) ----------------
__device__ float g_QKV[ROWS * NQKV];               // fused Q|K|V projections
__device__ __nv_bfloat16 g_xhi[ROWS * DMODEL];     // x split; reused for attn out
__device__ __nv_bfloat16 g_xlo[ROWS * DMODEL];
__device__ __nv_bfloat16 g_Khi[ROWS * DKV];
__device__ __nv_bfloat16 g_Klo[ROWS * DKV];
__device__ __nv_bfloat16 g_Vhi[ROWS * DKV];
__device__ __nv_bfloat16 g_Vlo[ROWS * DKV];
__device__ __nv_bfloat16 g_wqkv_hi[NQKV * KDIM];   // transposed [N,K], Q|K|V rows
__device__ __nv_bfloat16 g_wqkv_lo[NQKV * KDIM];
__device__ __nv_bfloat16 g_wo_hi[DMODEL * KDIM];
__device__ __nv_bfloat16 g_wo_lo[DMODEL * KDIM];

__device__ __forceinline__ uint32_t smem_u32(const void* p) {
    uint32_t a;
    asm("{ .reg .u64 t; cvta.to.shared.u64 t, %1; cvt.u32.u64 %0, t; }"
        : "=r"(a) : "l"(p));
    return a;
}
#define SMEM_SWIZZLE_128B(off) ((off) ^ (((off) >> 3) & 0x70))
#define SMEM_SWIZZLE_64B(off)  ((off) ^ (((off) >> 3) & 0x30))

__device__ __forceinline__ void ldsm_x4(uint32_t& r0, uint32_t& r1,
                                        uint32_t& r2, uint32_t& r3,
                                        uint32_t addr) {
    asm volatile("ldmatrix.sync.aligned.m8n8.x4.shared.b16 {%0,%1,%2,%3}, [%4];"
                 : "=r"(r0), "=r"(r1), "=r"(r2), "=r"(r3) : "r"(addr));
}
__device__ __forceinline__ void ldsm_x4_t(uint32_t& r0, uint32_t& r1,
                                          uint32_t& r2, uint32_t& r3,
                                          uint32_t addr) {
    asm volatile("ldmatrix.sync.aligned.m8n8.x4.trans.shared.b16 {%0,%1,%2,%3}, [%4];"
                 : "=r"(r0), "=r"(r1), "=r"(r2), "=r"(r3) : "r"(addr));
}
__device__ __forceinline__ void mma16816(float* c, const uint32_t* a,
                                         const uint32_t* b) {
    asm volatile(
        "mma.sync.aligned.m16n8k16.row.col.f32.bf16.bf16.f32 "
        "{%0,%1,%2,%3}, {%4,%5,%6,%7}, {%8,%9}, {%0,%1,%2,%3};"
        : "+f"(c[0]), "+f"(c[1]), "+f"(c[2]), "+f"(c[3])
        : "r"(a[0]), "r"(a[1]), "r"(a[2]), "r"(a[3]), "r"(b[0]), "r"(b[1]));
}
__device__ __forceinline__ uint32_t packbf(float lo, float hi) {
    __nv_bfloat162 t = __floats2bfloat162_rn(lo, hi);   // .x -> low 16 bits
    return *reinterpret_cast<uint32_t*>(&t);
}
__device__ __forceinline__ float bfres(float c) {
    return c - __bfloat162float(__float2bfloat16(c));
}
__device__ __forceinline__ void cp16(uint32_t s, const void* g) {
    asm volatile("cp.async.cg.shared.global [%0], [%1], 16;" :: "r"(s), "l"(g));
}
#define CP_COMMIT() asm volatile("cp.async.commit_group;")
#define CP_WAIT(n)  asm volatile("cp.async.wait_group %0;" :: "n"(n))

// ---------------- split fp32 -> bf16 hi/lo -----------------------------------
__global__ void split_kernel(const float* __restrict__ x,
                             __nv_bfloat16* __restrict__ hi,
                             __nv_bfloat16* __restrict__ lo, int n4) {
    int i = blockIdx.x * blockDim.x + threadIdx.x;
    if (i >= n4) return;
    float4 v = reinterpret_cast<const float4*>(x)[i];
    uint32_t* hp = reinterpret_cast<uint32_t*>(hi) + 2 * i;
    uint32_t* lp = reinterpret_cast<uint32_t*>(lo) + 2 * i;
    hp[0] = packbf(v.x, v.y); hp[1] = packbf(v.z, v.w);
    lp[0] = packbf(bfres(v.x), bfres(v.y));
    lp[1] = packbf(bfres(v.z), bfres(v.w));
}

// ---------------- strided split of K,V from fused QKV buffer -----------------
__global__ void split_kv(const float* __restrict__ qkv,
                         __nv_bfloat16* __restrict__ khi, __nv_bfloat16* __restrict__ klo,
                         __nv_bfloat16* __restrict__ vhi, __nv_bfloat16* __restrict__ vlo) {
    int i = blockIdx.x * blockDim.x + threadIdx.x;   // over ROWS * 64 granules
    if (i >= ROWS * (DKV / 4)) return;
    int row = i / (DKV / 4);
    int c = i % (DKV / 4);
    const float* base = qkv + (size_t)row * NQKV;
    float4 kv = *reinterpret_cast<const float4*>(base + DMODEL + c * 4);
    float4 vv = *reinterpret_cast<const float4*>(base + DMODEL + DKV + c * 4);
    size_t o = (size_t)row * DKV + c * 4;
    reinterpret_cast<uint32_t*>(khi + o)[0] = packbf(kv.x, kv.y);
    reinterpret_cast<uint32_t*>(khi + o)[1] = packbf(kv.z, kv.w);
    reinterpret_cast<uint32_t*>(klo + o)[0] = packbf(bfres(kv.x), bfres(kv.y));
    reinterpret_cast<uint32_t*>(klo + o)[1] = packbf(bfres(kv.z), bfres(kv.w));
    reinterpret_cast<uint32_t*>(vhi + o)[0] = packbf(vv.x, vv.y);
    reinterpret_cast<uint32_t*>(vhi + o)[1] = packbf(vv.z, vv.w);
    reinterpret_cast<uint32_t*>(vlo + o)[0] = packbf(bfres(vv.x), bfres(vv.y));
    reinterpret_cast<uint32_t*>(vlo + o)[1] = packbf(bfres(vv.z), bfres(vv.w));
}

// ---------------- transpose + split: W[K,N] -> Wt_hi/lo[N,K] ----------------
__global__ void transpose_split(const float* __restrict__ W,
                                __nv_bfloat16* __restrict__ hi,
                                __nv_bfloat16* __restrict__ lo,
                                int K, int N) {
    __shared__ float tile[32][33];
    int kb = blockIdx.y * 32, nb = blockIdx.x * 32;
    int tx = threadIdx.x, ty = threadIdx.y;
    for (int i = ty; i < 32; i += 8)
        tile[i][tx] = W[(size_t)(kb + i) * N + nb + tx];
    __syncthreads();
    for (int i = ty; i < 32; i += 8) {
        float v = tile[tx][i];
        __nv_bfloat16 h = __float2bfloat16(v);
        __nv_bfloat16 l = __float2bfloat16(v - __bfloat162float(h));
        size_t o = (size_t)(nb + i) * K + kb + tx;
        hi[o] = h;
        lo[o] = l;
    }
}

// ---------------- cp.async-pipelined mma.sync split-bf16 GEMM ----------------
// C[M,N] = A[M,K] @ B^T, A[M,K] hi/lo, B[N,K] hi/lo. CTA 128x128, 8 warps
// (4m x 2n). K staged in chunks of 32 (64B rows, SW64), 2-stage cp.async.
#define CHUNK 32
#define NCH   (KDIM / CHUNK)          // 32
#define STG_BYTES 32768               // 4 arrays x 8KB per stage
#define GEMM_SMEM_BYTES (2 * STG_BYTES + 1024)

__global__ __launch_bounds__(256, 1) void gemm_mma3(
    const __nv_bfloat16* __restrict__ Ahi, const __nv_bfloat16* __restrict__ Alo,
    const __nv_bfloat16* __restrict__ Bhi, const __nv_bfloat16* __restrict__ Blo,
    float* __restrict__ C, int Ncols) {
    extern __shared__ char dsm[];
    const int t = threadIdx.x;
    const int wid = t >> 5;
    const int lid = t & 31;
    const int warp_m = wid & 3;
    const int warp_n = wid >> 2;
    const int rowBase = blockIdx.y * 128;
    const int colBase = blockIdx.x * 128;

    uint32_t base = (smem_u32(dsm) + 1023u) & ~1023u;
    char* sm = dsm + (base - smem_u32(dsm));

    float acc[2][8][4];
#pragma unroll
    for (int mb = 0; mb < 2; mb++)
#pragma unroll
        for (int nb = 0; nb < 8; nb++)
#pragma unroll
            for (int q = 0; q < 4; q++) acc[mb][nb][q] = 0.f;

    // per-thread load coords: 128 rows x 4 granules(16B) per array per chunk
    const int lrow = t >> 2;           // 0..63 (+64 on second pass)
    const int lg = t & 3;

    // ldmatrix coords
    const int a_row = lid & 15;
    const int a_colB = (lid >> 4) * 16;
    const int b_rowl = ((lid >> 4) << 3) + (lid & 7);
    const int b_colB = ((lid >> 3) & 1) * 16;

#define LOAD_CHUNK(ch, stg) do {                                               \
        const int k0_ = (ch) * CHUNK;                                          \
        char* st_ = sm + (stg) * STG_BYTES;                                    \
        _Pragma("unroll")                                                      \
        for (int ii = 0; ii < 2; ii++) {                                       \
            int row_ = lrow + ii * 64;                                         \
            uint32_t sw_ = SMEM_SWIZZLE_64B((uint32_t)(row_ * 64 + lg * 16));  \
            size_t ao_ = (size_t)(rowBase + row_) * KDIM + k0_ + lg * 8;       \
            size_t bo_ = (size_t)(colBase + row_) * KDIM + k0_ + lg * 8;       \
            uint32_t sb_ = smem_u32(st_) + sw_;                                \
            cp16(sb_, Ahi + ao_);                                              \
            cp16(sb_ + 8192, Alo + ao_);                                       \
            cp16(sb_ + 16384, Bhi + bo_);                                      \
            cp16(sb_ + 24576, Blo + bo_);                                      \
        }                                                                      \
    } while (0)

    LOAD_CHUNK(0, 0);
    CP_COMMIT();

    for (int ch = 0; ch < NCH; ch++) {
        if (ch + 1 < NCH) {
            LOAD_CHUNK(ch + 1, (ch + 1) & 1);
            CP_COMMIT();
            CP_WAIT(1);
        } else {
            CP_WAIT(0);
        }
        __syncthreads();

        char* st = sm + (ch & 1) * STG_BYTES;
        uint32_t aHi = smem_u32(st);
        uint32_t aLo = aHi + 8192;
        uint32_t bHi = aHi + 16384;
        uint32_t bLo = aHi + 24576;

#pragma unroll
        for (int s = 0; s < 2; s++) {
            uint32_t ahi[2][4], alo[2][4], bhi[8][2], blo[8][2];
#pragma unroll
            for (int mb = 0; mb < 2; mb++) {
                int row = warp_m * 32 + mb * 16 + a_row;
                uint32_t sw = SMEM_SWIZZLE_64B(
                    (uint32_t)(row * 64 + a_colB + s * 32));
                ldsm_x4(ahi[mb][0], ahi[mb][1], ahi[mb][2], ahi[mb][3], aHi + sw);
                ldsm_x4(alo[mb][0], alo[mb][1], alo[mb][2], alo[mb][3], aLo + sw);
            }
#pragma unroll
            for (int p = 0; p < 4; p++) {
                int row = warp_n * 64 + p * 16 + b_rowl;
                uint32_t sw = SMEM_SWIZZLE_64B(
                    (uint32_t)(row * 64 + b_colB + s * 32));
                ldsm_x4(bhi[2 * p][0], bhi[2 * p][1], bhi[2 * p + 1][0],
                        bhi[2 * p + 1][1], bHi + sw);
                ldsm_x4(blo[2 * p][0], blo[2 * p][1], blo[2 * p + 1][0],
                        blo[2 * p + 1][1], bLo + sw);
            }
#pragma unroll
            for (int nb = 0; nb < 8; nb++) {
#pragma unroll
                for (int mb = 0; mb < 2; mb++) {
                    mma16816(acc[mb][nb], ahi[mb], bhi[nb]);
                    mma16816(acc[mb][nb], ahi[mb], blo[nb]);
                    mma16816(acc[mb][nb], alo[mb], bhi[nb]);
                }
            }
        }
        __syncthreads();
    }
#undef LOAD_CHUNK

    const int g = lid >> 2;
    const int q = lid & 3;
#pragma unroll
    for (int mb = 0; mb < 2; mb++) {
#pragma unroll
        for (int nb = 0; nb < 8; nb++) {
            int row = rowBase + warp_m * 32 + mb * 16 + g;
            int col = colBase + warp_n * 64 + nb * 8 + q * 2;
            *reinterpret_cast<float2*>(&C[(size_t)row * Ncols + col]) =
                make_float2(acc[mb][nb][0], acc[mb][nb][1]);
            *reinterpret_cast<float2*>(&C[(size_t)(row + 8) * Ncols + col]) =
                make_float2(acc[mb][nb][2], acc[mb][nb][3]);
        }
    }
}

// ---------------- RoPE (in place, strided base) -------------------------------
__global__ void rope_kernel(float* __restrict__ buf, int headsPerRow,
                            int rowStride, const int* __restrict__ offset_ptr,
                            float scale, int total) {
    int idx = blockIdx.x * blockDim.x + threadIdx.x;
    if (idx >= total) return;
    int j = idx & 31;
    int h = (idx >> 5) % headsPerRow;
    int row = idx / (32 * headsPerRow);
    int s = row & (SEQ - 1);
    int pos = s + offset_ptr[0];
    float inv = powf(10000.0f, -(float)j / 32.0f);
    float ang = (float)pos * inv;
    float c = cosf(ang), sn = sinf(ang);
    float* p = buf + (size_t)row * rowStride + h * HDIM + j;
    float a = p[0];
    float b = p[32];
    p[0]  = (a * c - b * sn) * scale;
    p[32] = (b * c + a * sn) * scale;
}

// ---------------- tensor-core flash attention (causal, GQA) ------------------
// CTA: 128 q-rows x 1 head. 8 warps, warp = m16 slice. K-tile 64.
// Q read from fused QKV buffer (stride NQKV); output written as bf16 hi/lo.
#define ATTN2_SMEM (65536 + 1024)

__global__ __launch_bounds__(256, 1) void attn_mma(
    const float* __restrict__ QKV,
    const __nv_bfloat16* __restrict__ Khi, const __nv_bfloat16* __restrict__ Klo,
    const __nv_bfloat16* __restrict__ Vhi, const __nv_bfloat16* __restrict__ Vlo,
    __nv_bfloat16* __restrict__ Ohi, __nv_bfloat16* __restrict__ Olo) {
    extern __shared__ char dsm[];
    uint32_t base = (smem_u32(dsm) + 1023u) & ~1023u;
    char* sm = dsm + (base - smem_u32(dsm));
    char* sQhi = sm;
    char* sQlo = sm + 16384;
    char* sKhi = sm + 32768;
    char* sKlo = sm + 40960;
    char* sVhi = sm + 49152;
    char* sVlo = sm + 57344;

    const int qt = (int)gridDim.x - 1 - (int)blockIdx.x;   // heavy CTAs first
    const int h  = blockIdx.y;
    const int b  = blockIdx.z;
    const int hkv = h >> 2;
    const int t  = threadIdx.x;
    const int wid = t >> 5;
    const int lid = t & 31;
    const int g = lid >> 2;
    const int qd = lid & 3;
    const int q0 = qt * 128;

    // ---- stage Q tile [128 x 64] fp32 -> hi/lo bf16, swizzled (1024 items)
    const float* Qbase = QKV + ((size_t)(b * SEQ + q0)) * NQKV + h * HDIM;
#pragma unroll
    for (int ii = 0; ii < 4; ii++) {
        int idx = t + ii * 256;            // 0..1023
        int row = idx >> 3;
        int ch = idx & 7;
        const float4* src = reinterpret_cast<const float4*>(
            Qbase + (size_t)row * NQKV + ch * 8);
        float4 v0 = src[0], v1 = src[1];
        uint32_t hpk[4], lpk[4];
        hpk[0] = packbf(v0.x, v0.y); hpk[1] = packbf(v0.z, v0.w);
        hpk[2] = packbf(v1.x, v1.y); hpk[3] = packbf(v1.z, v1.w);
        lpk[0] = packbf(bfres(v0.x), bfres(v0.y));
        lpk[1] = packbf(bfres(v0.z), bfres(v0.w));
        lpk[2] = packbf(bfres(v1.x), bfres(v1.y));
        lpk[3] = packbf(bfres(v1.z), bfres(v1.w));
        uint32_t sw = SMEM_SWIZZLE_128B((uint32_t)(row * 128 + ch * 16));
        *reinterpret_cast<uint4*>(sQhi + sw) = make_uint4(hpk[0], hpk[1], hpk[2], hpk[3]);
        *reinterpret_cast<uint4*>(sQlo + sw) = make_uint4(lpk[0], lpk[1], lpk[2], lpk[3]);
    }
    __syncthreads();

    // ---- Q fragments in registers
    uint32_t qh[4][4], ql[4][4];
    {
        int arow = wid * 16 + (lid & 15);
        int acolB = (lid >> 4) * 16;
#pragma unroll
        for (int s = 0; s < 4; s++) {
            uint32_t sw = SMEM_SWIZZLE_128B((uint32_t)(arow * 128 + acolB + s * 32));
            ldsm_x4(qh[s][0], qh[s][1], qh[s][2], qh[s][3], smem_u32(sQhi) + sw);
            ldsm_x4(ql[s][0], ql[s][1], ql[s][2], ql[s][3], smem_u32(sQlo) + sw);
        }
    }

    float o[8][4];
#pragma unroll
    for (int nb = 0; nb < 8; nb++)
#pragma unroll
        for (int q = 0; q < 4; q++) o[nb][q] = 0.f;
    float m0 = -1e30f, m1 = -1e30f, l0 = 0.f, l1 = 0.f;

    const size_t kvbase = ((size_t)b * SEQ) * DKV + (size_t)hkv * HDIM;
    const int ntiles = 2 * qt + 2;

    for (int kt = 0; kt < ntiles; kt++) {
        const int k0 = kt * 64;
#pragma unroll
        for (int ii = 0; ii < 2; ii++) {
            int idx = t + ii * 256;        // 0..511
            int row = idx >> 3;
            int ch = idx & 7;
            uint32_t sw = SMEM_SWIZZLE_128B((uint32_t)(row * 128 + ch * 16));
            size_t gl = kvbase + (size_t)(k0 + row) * DKV + ch * 8;
            *reinterpret_cast<uint4*>(sKhi + sw) = *reinterpret_cast<const uint4*>(Khi + gl);
            *reinterpret_cast<uint4*>(sKlo + sw) = *reinterpret_cast<const uint4*>(Klo + gl);
            *reinterpret_cast<uint4*>(sVhi + sw) = *reinterpret_cast<const uint4*>(Vhi + gl);
            *reinterpret_cast<uint4*>(sVlo + sw) = *reinterpret_cast<const uint4*>(Vlo + gl);
        }
        __syncthreads();

        // ---- S = Q K^T (3-term split)
        float sacc[8][4];
#pragma unroll
        for (int nb = 0; nb < 8; nb++)
#pragma unroll
            for (int q = 0; q < 4; q++) sacc[nb][q] = 0.f;

        {
            int brow = ((lid >> 4) << 3) + (lid & 7);
            int bcolB = ((lid >> 3) & 1) * 16;
#pragma unroll
            for (int s = 0; s < 4; s++) {
                uint32_t kh[8][2], kl[8][2];
#pragma unroll
                for (int p = 0; p < 4; p++) {
                    uint32_t sw = SMEM_SWIZZLE_128B(
                        (uint32_t)((p * 16 + brow) * 128 + bcolB + s * 32));
                    ldsm_x4(kh[2 * p][0], kh[2 * p][1], kh[2 * p + 1][0],
                            kh[2 * p + 1][1], smem_u32(sKhi) + sw);
                    ldsm_x4(kl[2 * p][0], kl[2 * p][1], kl[2 * p + 1][0],
                            kl[2 * p + 1][1], smem_u32(sKlo) + sw);
                }
#pragma unroll
                for (int nb = 0; nb < 8; nb++) {
                    mma16816(sacc[nb], qh[s], kh[nb]);
                    mma16816(sacc[nb], qh[s], kl[nb]);
                    mma16816(sacc[nb], ql[s], kh[nb]);
                }
            }
        }

        // ---- causal mask (only diagonal tiles)
        if (kt >= 2 * qt) {
            int rowa = q0 + wid * 16 + g;
#pragma unroll
            for (int nb = 0; nb < 8; nb++) {
                int col = k0 + nb * 8 + qd * 2;
                if (col > rowa)     sacc[nb][0] = -1e30f;
                if (col + 1 > rowa) sacc[nb][1] = -1e30f;
                if (col > rowa + 8)     sacc[nb][2] = -1e30f;
                if (col + 1 > rowa + 8) sacc[nb][3] = -1e30f;
            }
        }

        // ---- online softmax (register, quad shfl)
        {
            float mx0 = -1e30f, mx1 = -1e30f;
#pragma unroll
            for (int nb = 0; nb < 8; nb++) {
                mx0 = fmaxf(mx0, fmaxf(sacc[nb][0], sacc[nb][1]));
                mx1 = fmaxf(mx1, fmaxf(sacc[nb][2], sacc[nb][3]));
            }
            mx0 = fmaxf(mx0, __shfl_xor_sync(0xffffffff, mx0, 1));
            mx0 = fmaxf(mx0, __shfl_xor_sync(0xffffffff, mx0, 2));
            mx1 = fmaxf(mx1, __shfl_xor_sync(0xffffffff, mx1, 1));
            mx1 = fmaxf(mx1, __shfl_xor_sync(0xffffffff, mx1, 2));
            float mn0 = fmaxf(m0, mx0), mn1 = fmaxf(m1, mx1);
            float al0 = __expf(m0 - mn0), al1 = __expf(m1 - mn1);
            m0 = mn0; m1 = mn1;
            l0 *= al0; l1 *= al1;
            float la0 = 0.f, la1 = 0.f;
#pragma unroll
            for (int nb = 0; nb < 8; nb++) {
                sacc[nb][0] = __expf(sacc[nb][0] - mn0);
                sacc[nb][1] = __expf(sacc[nb][1] - mn0);
                sacc[nb][2] = __expf(sacc[nb][2] - mn1);
                sacc[nb][3] = __expf(sacc[nb][3] - mn1);
                la0 += sacc[nb][0] + sacc[nb][1];
                la1 += sacc[nb][2] + sacc[nb][3];
                o[nb][0] *= al0; o[nb][1] *= al0;
                o[nb][2] *= al1; o[nb][3] *= al1;
            }
            l0 += la0; l1 += la1;
        }

        // ---- pack P hi/lo as A-fragments
        uint32_t ph[4][4], pl[4][4];
#pragma unroll
        for (int j = 0; j < 4; j++) {
            float* c = sacc[2 * j];
            float* d = sacc[2 * j + 1];
            ph[j][0] = packbf(c[0], c[1]);
            ph[j][1] = packbf(c[2], c[3]);
            ph[j][2] = packbf(d[0], d[1]);
            ph[j][3] = packbf(d[2], d[3]);
            pl[j][0] = packbf(bfres(c[0]), bfres(c[1]));
            pl[j][1] = packbf(bfres(c[2]), bfres(c[3]));
            pl[j][2] = packbf(bfres(d[0]), bfres(d[1]));
            pl[j][3] = packbf(bfres(d[2]), bfres(d[3]));
        }

        // ---- O += P V (3-term split), V via ldmatrix.trans
        {
            int vrow = (lid & 15);
            int vcolB = (lid >> 4) * 16;
#pragma unroll
            for (int j = 0; j < 4; j++) {
                uint32_t vh[8][2], vl[8][2];
#pragma unroll
                for (int dj = 0; dj < 4; dj++) {
                    uint32_t sw = SMEM_SWIZZLE_128B(
                        (uint32_t)((j * 16 + vrow) * 128 + dj * 32 + vcolB));
                    ldsm_x4_t(vh[2 * dj][0], vh[2 * dj][1], vh[2 * dj + 1][0],
                              vh[2 * dj + 1][1], smem_u32(sVhi) + sw);
                    ldsm_x4_t(vl[2 * dj][0], vl[2 * dj][1], vl[2 * dj + 1][0],
                              vl[2 * dj + 1][1], smem_u32(sVlo) + sw);
                }
#pragma unroll
                for (int nb = 0; nb < 8; nb++) {
                    mma16816(o[nb], ph[j], vh[nb]);
                    mma16816(o[nb], ph[j], vl[nb]);
                    mma16816(o[nb], pl[j], vh[nb]);
                }
            }
        }
        __syncthreads();
    }

    // ---- finalize: normalize, write bf16 hi/lo directly (fused split)
    l0 += __shfl_xor_sync(0xffffffff, l0, 1);
    l0 += __shfl_xor_sync(0xffffffff, l0, 2);
    l1 += __shfl_xor_sync(0xffffffff, l1, 1);
    l1 += __shfl_xor_sync(0xffffffff, l1, 2);
    float inv0 = 1.0f / l0, inv1 = 1.0f / l1;

    int rowa = q0 + wid * 16 + g;
    size_t oa = ((size_t)(b * SEQ + rowa)) * DMODEL + h * HDIM;
    size_t ob = ((size_t)(b * SEQ + rowa + 8)) * DMODEL + h * HDIM;
#pragma unroll
    for (int nb = 0; nb < 8; nb++) {
        int col = nb * 8 + qd * 2;
        float a0 = o[nb][0] * inv0, a1 = o[nb][1] * inv0;
        float b0 = o[nb][2] * inv1, b1 = o[nb][3] * inv1;
        *reinterpret_cast<uint32_t*>(Ohi + oa + col) = packbf(a0, a1);
        *reinterpret_cast<uint32_t*>(Olo + oa + col) = packbf(bfres(a0), bfres(a1));
        *reinterpret_cast<uint32_t*>(Ohi + ob + col) = packbf(b0, b1);
        *reinterpret_cast<uint32_t*>(Olo + ob + col) = packbf(bfres(b0), bfres(b1));
    }
}

// ---------------- launch ------------------------------------------------------
extern "C" void kernel_launch(void* const* d_in, const int* in_sizes, int n_in,
                              void* d_out, int out_size) {
    (void)in_sizes; (void)n_in; (void)out_size;
    const float* x  = (const float*)d_in[0];
    const float* Wq = (const float*)d_in[1];
    const float* Wk = (const float*)d_in[2];
    const float* Wv = (const float*)d_in[3];
    const float* Wo = (const float*)d_in[4];
    const int* poff = (const int*)d_in[5];
    float* out = (float*)d_out;

    float* qkv;
    __nv_bfloat16 *xhi, *xlo, *khi, *klo, *vhi, *vlo;
    __nv_bfloat16 *wqkvh, *wqkvl, *woh, *wol;
    cudaGetSymbolAddress((void**)&qkv, g_QKV);
    cudaGetSymbolAddress((void**)&xhi, g_xhi);
    cudaGetSymbolAddress((void**)&xlo, g_xlo);
    cudaGetSymbolAddress((void**)&khi, g_Khi);
    cudaGetSymbolAddress((void**)&klo, g_Klo);
    cudaGetSymbolAddress((void**)&vhi, g_Vhi);
    cudaGetSymbolAddress((void**)&vlo, g_Vlo);
    cudaGetSymbolAddress((void**)&wqkvh, g_wqkv_hi);
    cudaGetSymbolAddress((void**)&wqkvl, g_wqkv_lo);
    cudaGetSymbolAddress((void**)&woh, g_wo_hi);
    cudaGetSymbolAddress((void**)&wol, g_wo_lo);

    cudaFuncSetAttribute(gemm_mma3, cudaFuncAttributeMaxDynamicSharedMemorySize,
                         GEMM_SMEM_BYTES);
    cudaFuncSetAttribute(attn_mma, cudaFuncAttributeMaxDynamicSharedMemorySize,
                         ATTN2_SMEM);

    // split x; transpose+split weights (Wq|Wk|Wv fused along N)
    split_kernel<<<(ROWS * DMODEL / 4 + 255) / 256, 256>>>(x, xhi, xlo, ROWS * DMODEL / 4);
    transpose_split<<<dim3(DMODEL / 32, KDIM / 32), dim3(32, 8)>>>(
        Wq, wqkvh, wqkvl, KDIM, DMODEL);
    transpose_split<<<dim3(DKV / 32, KDIM / 32), dim3(32, 8)>>>(
        Wk, wqkvh + (size_t)DMODEL * KDIM, wqkvl + (size_t)DMODEL * KDIM, KDIM, DKV);
    transpose_split<<<dim3(DKV / 32, KDIM / 32), dim3(32, 8)>>>(
        Wv, wqkvh + (size_t)(DMODEL + DKV) * KDIM, wqkvl + (size_t)(DMODEL + DKV) * KDIM,
        KDIM, DKV);
    transpose_split<<<dim3(DMODEL / 32, KDIM / 32), dim3(32, 8)>>>(Wo, woh, wol, KDIM, DMODEL);

    // fused QKV projection (tensor cores, cp.async pipelined)
    gemm_mma3<<<dim3(NQKV / 128, ROWS / 128), 256, GEMM_SMEM_BYTES>>>(
        xhi, xlo, wqkvh, wqkvl, qkv, NQKV);

    // RoPE on Q (scale folded) and K inside the fused buffer
    {
        int totQ = ROWS * NHEADS * 32;
        int totK = ROWS * NKV * 32;
        rope_kernel<<<(totQ + 255) / 256, 256>>>(qkv, NHEADS, NQKV, poff, 0.125f, totQ);
        rope_kernel<<<(totK + 255) / 256, 256>>>(qkv + DMODEL, NKV, NQKV, poff, 1.0f, totK);
    }

    // split K/V to bf16 hi/lo
    split_kv<<<(ROWS * (DKV / 4) + 255) / 256, 256>>>(qkv, khi, klo, vhi, vlo);

    // attention (tensor cores) -> writes hi/lo directly into xhi/xlo
    attn_mma<<<dim3(SEQ / 128, NHEADS, BATCH), 256, ATTN2_SMEM>>>(
        qkv, khi, klo, vhi, vlo, xhi, xlo);

    // O projection
    gemm_mma3<<<dim3(DMODEL / 128, ROWS / 128), 256, GEMM_SMEM_BYTES>>>(
        xhi, xlo, woh, wol, out, DMODEL);
}

// round 7
// speedup vs baseline: 3.6509x; 1.0810x over previous
#include <cuda_runtime.h>
#include <cuda_bf16.h>
#include <math.h>
#include <cstdint>

// Problem constants
#define BATCH 2
#define SEQ   2048
#define DMODEL 1024
#define NHEADS 16
#define NKV    4
#define HDIM   64
#define ROWS   (BATCH * SEQ)          // 4096
#define DKV    (NKV * HDIM)           // 256
#define KDIM   1024
#define NQKV   (DMODEL + 2 * DKV)     // 1536

// ---------------- scratch (static __device__, no allocation) ----------------
__device__ float g_QKV[ROWS * NQKV];               // fused Q|K|V projections
__device__ __nv_bfloat16 g_xhi[ROWS * DMODEL];     // x split; reused for attn out
__device__ __nv_bfloat16 g_xlo[ROWS * DMODEL];
__device__ __nv_bfloat16 g_Khi[ROWS * DKV];
__device__ __nv_bfloat16 g_Klo[ROWS * DKV];
__device__ __nv_bfloat16 g_Vhi[ROWS * DKV];
__device__ __nv_bfloat16 g_Vlo[ROWS * DKV];
__device__ __nv_bfloat16 g_wqkv_hi[NQKV * KDIM];   // transposed [N,K], Q|K|V rows
__device__ __nv_bfloat16 g_wqkv_lo[NQKV * KDIM];
__device__ __nv_bfloat16 g_wo_hi[DMODEL * KDIM];
__device__ __nv_bfloat16 g_wo_lo[DMODEL * KDIM];

__device__ __forceinline__ uint32_t smem_u32(const void* p) {
    uint32_t a;
    asm("{ .reg .u64 t; cvta.to.shared.u64 t, %1; cvt.u32.u64 %0, t; }"
        : "=r"(a) : "l"(p));
    return a;
}
#define SMEM_SWIZZLE_128B(off) ((off) ^ (((off) >> 3) & 0x70))
#define SMEM_SWIZZLE_64B(off)  ((off) ^ (((off) >> 3) & 0x30))

__device__ __forceinline__ void ldsm_x4(uint32_t& r0, uint32_t& r1,
                                        uint32_t& r2, uint32_t& r3,
                                        uint32_t addr) {
    asm volatile("ldmatrix.sync.aligned.m8n8.x4.shared.b16 {%0,%1,%2,%3}, [%4];"
                 : "=r"(r0), "=r"(r1), "=r"(r2), "=r"(r3) : "r"(addr));
}
__device__ __forceinline__ void ldsm_x4_t(uint32_t& r0, uint32_t& r1,
                                          uint32_t& r2, uint32_t& r3,
                                          uint32_t addr) {
    asm volatile("ldmatrix.sync.aligned.m8n8.x4.trans.shared.b16 {%0,%1,%2,%3}, [%4];"
                 : "=r"(r0), "=r"(r1), "=r"(r2), "=r"(r3) : "r"(addr));
}
__device__ __forceinline__ void mma16816(float* c, const uint32_t* a,
                                         const uint32_t* b) {
    asm volatile(
        "mma.sync.aligned.m16n8k16.row.col.f32.bf16.bf16.f32 "
        "{%0,%1,%2,%3}, {%4,%5,%6,%7}, {%8,%9}, {%0,%1,%2,%3};"
        : "+f"(c[0]), "+f"(c[1]), "+f"(c[2]), "+f"(c[3])
        : "r"(a[0]), "r"(a[1]), "r"(a[2]), "r"(a[3]), "r"(b[0]), "r"(b[1]));
}
__device__ __forceinline__ uint32_t packbf(float lo, float hi) {
    __nv_bfloat162 t = __floats2bfloat162_rn(lo, hi);   // .x -> low 16 bits
    return *reinterpret_cast<uint32_t*>(&t);
}
__device__ __forceinline__ float bfres(float c) {
    return c - __bfloat162float(__float2bfloat16(c));
}
__device__ __forceinline__ void cp16(uint32_t s, const void* g) {
    asm volatile("cp.async.cg.shared.global [%0], [%1], 16;" :: "r"(s), "l"(g));
}
#define CP_COMMIT() asm volatile("cp.async.commit_group;")
#define CP_WAIT(n)  asm volatile("cp.async.wait_group %0;" :: "n"(n))

// ---------------- fused prep: x split + 4 weight transposes ------------------
// grid (128, 32, 5), block (32, 8).
// z==4: elementwise split of x. z==0..3: transpose+split Wq/Wk/Wv/Wo.
__global__ void prep_kernel(const float* __restrict__ x,
                            const float* __restrict__ Wq,
                            const float* __restrict__ Wk,
                            const float* __restrict__ Wv,
                            const float* __restrict__ Wo,
                            __nv_bfloat16* __restrict__ xhi,
                            __nv_bfloat16* __restrict__ xlo,
                            __nv_bfloat16* __restrict__ wqkvh,
                            __nv_bfloat16* __restrict__ wqkvl,
                            __nv_bfloat16* __restrict__ woh,
                            __nv_bfloat16* __restrict__ wol) {
    const int z = blockIdx.z;
    const int tx = threadIdx.x, ty = threadIdx.y;

    if (z == 4) {   // split x: 1048576 float4 granules
        int i = (blockIdx.y * 128 + blockIdx.x) * 256 + ty * 32 + tx;
        float4 v = reinterpret_cast<const float4*>(x)[i];
        uint32_t* hp = reinterpret_cast<uint32_t*>(xhi) + 2 * i;
        uint32_t* lp = reinterpret_cast<uint32_t*>(xlo) + 2 * i;
        hp[0] = packbf(v.x, v.y); hp[1] = packbf(v.z, v.w);
        lp[0] = packbf(bfres(v.x), bfres(v.y));
        lp[1] = packbf(bfres(v.z), bfres(v.w));
        return;
    }

    const float* W;
    __nv_bfloat16 *hi, *lo;
    int N;
    if (z == 0)      { W = Wq; N = DMODEL; hi = wqkvh; lo = wqkvl; }
    else if (z == 1) { W = Wk; N = DKV;
                       hi = wqkvh + (size_t)DMODEL * KDIM;
                       lo = wqkvl + (size_t)DMODEL * KDIM; }
    else if (z == 2) { W = Wv; N = DKV;
                       hi = wqkvh + (size_t)(DMODEL + DKV) * KDIM;
                       lo = wqkvl + (size_t)(DMODEL + DKV) * KDIM; }
    else             { W = Wo; N = DMODEL; hi = woh; lo = wol; }

    int nb = blockIdx.x * 32;
    if (nb >= N) return;
    int kb = blockIdx.y * 32;

    __shared__ float tile[32][33];
    for (int i = ty; i < 32; i += 8)
        tile[i][tx] = W[(size_t)(kb + i) * N + nb + tx];
    __syncthreads();
    for (int i = ty; i < 32; i += 8) {
        float v = tile[tx][i];
        __nv_bfloat16 h = __float2bfloat16(v);
        __nv_bfloat16 l = __float2bfloat16(v - __bfloat162float(h));
        size_t o = (size_t)(nb + i) * KDIM + kb + tx;
        hi[o] = h;
        lo[o] = l;
    }
}

// ---------------- split K,V from fused QKV buffer (K-RoPE fused) -------------
__global__ void split_kv(const float* __restrict__ qkv,
                         const int* __restrict__ offset_ptr,
                         __nv_bfloat16* __restrict__ khi, __nv_bfloat16* __restrict__ klo,
                         __nv_bfloat16* __restrict__ vhi, __nv_bfloat16* __restrict__ vlo) {
    int i = blockIdx.x * blockDim.x + threadIdx.x;   // ROWS * (DKV/4) granules
    if (i >= ROWS * (DKV / 4)) return;
    int row = i / (DKV / 4);
    int c = i % (DKV / 4);
    const float* base = qkv + (size_t)row * NQKV;

    // V: plain split
    float4 vv = *reinterpret_cast<const float4*>(base + DMODEL + DKV + c * 4);
    size_t o = (size_t)row * DKV + c * 4;
    reinterpret_cast<uint32_t*>(vhi + o)[0] = packbf(vv.x, vv.y);
    reinterpret_cast<uint32_t*>(vhi + o)[1] = packbf(vv.z, vv.w);
    reinterpret_cast<uint32_t*>(vlo + o)[0] = packbf(bfres(vv.x), bfres(vv.y));
    reinterpret_cast<uint32_t*>(vlo + o)[1] = packbf(bfres(vv.z), bfres(vv.w));

    // K: apply RoPE, then split. head-local dim d0 = (c*4) & 63.
    float4 a = *reinterpret_cast<const float4*>(base + DMODEL + c * 4);
    int d0 = (c * 4) & 63;
    bool firstHalf = d0 < 32;
    // partner granule at +/- 8 granules (32 dims)
    float4 pb = *reinterpret_cast<const float4*>(
        base + DMODEL + (firstHalf ? (c + 8) : (c - 8)) * 4);
    int s = row & (SEQ - 1);
    float pos = (float)(s + offset_ptr[0]);
    float kq[4];
#pragma unroll
    for (int e = 0; e < 4; e++) {
        int j = (d0 + e) & 31;
        float inv = powf(10000.0f, -(float)j / 32.0f);
        float ang = pos * inv;
        float cs = cosf(ang), sn = sinf(ang);
        float av = (&a.x)[e];
        float bv = (&pb.x)[e];
        kq[e] = firstHalf ? (av * cs - bv * sn) : (av * cs + bv * sn);
    }
    reinterpret_cast<uint32_t*>(khi + o)[0] = packbf(kq[0], kq[1]);
    reinterpret_cast<uint32_t*>(khi + o)[1] = packbf(kq[2], kq[3]);
    reinterpret_cast<uint32_t*>(klo + o)[0] = packbf(bfres(kq[0]), bfres(kq[1]));
    reinterpret_cast<uint32_t*>(klo + o)[1] = packbf(bfres(kq[2]), bfres(kq[3]));
}

// ---------------- cp.async-pipelined mma.sync split-bf16 GEMM ----------------
#define CHUNK 32
#define NCH   (KDIM / CHUNK)          // 32
#define STG_BYTES 32768               // 4 arrays x 8KB per stage
#define GEMM_SMEM_BYTES (2 * STG_BYTES + 1024)

__global__ __launch_bounds__(256, 1) void gemm_mma3(
    const __nv_bfloat16* __restrict__ Ahi, const __nv_bfloat16* __restrict__ Alo,
    const __nv_bfloat16* __restrict__ Bhi, const __nv_bfloat16* __restrict__ Blo,
    float* __restrict__ C, int Ncols) {
    extern __shared__ char dsm[];
    const int t = threadIdx.x;
    const int wid = t >> 5;
    const int lid = t & 31;
    const int warp_m = wid & 3;
    const int warp_n = wid >> 2;
    const int rowBase = blockIdx.y * 128;
    const int colBase = blockIdx.x * 128;

    uint32_t base = (smem_u32(dsm) + 1023u) & ~1023u;
    char* sm = dsm + (base - smem_u32(dsm));

    float acc[2][8][4];
#pragma unroll
    for (int mb = 0; mb < 2; mb++)
#pragma unroll
        for (int nb = 0; nb < 8; nb++)
#pragma unroll
            for (int q = 0; q < 4; q++) acc[mb][nb][q] = 0.f;

    const int lrow = t >> 2;
    const int lg = t & 3;
    const int a_row = lid & 15;
    const int a_colB = (lid >> 4) * 16;
    const int b_rowl = ((lid >> 4) << 3) + (lid & 7);
    const int b_colB = ((lid >> 3) & 1) * 16;

#define LOAD_CHUNK(ch, stg) do {                                               \
        const int k0_ = (ch) * CHUNK;                                          \
        char* st_ = sm + (stg) * STG_BYTES;                                    \
        _Pragma("unroll")                                                      \
        for (int ii = 0; ii < 2; ii++) {                                       \
            int row_ = lrow + ii * 64;                                         \
            uint32_t sw_ = SMEM_SWIZZLE_64B((uint32_t)(row_ * 64 + lg * 16));  \
            size_t ao_ = (size_t)(rowBase + row_) * KDIM + k0_ + lg * 8;       \
            size_t bo_ = (size_t)(colBase + row_) * KDIM + k0_ + lg * 8;       \
            uint32_t sb_ = smem_u32(st_) + sw_;                                \
            cp16(sb_, Ahi + ao_);                                              \
            cp16(sb_ + 8192, Alo + ao_);                                       \
            cp16(sb_ + 16384, Bhi + bo_);                                      \
            cp16(sb_ + 24576, Blo + bo_);                                      \
        }                                                                      \
    } while (0)

    LOAD_CHUNK(0, 0);
    CP_COMMIT();

    for (int ch = 0; ch < NCH; ch++) {
        if (ch + 1 < NCH) {
            LOAD_CHUNK(ch + 1, (ch + 1) & 1);
            CP_COMMIT();
            CP_WAIT(1);
        } else {
            CP_WAIT(0);
        }
        __syncthreads();

        char* st = sm + (ch & 1) * STG_BYTES;
        uint32_t aHi = smem_u32(st);
        uint32_t aLo = aHi + 8192;
        uint32_t bHi = aHi + 16384;
        uint32_t bLo = aHi + 24576;

#pragma unroll
        for (int s = 0; s < 2; s++) {
            uint32_t ahi[2][4], alo[2][4], bhi[8][2], blo[8][2];
#pragma unroll
            for (int mb = 0; mb < 2; mb++) {
                int row = warp_m * 32 + mb * 16 + a_row;
                uint32_t sw = SMEM_SWIZZLE_64B(
                    (uint32_t)(row * 64 + a_colB + s * 32));
                ldsm_x4(ahi[mb][0], ahi[mb][1], ahi[mb][2], ahi[mb][3], aHi + sw);
                ldsm_x4(alo[mb][0], alo[mb][1], alo[mb][2], alo[mb][3], aLo + sw);
            }
#pragma unroll
            for (int p = 0; p < 4; p++) {
                int row = warp_n * 64 + p * 16 + b_rowl;
                uint32_t sw = SMEM_SWIZZLE_64B(
                    (uint32_t)(row * 64 + b_colB + s * 32));
                ldsm_x4(bhi[2 * p][0], bhi[2 * p][1], bhi[2 * p + 1][0],
                        bhi[2 * p + 1][1], bHi + sw);
                ldsm_x4(blo[2 * p][0], blo[2 * p][1], blo[2 * p + 1][0],
                        blo[2 * p + 1][1], bLo + sw);
            }
#pragma unroll
            for (int nb = 0; nb < 8; nb++) {
#pragma unroll
                for (int mb = 0; mb < 2; mb++) {
                    mma16816(acc[mb][nb], ahi[mb], bhi[nb]);
                    mma16816(acc[mb][nb], ahi[mb], blo[nb]);
                    mma16816(acc[mb][nb], alo[mb], bhi[nb]);
                }
            }
        }
        __syncthreads();
    }
#undef LOAD_CHUNK

    const int g = lid >> 2;
    const int q = lid & 3;
#pragma unroll
    for (int mb = 0; mb < 2; mb++) {
#pragma unroll
        for (int nb = 0; nb < 8; nb++) {
            int row = rowBase + warp_m * 32 + mb * 16 + g;
            int col = colBase + warp_n * 64 + nb * 8 + q * 2;
            *reinterpret_cast<float2*>(&C[(size_t)row * Ncols + col]) =
                make_float2(acc[mb][nb][0], acc[mb][nb][1]);
            *reinterpret_cast<float2*>(&C[(size_t)(row + 8) * Ncols + col]) =
                make_float2(acc[mb][nb][2], acc[mb][nb][3]);
        }
    }
}

// ---------------- RoPE for Q (in place, strided, scale folded) ---------------
__global__ void rope_kernel(float* __restrict__ buf, int headsPerRow,
                            int rowStride, const int* __restrict__ offset_ptr,
                            float scale, int total) {
    int idx = blockIdx.x * blockDim.x + threadIdx.x;
    if (idx >= total) return;
    int j = idx & 31;
    int h = (idx >> 5) % headsPerRow;
    int row = idx / (32 * headsPerRow);
    int s = row & (SEQ - 1);
    int pos = s + offset_ptr[0];
    float inv = powf(10000.0f, -(float)j / 32.0f);
    float ang = (float)pos * inv;
    float c = cosf(ang), sn = sinf(ang);
    float* p = buf + (size_t)row * rowStride + h * HDIM + j;
    float a = p[0];
    float b = p[32];
    p[0]  = (a * c - b * sn) * scale;
    p[32] = (b * c + a * sn) * scale;
}

// ---------------- tensor-core flash attention (causal, GQA) ------------------
// CTA: 128 q-rows x 1 head. 8 warps. K-tile 64, cp.async double-buffered K/V.
#define KV_STG 32768
#define ATTN2_SMEM (32768 + 2 * KV_STG + 1024)

__global__ __launch_bounds__(256, 1) void attn_mma(
    const float* __restrict__ QKV,
    const __nv_bfloat16* __restrict__ Khi, const __nv_bfloat16* __restrict__ Klo,
    const __nv_bfloat16* __restrict__ Vhi, const __nv_bfloat16* __restrict__ Vlo,
    __nv_bfloat16* __restrict__ Ohi, __nv_bfloat16* __restrict__ Olo) {
    extern __shared__ char dsm[];
    uint32_t base = (smem_u32(dsm) + 1023u) & ~1023u;
    char* sm = dsm + (base - smem_u32(dsm));
    char* sQhi = sm;            // 16KB
    char* sQlo = sm + 16384;    // 16KB
    // stages at sm+32768: each {Khi 8K | Klo 8K | Vhi 8K | Vlo 8K}

    const int qt = (int)gridDim.x - 1 - (int)blockIdx.x;   // heavy CTAs first
    const int h  = blockIdx.y;
    const int b  = blockIdx.z;
    const int hkv = h >> 2;
    const int t  = threadIdx.x;
    const int wid = t >> 5;
    const int lid = t & 31;
    const int g = lid >> 2;
    const int qd = lid & 3;
    const int q0 = qt * 128;

    const size_t kvbase = ((size_t)b * SEQ) * DKV + (size_t)hkv * HDIM;
    const int ntiles = 2 * qt + 2;

#define LOADKV(kt_, stg_) do {                                                  \
        const int k0_ = (kt_) * 64;                                            \
        uint32_t sb0_ = smem_u32(sm + 32768 + (stg_) * KV_STG);                 \
        _Pragma("unroll")                                                       \
        for (int ii = 0; ii < 2; ii++) {                                        \
            int idx_ = t + ii * 256;                                            \
            int row_ = idx_ >> 3;                                               \
            int ch_ = idx_ & 7;                                                 \
            uint32_t sw_ = SMEM_SWIZZLE_128B((uint32_t)(row_ * 128 + ch_ * 16));\
            size_t gl_ = kvbase + (size_t)(k0_ + row_) * DKV + ch_ * 8;         \
            cp16(sb0_ + sw_, Khi + gl_);                                        \
            cp16(sb0_ + 8192 + sw_, Klo + gl_);                                 \
            cp16(sb0_ + 16384 + sw_, Vhi + gl_);                                \
            cp16(sb0_ + 24576 + sw_, Vlo + gl_);                                \
        }                                                                       \
    } while (0)

    // prefetch tile 0 while converting Q
    LOADKV(0, 0);
    CP_COMMIT();

    // ---- stage Q tile [128 x 64] fp32 -> hi/lo bf16, swizzled (1024 items)
    const float* Qbase = QKV + ((size_t)(b * SEQ + q0)) * NQKV + h * HDIM;
#pragma unroll
    for (int ii = 0; ii < 4; ii++) {
        int idx = t + ii * 256;
        int row = idx >> 3;
        int ch = idx & 7;
        const float4* src = reinterpret_cast<const float4*>(
            Qbase + (size_t)row * NQKV + ch * 8);
        float4 v0 = src[0], v1 = src[1];
        uint32_t hpk[4], lpk[4];
        hpk[0] = packbf(v0.x, v0.y); hpk[1] = packbf(v0.z, v0.w);
        hpk[2] = packbf(v1.x, v1.y); hpk[3] = packbf(v1.z, v1.w);
        lpk[0] = packbf(bfres(v0.x), bfres(v0.y));
        lpk[1] = packbf(bfres(v0.z), bfres(v0.w));
        lpk[2] = packbf(bfres(v1.x), bfres(v1.y));
        lpk[3] = packbf(bfres(v1.z), bfres(v1.w));
        uint32_t sw = SMEM_SWIZZLE_128B((uint32_t)(row * 128 + ch * 16));
        *reinterpret_cast<uint4*>(sQhi + sw) = make_uint4(hpk[0], hpk[1], hpk[2], hpk[3]);
        *reinterpret_cast<uint4*>(sQlo + sw) = make_uint4(lpk[0], lpk[1], lpk[2], lpk[3]);
    }
    __syncthreads();

    // ---- Q fragments in registers
    uint32_t qh[4][4], ql[4][4];
    {
        int arow = wid * 16 + (lid & 15);
        int acolB = (lid >> 4) * 16;
#pragma unroll
        for (int s = 0; s < 4; s++) {
            uint32_t sw = SMEM_SWIZZLE_128B((uint32_t)(arow * 128 + acolB + s * 32));
            ldsm_x4(qh[s][0], qh[s][1], qh[s][2], qh[s][3], smem_u32(sQhi) + sw);
            ldsm_x4(ql[s][0], ql[s][1], ql[s][2], ql[s][3], smem_u32(sQlo) + sw);
        }
    }

    float o[8][4];
#pragma unroll
    for (int nb = 0; nb < 8; nb++)
#pragma unroll
        for (int q = 0; q < 4; q++) o[nb][q] = 0.f;
    float m0 = -1e30f, m1 = -1e30f, l0 = 0.f, l1 = 0.f;

    for (int kt = 0; kt < ntiles; kt++) {
        const int k0 = kt * 64;
        if (kt + 1 < ntiles) {
            LOADKV(kt + 1, (kt + 1) & 1);
            CP_COMMIT();
            CP_WAIT(1);
        } else {
            CP_WAIT(0);
        }
        __syncthreads();

        uint32_t kvb = smem_u32(sm + 32768 + (kt & 1) * KV_STG);
        uint32_t sKhi_ = kvb;
        uint32_t sKlo_ = kvb + 8192;
        uint32_t sVhi_ = kvb + 16384;
        uint32_t sVlo_ = kvb + 24576;

        // ---- S = Q K^T (3-term split)
        float sacc[8][4];
#pragma unroll
        for (int nb = 0; nb < 8; nb++)
#pragma unroll
            for (int q = 0; q < 4; q++) sacc[nb][q] = 0.f;

        {
            int brow = ((lid >> 4) << 3) + (lid & 7);
            int bcolB = ((lid >> 3) & 1) * 16;
#pragma unroll
            for (int s = 0; s < 4; s++) {
                uint32_t kh[8][2], kl[8][2];
#pragma unroll
                for (int p = 0; p < 4; p++) {
                    uint32_t sw = SMEM_SWIZZLE_128B(
                        (uint32_t)((p * 16 + brow) * 128 + bcolB + s * 32));
                    ldsm_x4(kh[2 * p][0], kh[2 * p][1], kh[2 * p + 1][0],
                            kh[2 * p + 1][1], sKhi_ + sw);
                    ldsm_x4(kl[2 * p][0], kl[2 * p][1], kl[2 * p + 1][0],
                            kl[2 * p + 1][1], sKlo_ + sw);
                }
#pragma unroll
                for (int nb = 0; nb < 8; nb++) {
                    mma16816(sacc[nb], qh[s], kh[nb]);
                    mma16816(sacc[nb], qh[s], kl[nb]);
                    mma16816(sacc[nb], ql[s], kh[nb]);
                }
            }
        }

        // ---- causal mask (only diagonal tiles)
        if (kt >= 2 * qt) {
            int rowa = q0 + wid * 16 + g;
#pragma unroll
            for (int nb = 0; nb < 8; nb++) {
                int col = k0 + nb * 8 + qd * 2;
                if (col > rowa)     sacc[nb][0] = -1e30f;
                if (col + 1 > rowa) sacc[nb][1] = -1e30f;
                if (col > rowa + 8)     sacc[nb][2] = -1e30f;
                if (col + 1 > rowa + 8) sacc[nb][3] = -1e30f;
            }
        }

        // ---- online softmax
        {
            float mx0 = -1e30f, mx1 = -1e30f;
#pragma unroll
            for (int nb = 0; nb < 8; nb++) {
                mx0 = fmaxf(mx0, fmaxf(sacc[nb][0], sacc[nb][1]));
                mx1 = fmaxf(mx1, fmaxf(sacc[nb][2], sacc[nb][3]));
            }
            mx0 = fmaxf(mx0, __shfl_xor_sync(0xffffffff, mx0, 1));
            mx0 = fmaxf(mx0, __shfl_xor_sync(0xffffffff, mx0, 2));
            mx1 = fmaxf(mx1, __shfl_xor_sync(0xffffffff, mx1, 1));
            mx1 = fmaxf(mx1, __shfl_xor_sync(0xffffffff, mx1, 2));
            float mn0 = fmaxf(m0, mx0), mn1 = fmaxf(m1, mx1);
            float al0 = __expf(m0 - mn0), al1 = __expf(m1 - mn1);
            m0 = mn0; m1 = mn1;
            l0 *= al0; l1 *= al1;
            float la0 = 0.f, la1 = 0.f;
#pragma unroll
            for (int nb = 0; nb < 8; nb++) {
                sacc[nb][0] = __expf(sacc[nb][0] - mn0);
                sacc[nb][1] = __expf(sacc[nb][1] - mn0);
                sacc[nb][2] = __expf(sacc[nb][2] - mn1);
                sacc[nb][3] = __expf(sacc[nb][3] - mn1);
                la0 += sacc[nb][0] + sacc[nb][1];
                la1 += sacc[nb][2] + sacc[nb][3];
                o[nb][0] *= al0; o[nb][1] *= al0;
                o[nb][2] *= al1; o[nb][3] *= al1;
            }
            l0 += la0; l1 += la1;
        }

        // ---- pack P hi/lo as A-fragments
        uint32_t ph[4][4], pl[4][4];
#pragma unroll
        for (int j = 0; j < 4; j++) {
            float* c = sacc[2 * j];
            float* d = sacc[2 * j + 1];
            ph[j][0] = packbf(c[0], c[1]);
            ph[j][1] = packbf(c[2], c[3]);
            ph[j][2] = packbf(d[0], d[1]);
            ph[j][3] = packbf(d[2], d[3]);
            pl[j][0] = packbf(bfres(c[0]), bfres(c[1]));
            pl[j][1] = packbf(bfres(c[2]), bfres(c[3]));
            pl[j][2] = packbf(bfres(d[0]), bfres(d[1]));
            pl[j][3] = packbf(bfres(d[2]), bfres(d[3]));
        }

        // ---- O += P V (3-term split), V via ldmatrix.trans
        {
            int vrow = (lid & 15);
            int vcolB = (lid >> 4) * 16;
#pragma unroll
            for (int j = 0; j < 4; j++) {
                uint32_t vh[8][2], vl[8][2];
#pragma unroll
                for (int dj = 0; dj < 4; dj++) {
                    uint32_t sw = SMEM_SWIZZLE_128B(
                        (uint32_t)((j * 16 + vrow) * 128 + dj * 32 + vcolB));
                    ldsm_x4_t(vh[2 * dj][0], vh[2 * dj][1], vh[2 * dj + 1][0],
                              vh[2 * dj + 1][1], sVhi_ + sw);
                    ldsm_x4_t(vl[2 * dj][0], vl[2 * dj][1], vl[2 * dj + 1][0],
                              vl[2 * dj + 1][1], sVlo_ + sw);
                }
#pragma unroll
                for (int nb = 0; nb < 8; nb++) {
                    mma16816(o[nb], ph[j], vh[nb]);
                    mma16816(o[nb], ph[j], vl[nb]);
                    mma16816(o[nb], pl[j], vh[nb]);
                }
            }
        }
        __syncthreads();
    }
#undef LOADKV

    // ---- finalize: normalize, write bf16 hi/lo (fused split)
    l0 += __shfl_xor_sync(0xffffffff, l0, 1);
    l0 += __shfl_xor_sync(0xffffffff, l0, 2);
    l1 += __shfl_xor_sync(0xffffffff, l1, 1);
    l1 += __shfl_xor_sync(0xffffffff, l1, 2);
    float inv0 = 1.0f / l0, inv1 = 1.0f / l1;

    int rowa = q0 + wid * 16 + g;
    size_t oa = ((size_t)(b * SEQ + rowa)) * DMODEL + h * HDIM;
    size_t ob = ((size_t)(b * SEQ + rowa + 8)) * DMODEL + h * HDIM;
#pragma unroll
    for (int nb = 0; nb < 8; nb++) {
        int col = nb * 8 + qd * 2;
        float a0 = o[nb][0] * inv0, a1 = o[nb][1] * inv0;
        float b0 = o[nb][2] * inv1, b1 = o[nb][3] * inv1;
        *reinterpret_cast<uint32_t*>(Ohi + oa + col) = packbf(a0, a1);
        *reinterpret_cast<uint32_t*>(Olo + oa + col) = packbf(bfres(a0), bfres(a1));
        *reinterpret_cast<uint32_t*>(Ohi + ob + col) = packbf(b0, b1);
        *reinterpret_cast<uint32_t*>(Olo + ob + col) = packbf(bfres(b0), bfres(b1));
    }
}

// ---------------- launch ------------------------------------------------------
extern "C" void kernel_launch(void* const* d_in, const int* in_sizes, int n_in,
                              void* d_out, int out_size) {
    (void)in_sizes; (void)n_in; (void)out_size;
    const float* x  = (const float*)d_in[0];
    const float* Wq = (const float*)d_in[1];
    const float* Wk = (const float*)d_in[2];
    const float* Wv = (const float*)d_in[3];
    const float* Wo = (const float*)d_in[4];
    const int* poff = (const int*)d_in[5];
    float* out = (float*)d_out;

    float* qkv;
    __nv_bfloat16 *xhi, *xlo, *khi, *klo, *vhi, *vlo;
    __nv_bfloat16 *wqkvh, *wqkvl, *woh, *wol;
    cudaGetSymbolAddress((void**)&qkv, g_QKV);
    cudaGetSymbolAddress((void**)&xhi, g_xhi);
    cudaGetSymbolAddress((void**)&xlo, g_xlo);
    cudaGetSymbolAddress((void**)&khi, g_Khi);
    cudaGetSymbolAddress((void**)&klo, g_Klo);
    cudaGetSymbolAddress((void**)&vhi, g_Vhi);
    cudaGetSymbolAddress((void**)&vlo, g_Vlo);
    cudaGetSymbolAddress((void**)&wqkvh, g_wqkv_hi);
    cudaGetSymbolAddress((void**)&wqkvl, g_wqkv_lo);
    cudaGetSymbolAddress((void**)&woh, g_wo_hi);
    cudaGetSymbolAddress((void**)&wol, g_wo_lo);

    cudaFuncSetAttribute(gemm_mma3, cudaFuncAttributeMaxDynamicSharedMemorySize,
                         GEMM_SMEM_BYTES);
    cudaFuncSetAttribute(attn_mma, cudaFuncAttributeMaxDynamicSharedMemorySize,
                         ATTN2_SMEM);

    // fused prep: x split + all weight transposes in one launch
    prep_kernel<<<dim3(128, 32, 5), dim3(32, 8)>>>(
        x, Wq, Wk, Wv, Wo, xhi, xlo, wqkvh, wqkvl, woh, wol);

    // fused QKV projection
    gemm_mma3<<<dim3(NQKV / 128, ROWS / 128), 256, GEMM_SMEM_BYTES>>>(
        xhi, xlo, wqkvh, wqkvl, qkv, NQKV);

    // RoPE on Q (scale folded); K-RoPE is fused into split_kv
    {
        int totQ = ROWS * NHEADS * 32;
        rope_kernel<<<(totQ + 255) / 256, 256>>>(qkv, NHEADS, NQKV, poff, 0.125f, totQ);
    }

    // split K/V to bf16 hi/lo (K with RoPE applied)
    split_kv<<<(ROWS * (DKV / 4) + 255) / 256, 256>>>(qkv, poff, khi, klo, vhi, vlo);

    // attention -> writes hi/lo directly into xhi/xlo
    attn_mma<<<dim3(SEQ / 128, NHEADS, BATCH), 256, ATTN2_SMEM>>>(
        qkv, khi, klo, vhi, vlo, xhi, xlo);

    // O projection
    gemm_mma3<<<dim3(DMODEL / 128, ROWS / 128), 256, GEMM_SMEM_BYTES>>>(
        xhi, xlo, woh, wol, out, DMODEL);
}

// round 8
// speedup vs baseline: 3.7739x; 1.0337x over previous
#include <cuda_runtime.h>
#include <cuda_bf16.h>
#include <math.h>
#include <cstdint>

// Problem constants
#define BATCH 2
#define SEQ   2048
#define DMODEL 1024
#define NHEADS 16
#define NKV    4
#define HDIM   64
#define ROWS   (BATCH * SEQ)          // 4096
#define DKV    (NKV * HDIM)           // 256
#define KDIM   1024
#define NQKV   (DMODEL + 2 * DKV)     // 1536

// ---------------- scratch (static __device__, no allocation) ----------------
__device__ __nv_bfloat16 g_xhi[ROWS * DMODEL];     // x split; reused for attn out
__device__ __nv_bfloat16 g_xlo[ROWS * DMODEL];
__device__ __nv_bfloat16 g_Qhi[ROWS * DMODEL];
__device__ __nv_bfloat16 g_Qlo[ROWS * DMODEL];
__device__ __nv_bfloat16 g_Khi[ROWS * DKV];
__device__ __nv_bfloat16 g_Klo[ROWS * DKV];
__device__ __nv_bfloat16 g_Vhi[ROWS * DKV];
__device__ __nv_bfloat16 g_Vlo[ROWS * DKV];
__device__ __nv_bfloat16 g_wqkv_hi[NQKV * KDIM];   // transposed [N,K], Q|K|V rows
__device__ __nv_bfloat16 g_wqkv_lo[NQKV * KDIM];
__device__ __nv_bfloat16 g_wo_hi[DMODEL * KDIM];
__device__ __nv_bfloat16 g_wo_lo[DMODEL * KDIM];
__device__ float2 g_rope[SEQ * 32];                // (cos, sin) per (s, j)

__device__ __forceinline__ uint32_t smem_u32(const void* p) {
    uint32_t a;
    asm("{ .reg .u64 t; cvta.to.shared.u64 t, %1; cvt.u32.u64 %0, t; }"
        : "=r"(a) : "l"(p));
    return a;
}
#define SMEM_SWIZZLE_128B(off) ((off) ^ (((off) >> 3) & 0x70))
#define SMEM_SWIZZLE_64B(off)  ((off) ^ (((off) >> 3) & 0x30))

__device__ __forceinline__ void ldsm_x4(uint32_t& r0, uint32_t& r1,
                                        uint32_t& r2, uint32_t& r3,
                                        uint32_t addr) {
    asm volatile("ldmatrix.sync.aligned.m8n8.x4.shared.b16 {%0,%1,%2,%3}, [%4];"
                 : "=r"(r0), "=r"(r1), "=r"(r2), "=r"(r3) : "r"(addr));
}
__device__ __forceinline__ void ldsm_x4_t(uint32_t& r0, uint32_t& r1,
                                          uint32_t& r2, uint32_t& r3,
                                          uint32_t addr) {
    asm volatile("ldmatrix.sync.aligned.m8n8.x4.trans.shared.b16 {%0,%1,%2,%3}, [%4];"
                 : "=r"(r0), "=r"(r1), "=r"(r2), "=r"(r3) : "r"(addr));
}
__device__ __forceinline__ void mma16816(float* c, const uint32_t* a,
                                         const uint32_t* b) {
    asm volatile(
        "mma.sync.aligned.m16n8k16.row.col.f32.bf16.bf16.f32 "
        "{%0,%1,%2,%3}, {%4,%5,%6,%7}, {%8,%9}, {%0,%1,%2,%3};"
        : "+f"(c[0]), "+f"(c[1]), "+f"(c[2]), "+f"(c[3])
        : "r"(a[0]), "r"(a[1]), "r"(a[2]), "r"(a[3]), "r"(b[0]), "r"(b[1]));
}
__device__ __forceinline__ uint32_t packbf(float lo, float hi) {
    __nv_bfloat162 t = __floats2bfloat162_rn(lo, hi);   // .x -> low 16 bits
    return *reinterpret_cast<uint32_t*>(&t);
}
__device__ __forceinline__ float bfres(float c) {
    return c - __bfloat162float(__float2bfloat16(c));
}
__device__ __forceinline__ void cp16(uint32_t s, const void* g) {
    asm volatile("cp.async.cg.shared.global [%0], [%1], 16;" :: "r"(s), "l"(g));
}
#define CP_COMMIT() asm volatile("cp.async.commit_group;")
#define CP_WAIT(n)  asm volatile("cp.async.wait_group %0;" :: "n"(n))

// ---------------- fused prep: x split + 4 weight transposes + rope table -----
// grid (128, 32, 6), block (32, 8).
__global__ void prep_kernel(const float* __restrict__ x,
                            const float* __restrict__ Wq,
                            const float* __restrict__ Wk,
                            const float* __restrict__ Wv,
                            const float* __restrict__ Wo,
                            const int* __restrict__ offset_ptr,
                            __nv_bfloat16* __restrict__ xhi,
                            __nv_bfloat16* __restrict__ xlo,
                            __nv_bfloat16* __restrict__ wqkvh,
                            __nv_bfloat16* __restrict__ wqkvl,
                            __nv_bfloat16* __restrict__ woh,
                            __nv_bfloat16* __restrict__ wol,
                            float2* __restrict__ ropeTab) {
    const int z = blockIdx.z;
    const int tx = threadIdx.x, ty = threadIdx.y;

    if (z == 4) {   // split x: ROWS*DMODEL/4 float4 granules
        int i = (blockIdx.y * 128 + blockIdx.x) * 256 + ty * 32 + tx;
        float4 v = reinterpret_cast<const float4*>(x)[i];
        uint32_t* hp = reinterpret_cast<uint32_t*>(xhi) + 2 * i;
        uint32_t* lp = reinterpret_cast<uint32_t*>(xlo) + 2 * i;
        hp[0] = packbf(v.x, v.y); hp[1] = packbf(v.z, v.w);
        lp[0] = packbf(bfres(v.x), bfres(v.y));
        lp[1] = packbf(bfres(v.z), bfres(v.w));
        return;
    }
    if (z == 5) {   // rope table: 2048 x 32 entries
        int bid = blockIdx.y * 128 + blockIdx.x;
        if (bid >= 256) return;
        int i = bid * 256 + ty * 32 + tx;      // 0..65535
        int s = i >> 5, j = i & 31;
        float pos = (float)(s + offset_ptr[0]);
        float inv = powf(10000.0f, -(float)j / 32.0f);
        float ang = pos * inv;
        ropeTab[i] = make_float2(cosf(ang), sinf(ang));
        return;
    }

    const float* W;
    __nv_bfloat16 *hi, *lo;
    int N;
    if (z == 0)      { W = Wq; N = DMODEL; hi = wqkvh; lo = wqkvl; }
    else if (z == 1) { W = Wk; N = DKV;
                       hi = wqkvh + (size_t)DMODEL * KDIM;
                       lo = wqkvl + (size_t)DMODEL * KDIM; }
    else if (z == 2) { W = Wv; N = DKV;
                       hi = wqkvh + (size_t)(DMODEL + DKV) * KDIM;
                       lo = wqkvl + (size_t)(DMODEL + DKV) * KDIM; }
    else             { W = Wo; N = DMODEL; hi = woh; lo = wol; }

    int nb = blockIdx.x * 32;
    if (nb >= N) return;
    int kb = blockIdx.y * 32;

    __shared__ float tile[32][33];
    for (int i = ty; i < 32; i += 8)
        tile[i][tx] = W[(size_t)(kb + i) * N + nb + tx];
    __syncthreads();
    for (int i = ty; i < 32; i += 8) {
        float v = tile[tx][i];
        __nv_bfloat16 h = __float2bfloat16(v);
        __nv_bfloat16 l = __float2bfloat16(v - __bfloat162float(h));
        size_t o = (size_t)(nb + i) * KDIM + kb + tx;
        hi[o] = h;
        lo[o] = l;
    }
}

// ---------------- shared GEMM mainloop (macro) --------------------------------
#define CHUNK 32
#define NCH   (KDIM / CHUNK)          // 32
#define STG_BYTES 32768               // 4 arrays x 8KB per stage
#define GEMM_SMEM_BYTES (2 * STG_BYTES + 1024)

#define GEMM_MAINLOOP(Ahi, Alo, Bhi, Blo)                                      \
    uint32_t base = (smem_u32(dsm) + 1023u) & ~1023u;                          \
    char* sm = dsm + (base - smem_u32(dsm));                                   \
    float acc[2][8][4];                                                        \
    _Pragma("unroll")                                                          \
    for (int mb = 0; mb < 2; mb++)                                             \
        _Pragma("unroll")                                                      \
        for (int nb = 0; nb < 8; nb++)                                         \
            _Pragma("unroll")                                                  \
            for (int q = 0; q < 4; q++) acc[mb][nb][q] = 0.f;                  \
    const int lrow = t >> 2;                                                   \
    const int lg = t & 3;                                                      \
    const int a_row = lid & 15;                                                \
    const int a_colB = (lid >> 4) * 16;                                        \
    const int b_rowl = ((lid >> 4) << 3) + (lid & 7);                          \
    const int b_colB = ((lid >> 3) & 1) * 16;                                  \
    {                                                                          \
        const int k0_ = 0;                                                     \
        char* st_ = sm;                                                        \
        _Pragma("unroll")                                                      \
        for (int ii = 0; ii < 2; ii++) {                                       \
            int row_ = lrow + ii * 64;                                         \
            uint32_t sw_ = SMEM_SWIZZLE_64B((uint32_t)(row_ * 64 + lg * 16));  \
            size_t ao_ = (size_t)(rowBase + row_) * KDIM + k0_ + lg * 8;       \
            size_t bo_ = (size_t)(colBase + row_) * KDIM + k0_ + lg * 8;       \
            uint32_t sb_ = smem_u32(st_) + sw_;                                \
            cp16(sb_, Ahi + ao_);                                              \
            cp16(sb_ + 8192, Alo + ao_);                                       \
            cp16(sb_ + 16384, Bhi + bo_);                                      \
            cp16(sb_ + 24576, Blo + bo_);                                      \
        }                                                                      \
        CP_COMMIT();                                                           \
    }                                                                          \
    for (int ch = 0; ch < NCH; ch++) {                                         \
        if (ch + 1 < NCH) {                                                    \
            const int k0_ = (ch + 1) * CHUNK;                                  \
            char* st_ = sm + ((ch + 1) & 1) * STG_BYTES;                       \
            _Pragma("unroll")                                                  \
            for (int ii = 0; ii < 2; ii++) {                                   \
                int row_ = lrow + ii * 64;                                     \
                uint32_t sw_ = SMEM_SWIZZLE_64B(                               \
                    (uint32_t)(row_ * 64 + lg * 16));                          \
                size_t ao_ = (size_t)(rowBase + row_) * KDIM + k0_ + lg * 8;   \
                size_t bo_ = (size_t)(colBase + row_) * KDIM + k0_ + lg * 8;   \
                uint32_t sb_ = smem_u32(st_) + sw_;                            \
                cp16(sb_, Ahi + ao_);                                          \
                cp16(sb_ + 8192, Alo + ao_);                                   \
                cp16(sb_ + 16384, Bhi + bo_);                                  \
                cp16(sb_ + 24576, Blo + bo_);                                  \
            }                                                                  \
            CP_COMMIT();                                                       \
            CP_WAIT(1);                                                        \
        } else {                                                               \
            CP_WAIT(0);                                                        \
        }                                                                      \
        __syncthreads();                                                       \
        char* st = sm + (ch & 1) * STG_BYTES;                                  \
        uint32_t aHi = smem_u32(st);                                           \
        uint32_t aLo = aHi + 8192;                                             \
        uint32_t bHi = aHi + 16384;                                            \
        uint32_t bLo = aHi + 24576;                                            \
        _Pragma("unroll")                                                      \
        for (int s = 0; s < 2; s++) {                                          \
            uint32_t ahi[2][4], alo[2][4], bhi[8][2], blo[8][2];               \
            _Pragma("unroll")                                                  \
            for (int mb = 0; mb < 2; mb++) {                                   \
                int row = warp_m * 32 + mb * 16 + a_row;                       \
                uint32_t sw = SMEM_SWIZZLE_64B(                                \
                    (uint32_t)(row * 64 + a_colB + s * 32));                   \
                ldsm_x4(ahi[mb][0], ahi[mb][1], ahi[mb][2], ahi[mb][3],        \
                        aHi + sw);                                             \
                ldsm_x4(alo[mb][0], alo[mb][1], alo[mb][2], alo[mb][3],        \
                        aLo + sw);                                             \
            }                                                                  \
            _Pragma("unroll")                                                  \
            for (int p = 0; p < 4; p++) {                                      \
                int row = warp_n * 64 + p * 16 + b_rowl;                       \
                uint32_t sw = SMEM_SWIZZLE_64B(                                \
                    (uint32_t)(row * 64 + b_colB + s * 32));                   \
                ldsm_x4(bhi[2 * p][0], bhi[2 * p][1], bhi[2 * p + 1][0],       \
                        bhi[2 * p + 1][1], bHi + sw);                          \
                ldsm_x4(blo[2 * p][0], blo[2 * p][1], blo[2 * p + 1][0],       \
                        blo[2 * p + 1][1], bLo + sw);                          \
            }                                                                  \
            _Pragma("unroll")                                                  \
            for (int nb = 0; nb < 8; nb++) {                                   \
                _Pragma("unroll")                                              \
                for (int mb = 0; mb < 2; mb++) {                               \
                    mma16816(acc[mb][nb], ahi[mb], bhi[nb]);                   \
                    mma16816(acc[mb][nb], ahi[mb], blo[nb]);                   \
                    mma16816(acc[mb][nb], alo[mb], bhi[nb]);                   \
                }                                                              \
            }                                                                  \
        }                                                                      \
        __syncthreads();                                                       \
    }

// ---------------- GEMM with plain fp32 epilogue (O projection) ---------------
__global__ __launch_bounds__(256, 1) void gemm_mma3(
    const __nv_bfloat16* __restrict__ Ahi, const __nv_bfloat16* __restrict__ Alo,
    const __nv_bfloat16* __restrict__ Bhi, const __nv_bfloat16* __restrict__ Blo,
    float* __restrict__ C, int Ncols) {
    extern __shared__ char dsm[];
    const int t = threadIdx.x;
    const int wid = t >> 5;
    const int lid = t & 31;
    const int warp_m = wid & 3;
    const int warp_n = wid >> 2;
    const int rowBase = blockIdx.y * 128;
    const int colBase = blockIdx.x * 128;

    GEMM_MAINLOOP(Ahi, Alo, Bhi, Blo)

    const int g = lid >> 2;
    const int q = lid & 3;
#pragma unroll
    for (int mb = 0; mb < 2; mb++) {
#pragma unroll
        for (int nb = 0; nb < 8; nb++) {
            int row = rowBase + warp_m * 32 + mb * 16 + g;
            int col = colBase + warp_n * 64 + nb * 8 + q * 2;
            *reinterpret_cast<float2*>(&C[(size_t)row * Ncols + col]) =
                make_float2(acc[mb][nb][0], acc[mb][nb][1]);
            *reinterpret_cast<float2*>(&C[(size_t)(row + 8) * Ncols + col]) =
                make_float2(acc[mb][nb][2], acc[mb][nb][3]);
        }
    }
}

// ---------------- QKV GEMM with fused RoPE + hi/lo split epilogue ------------
// Warp N-tile (64) == one head's dims; RoPE pair (j, j+32) = acc[.][nb]/acc[.][nb+4].
__global__ __launch_bounds__(256, 1) void gemm_qkv(
    const __nv_bfloat16* __restrict__ Ahi, const __nv_bfloat16* __restrict__ Alo,
    const __nv_bfloat16* __restrict__ Bhi, const __nv_bfloat16* __restrict__ Blo,
    __nv_bfloat16* __restrict__ qhi, __nv_bfloat16* __restrict__ qlo,
    __nv_bfloat16* __restrict__ khi, __nv_bfloat16* __restrict__ klo,
    __nv_bfloat16* __restrict__ vhi, __nv_bfloat16* __restrict__ vlo,
    const float2* __restrict__ ropeTab) {
    extern __shared__ char dsm[];
    const int t = threadIdx.x;
    const int wid = t >> 5;
    const int lid = t & 31;
    const int warp_m = wid & 3;
    const int warp_n = wid >> 2;
    const int rowBase = blockIdx.y * 128;
    const int colBase = blockIdx.x * 128;

    GEMM_MAINLOOP(Ahi, Alo, Bhi, Blo)

    const int g2 = lid >> 2;
    const int qd2 = (lid & 3) * 2;
    const int col0 = colBase + warp_n * 64;   // 64-aligned -> one head

    if (col0 < DMODEL + DKV) {
        const bool isQ = col0 < DMODEL;
        const float sc = isQ ? 0.125f : 1.0f;   // 1/sqrt(64) folded into Q
        __nv_bfloat16* Hhi = isQ ? qhi : khi;
        __nv_bfloat16* Hlo = isQ ? qlo : klo;
        const int ncols = isQ ? DMODEL : DKV;
        const int cbase = isQ ? col0 : col0 - DMODEL;
#pragma unroll
        for (int mb = 0; mb < 2; mb++) {
            int r0 = rowBase + warp_m * 32 + mb * 16 + g2;
            int s0 = r0 & (SEQ - 1);
            int s1 = (r0 + 8) & (SEQ - 1);
#pragma unroll
            for (int nb = 0; nb < 4; nb++) {
                int j0 = nb * 8 + qd2;          // head-local dim 0..31 (even)
                float2 c00 = ropeTab[s0 * 32 + j0];
                float2 c01 = ropeTab[s0 * 32 + j0 + 1];
                float2 c10 = ropeTab[s1 * 32 + j0];
                float2 c11 = ropeTab[s1 * 32 + j0 + 1];
                float a0 = acc[mb][nb][0], a1 = acc[mb][nb][1];
                float a2 = acc[mb][nb][2], a3 = acc[mb][nb][3];
                float b0 = acc[mb][nb + 4][0], b1 = acc[mb][nb + 4][1];
                float b2 = acc[mb][nb + 4][2], b3 = acc[mb][nb + 4][3];
                float q0 = (a0 * c00.x - b0 * c00.y) * sc;
                float q1 = (a1 * c01.x - b1 * c01.y) * sc;
                float q2 = (a2 * c10.x - b2 * c10.y) * sc;
                float q3 = (a3 * c11.x - b3 * c11.y) * sc;
                float u0 = (b0 * c00.x + a0 * c00.y) * sc;
                float u1 = (b1 * c01.x + a1 * c01.y) * sc;
                float u2 = (b2 * c10.x + a2 * c10.y) * sc;
                float u3 = (b3 * c11.x + a3 * c11.y) * sc;
                size_t o0 = (size_t)r0 * ncols + cbase + j0;
                size_t o1 = (size_t)(r0 + 8) * ncols + cbase + j0;
                *reinterpret_cast<uint32_t*>(Hhi + o0) = packbf(q0, q1);
                *reinterpret_cast<uint32_t*>(Hlo + o0) = packbf(bfres(q0), bfres(q1));
                *reinterpret_cast<uint32_t*>(Hhi + o1) = packbf(q2, q3);
                *reinterpret_cast<uint32_t*>(Hlo + o1) = packbf(bfres(q2), bfres(q3));
                *reinterpret_cast<uint32_t*>(Hhi + o0 + 32) = packbf(u0, u1);
                *reinterpret_cast<uint32_t*>(Hlo + o0 + 32) = packbf(bfres(u0), bfres(u1));
                *reinterpret_cast<uint32_t*>(Hhi + o1 + 32) = packbf(u2, u3);
                *reinterpret_cast<uint32_t*>(Hlo + o1 + 32) = packbf(bfres(u2), bfres(u3));
            }
        }
    } else {
        // V: plain hi/lo split
#pragma unroll
        for (int mb = 0; mb < 2; mb++) {
            int r0 = rowBase + warp_m * 32 + mb * 16 + g2;
#pragma unroll
            for (int nb = 0; nb < 8; nb++) {
                int col = col0 - DMODEL - DKV + nb * 8 + qd2;
                float v0 = acc[mb][nb][0], v1 = acc[mb][nb][1];
                float v2 = acc[mb][nb][2], v3 = acc[mb][nb][3];
                size_t o0 = (size_t)r0 * DKV + col;
                size_t o1 = (size_t)(r0 + 8) * DKV + col;
                *reinterpret_cast<uint32_t*>(vhi + o0) = packbf(v0, v1);
                *reinterpret_cast<uint32_t*>(vlo + o0) = packbf(bfres(v0), bfres(v1));
                *reinterpret_cast<uint32_t*>(vhi + o1) = packbf(v2, v3);
                *reinterpret_cast<uint32_t*>(vlo + o1) = packbf(bfres(v2), bfres(v3));
            }
        }
    }
}

// ---------------- tensor-core flash attention (causal, GQA) ------------------
// CTA: 128 q-rows x 1 head. 8 warps. K-tile 64, cp.async double-buffered K/V.
// Q loaded via cp.async from pre-split bf16 hi/lo.
#define KV_STG 32768
#define ATTN2_SMEM (32768 + 2 * KV_STG + 1024)

__global__ __launch_bounds__(256, 1) void attn_mma(
    const __nv_bfloat16* __restrict__ Qhi, const __nv_bfloat16* __restrict__ Qlo,
    const __nv_bfloat16* __restrict__ Khi, const __nv_bfloat16* __restrict__ Klo,
    const __nv_bfloat16* __restrict__ Vhi, const __nv_bfloat16* __restrict__ Vlo,
    __nv_bfloat16* __restrict__ Ohi, __nv_bfloat16* __restrict__ Olo) {
    extern __shared__ char dsm[];
    uint32_t base = (smem_u32(dsm) + 1023u) & ~1023u;
    char* sm = dsm + (base - smem_u32(dsm));
    char* sQhi = sm;            // 16KB
    char* sQlo = sm + 16384;    // 16KB

    const int qt = (int)gridDim.x - 1 - (int)blockIdx.x;   // heavy CTAs first
    const int h  = blockIdx.y;
    const int b  = blockIdx.z;
    const int hkv = h >> 2;
    const int t  = threadIdx.x;
    const int wid = t >> 5;
    const int lid = t & 31;
    const int g = lid >> 2;
    const int qd = lid & 3;
    const int q0 = qt * 128;

    const size_t kvbase = ((size_t)b * SEQ) * DKV + (size_t)hkv * HDIM;
    const int ntiles = 2 * qt + 2;

#define LOADKV(kt_, stg_) do {                                                  \
        const int k0_ = (kt_) * 64;                                            \
        uint32_t sb0_ = smem_u32(sm + 32768 + (stg_) * KV_STG);                 \
        _Pragma("unroll")                                                       \
        for (int ii = 0; ii < 2; ii++) {                                        \
            int idx_ = t + ii * 256;                                            \
            int row_ = idx_ >> 3;                                               \
            int ch_ = idx_ & 7;                                                 \
            uint32_t sw_ = SMEM_SWIZZLE_128B((uint32_t)(row_ * 128 + ch_ * 16));\
            size_t gl_ = kvbase + (size_t)(k0_ + row_) * DKV + ch_ * 8;         \
            cp16(sb0_ + sw_, Khi + gl_);                                        \
            cp16(sb0_ + 8192 + sw_, Klo + gl_);                                 \
            cp16(sb0_ + 16384 + sw_, Vhi + gl_);                                \
            cp16(sb0_ + 24576 + sw_, Vlo + gl_);                                \
        }                                                                       \
    } while (0)

    // group A: Q hi/lo tiles via cp.async (bf16, already roped+scaled)
    {
        const __nv_bfloat16* Qh = Qhi + ((size_t)(b * SEQ + q0)) * DMODEL + h * HDIM;
        const __nv_bfloat16* Ql = Qlo + ((size_t)(b * SEQ + q0)) * DMODEL + h * HDIM;
#pragma unroll
        for (int ii = 0; ii < 4; ii++) {
            int idx = t + ii * 256;        // 0..1023
            int row = idx >> 3;
            int ch = idx & 7;
            uint32_t sw = SMEM_SWIZZLE_128B((uint32_t)(row * 128 + ch * 16));
            size_t gl = (size_t)row * DMODEL + ch * 8;
            cp16(smem_u32(sQhi) + sw, Qh + gl);
            cp16(smem_u32(sQlo) + sw, Ql + gl);
        }
        CP_COMMIT();
    }
    // group B: KV tile 0
    LOADKV(0, 0);
    CP_COMMIT();

    CP_WAIT(1);        // Q tiles complete (KV0 may still be in flight)
    __syncthreads();

    // ---- Q fragments in registers
    uint32_t qh[4][4], ql[4][4];
    {
        int arow = wid * 16 + (lid & 15);
        int acolB = (lid >> 4) * 16;
#pragma unroll
        for (int s = 0; s < 4; s++) {
            uint32_t sw = SMEM_SWIZZLE_128B((uint32_t)(arow * 128 + acolB + s * 32));
            ldsm_x4(qh[s][0], qh[s][1], qh[s][2], qh[s][3], smem_u32(sQhi) + sw);
            ldsm_x4(ql[s][0], ql[s][1], ql[s][2], ql[s][3], smem_u32(sQlo) + sw);
        }
    }

    float o[8][4];
#pragma unroll
    for (int nb = 0; nb < 8; nb++)
#pragma unroll
        for (int q = 0; q < 4; q++) o[nb][q] = 0.f;
    float m0 = -1e30f, m1 = -1e30f, l0 = 0.f, l1 = 0.f;

    for (int kt = 0; kt < ntiles; kt++) {
        const int k0 = kt * 64;
        if (kt + 1 < ntiles) {
            LOADKV(kt + 1, (kt + 1) & 1);
            CP_COMMIT();
            CP_WAIT(1);
        } else {
            CP_WAIT(0);
        }
        __syncthreads();

        uint32_t kvb = smem_u32(sm + 32768 + (kt & 1) * KV_STG);
        uint32_t sKhi_ = kvb;
        uint32_t sKlo_ = kvb + 8192;
        uint32_t sVhi_ = kvb + 16384;
        uint32_t sVlo_ = kvb + 24576;

        // ---- S = Q K^T (3-term split)
        float sacc[8][4];
#pragma unroll
        for (int nb = 0; nb < 8; nb++)
#pragma unroll
            for (int q = 0; q < 4; q++) sacc[nb][q] = 0.f;

        {
            int brow = ((lid >> 4) << 3) + (lid & 7);
            int bcolB = ((lid >> 3) & 1) * 16;
#pragma unroll
            for (int s = 0; s < 4; s++) {
                uint32_t kh[8][2], kl[8][2];
#pragma unroll
                for (int p = 0; p < 4; p++) {
                    uint32_t sw = SMEM_SWIZZLE_128B(
                        (uint32_t)((p * 16 + brow) * 128 + bcolB + s * 32));
                    ldsm_x4(kh[2 * p][0], kh[2 * p][1], kh[2 * p + 1][0],
                            kh[2 * p + 1][1], sKhi_ + sw);
                    ldsm_x4(kl[2 * p][0], kl[2 * p][1], kl[2 * p + 1][0],
                            kl[2 * p + 1][1], sKlo_ + sw);
                }
#pragma unroll
                for (int nb = 0; nb < 8; nb++) {
                    mma16816(sacc[nb], qh[s], kh[nb]);
                    mma16816(sacc[nb], qh[s], kl[nb]);
                    mma16816(sacc[nb], ql[s], kh[nb]);
                }
            }
        }

        // ---- causal mask (only diagonal tiles)
        if (kt >= 2 * qt) {
            int rowa = q0 + wid * 16 + g;
#pragma unroll
            for (int nb = 0; nb < 8; nb++) {
                int col = k0 + nb * 8 + qd * 2;
                if (col > rowa)     sacc[nb][0] = -1e30f;
                if (col + 1 > rowa) sacc[nb][1] = -1e30f;
                if (col > rowa + 8)     sacc[nb][2] = -1e30f;
                if (col + 1 > rowa + 8) sacc[nb][3] = -1e30f;
            }
        }

        // ---- online softmax
        {
            float mx0 = -1e30f, mx1 = -1e30f;
#pragma unroll
            for (int nb = 0; nb < 8; nb++) {
                mx0 = fmaxf(mx0, fmaxf(sacc[nb][0], sacc[nb][1]));
                mx1 = fmaxf(mx1, fmaxf(sacc[nb][2], sacc[nb][3]));
            }
            mx0 = fmaxf(mx0, __shfl_xor_sync(0xffffffff, mx0, 1));
            mx0 = fmaxf(mx0, __shfl_xor_sync(0xffffffff, mx0, 2));
            mx1 = fmaxf(mx1, __shfl_xor_sync(0xffffffff, mx1, 1));
            mx1 = fmaxf(mx1, __shfl_xor_sync(0xffffffff, mx1, 2));
            float mn0 = fmaxf(m0, mx0), mn1 = fmaxf(m1, mx1);
            float al0 = __expf(m0 - mn0), al1 = __expf(m1 - mn1);
            m0 = mn0; m1 = mn1;
            l0 *= al0; l1 *= al1;
            float la0 = 0.f, la1 = 0.f;
#pragma unroll
            for (int nb = 0; nb < 8; nb++) {
                sacc[nb][0] = __expf(sacc[nb][0] - mn0);
                sacc[nb][1] = __expf(sacc[nb][1] - mn0);
                sacc[nb][2] = __expf(sacc[nb][2] - mn1);
                sacc[nb][3] = __expf(sacc[nb][3] - mn1);
                la0 += sacc[nb][0] + sacc[nb][1];
                la1 += sacc[nb][2] + sacc[nb][3];
                o[nb][0] *= al0; o[nb][1] *= al0;
                o[nb][2] *= al1; o[nb][3] *= al1;
            }
            l0 += la0; l1 += la1;
        }

        // ---- pack P hi/lo as A-fragments
        uint32_t ph[4][4], pl[4][4];
#pragma unroll
        for (int j = 0; j < 4; j++) {
            float* c = sacc[2 * j];
            float* d = sacc[2 * j + 1];
            ph[j][0] = packbf(c[0], c[1]);
            ph[j][1] = packbf(c[2], c[3]);
            ph[j][2] = packbf(d[0], d[1]);
            ph[j][3] = packbf(d[2], d[3]);
            pl[j][0] = packbf(bfres(c[0]), bfres(c[1]));
            pl[j][1] = packbf(bfres(c[2]), bfres(c[3]));
            pl[j][2] = packbf(bfres(d[0]), bfres(d[1]));
            pl[j][3] = packbf(bfres(d[2]), bfres(d[3]));
        }

        // ---- O += P V (3-term split), V via ldmatrix.trans
        {
            int vrow = (lid & 15);
            int vcolB = (lid >> 4) * 16;
#pragma unroll
            for (int j = 0; j < 4; j++) {
                uint32_t vh[8][2], vl[8][2];
#pragma unroll
                for (int dj = 0; dj < 4; dj++) {
                    uint32_t sw = SMEM_SWIZZLE_128B(
                        (uint32_t)((j * 16 + vrow) * 128 + dj * 32 + vcolB));
                    ldsm_x4_t(vh[2 * dj][0], vh[2 * dj][1], vh[2 * dj + 1][0],
                              vh[2 * dj + 1][1], sVhi_ + sw);
                    ldsm_x4_t(vl[2 * dj][0], vl[2 * dj][1], vl[2 * dj + 1][0],
                              vl[2 * dj + 1][1], sVlo_ + sw);
                }
#pragma unroll
                for (int nb = 0; nb < 8; nb++) {
                    mma16816(o[nb], ph[j], vh[nb]);
                    mma16816(o[nb], ph[j], vl[nb]);
                    mma16816(o[nb], pl[j], vh[nb]);
                }
            }
        }
        __syncthreads();
    }
#undef LOADKV

    // ---- finalize: normalize, write bf16 hi/lo (fused split)
    l0 += __shfl_xor_sync(0xffffffff, l0, 1);
    l0 += __shfl_xor_sync(0xffffffff, l0, 2);
    l1 += __shfl_xor_sync(0xffffffff, l1, 1);
    l1 += __shfl_xor_sync(0xffffffff, l1, 2);
    float inv0 = 1.0f / l0, inv1 = 1.0f / l1;

    int rowa = q0 + wid * 16 + g;
    size_t oa = ((size_t)(b * SEQ + rowa)) * DMODEL + h * HDIM;
    size_t ob = ((size_t)(b * SEQ + rowa + 8)) * DMODEL + h * HDIM;
#pragma unroll
    for (int nb = 0; nb < 8; nb++) {
        int col = nb * 8 + qd * 2;
        float a0 = o[nb][0] * inv0, a1 = o[nb][1] * inv0;
        float b0 = o[nb][2] * inv1, b1 = o[nb][3] * inv1;
        *reinterpret_cast<uint32_t*>(Ohi + oa + col) = packbf(a0, a1);
        *reinterpret_cast<uint32_t*>(Olo + oa + col) = packbf(bfres(a0), bfres(a1));
        *reinterpret_cast<uint32_t*>(Ohi + ob + col) = packbf(b0, b1);
        *reinterpret_cast<uint32_t*>(Olo + ob + col) = packbf(bfres(b0), bfres(b1));
    }
}

// ---------------- launch ------------------------------------------------------
extern "C" void kernel_launch(void* const* d_in, const int* in_sizes, int n_in,
                              void* d_out, int out_size) {
    (void)in_sizes; (void)n_in; (void)out_size;
    const float* x  = (const float*)d_in[0];
    const float* Wq = (const float*)d_in[1];
    const float* Wk = (const float*)d_in[2];
    const float* Wv = (const float*)d_in[3];
    const float* Wo = (const float*)d_in[4];
    const int* poff = (const int*)d_in[5];
    float* out = (float*)d_out;

    __nv_bfloat16 *xhi, *xlo, *qhi, *qlo, *khi, *klo, *vhi, *vlo;
    __nv_bfloat16 *wqkvh, *wqkvl, *woh, *wol;
    float2* rtab;
    cudaGetSymbolAddress((void**)&xhi, g_xhi);
    cudaGetSymbolAddress((void**)&xlo, g_xlo);
    cudaGetSymbolAddress((void**)&qhi, g_Qhi);
    cudaGetSymbolAddress((void**)&qlo, g_Qlo);
    cudaGetSymbolAddress((void**)&khi, g_Khi);
    cudaGetSymbolAddress((void**)&klo, g_Klo);
    cudaGetSymbolAddress((void**)&vhi, g_Vhi);
    cudaGetSymbolAddress((void**)&vlo, g_Vlo);
    cudaGetSymbolAddress((void**)&wqkvh, g_wqkv_hi);
    cudaGetSymbolAddress((void**)&wqkvl, g_wqkv_lo);
    cudaGetSymbolAddress((void**)&woh, g_wo_hi);
    cudaGetSymbolAddress((void**)&wol, g_wo_lo);
    cudaGetSymbolAddress((void**)&rtab, g_rope);

    cudaFuncSetAttribute(gemm_mma3, cudaFuncAttributeMaxDynamicSharedMemorySize,
                         GEMM_SMEM_BYTES);
    cudaFuncSetAttribute(gemm_qkv, cudaFuncAttributeMaxDynamicSharedMemorySize,
                         GEMM_SMEM_BYTES);
    cudaFuncSetAttribute(attn_mma, cudaFuncAttributeMaxDynamicSharedMemorySize,
                         ATTN2_SMEM);

    // fused prep: x split + weight transposes + rope table (one launch)
    prep_kernel<<<dim3(128, 32, 6), dim3(32, 8)>>>(
        x, Wq, Wk, Wv, Wo, poff, xhi, xlo, wqkvh, wqkvl, woh, wol, rtab);

    // fused QKV projection + RoPE + hi/lo quantization (one launch)
    gemm_qkv<<<dim3(NQKV / 128, ROWS / 128), 256, GEMM_SMEM_BYTES>>>(
        xhi, xlo, wqkvh, wqkvl, qhi, qlo, khi, klo, vhi, vlo, rtab);

    // attention -> writes hi/lo directly into xhi/xlo
    attn_mma<<<dim3(SEQ / 128, NHEADS, BATCH), 256, ATTN2_SMEM>>>(
        qhi, qlo, khi, klo, vhi, vlo, xhi, xlo);

    // O projection
    gemm_mma3<<<dim3(DMODEL / 128, ROWS / 128), 256, GEMM_SMEM_BYTES>>>(
        xhi, xlo, woh, wol, out, DMODEL);
}

// round 9
// speedup vs baseline: 4.0265x; 1.0669x over previous
#include <cuda_runtime.h>
#include <cuda_bf16.h>
#include <math.h>
#include <cstdint>

// Problem constants
#define BATCH 2
#define SEQ   2048
#define DMODEL 1024
#define NHEADS 16
#define NKV    4
#define HDIM   64
#define ROWS   (BATCH * SEQ)          // 4096
#define DKV    (NKV * HDIM)           // 256
#define KDIM   1024
#define NQKV   (DMODEL + 2 * DKV)     // 1536

// ---------------- scratch (static __device__, no allocation) ----------------
__device__ __nv_bfloat16 g_xhi[ROWS * DMODEL];     // x split; reused for attn out
__device__ __nv_bfloat16 g_xlo[ROWS * DMODEL];
__device__ __nv_bfloat16 g_Qhi[ROWS * DMODEL];
__device__ __nv_bfloat16 g_Qlo[ROWS * DMODEL];
__device__ __nv_bfloat16 g_Khi[ROWS * DKV];
__device__ __nv_bfloat16 g_Klo[ROWS * DKV];
__device__ __nv_bfloat16 g_Vhi[ROWS * DKV];
__device__ __nv_bfloat16 g_Vlo[ROWS * DKV];
__device__ __nv_bfloat16 g_wqkv_hi[NQKV * KDIM];   // transposed [N,K], Q|K|V rows
__device__ __nv_bfloat16 g_wqkv_lo[NQKV * KDIM];
__device__ __nv_bfloat16 g_wo_hi[DMODEL * KDIM];
__device__ __nv_bfloat16 g_wo_lo[DMODEL * KDIM];
__device__ float2 g_rope[SEQ * 32];                // (cos, sin) per (s, j)

__device__ __forceinline__ uint32_t smem_u32(const void* p) {
    uint32_t a;
    asm("{ .reg .u64 t; cvta.to.shared.u64 t, %1; cvt.u32.u64 %0, t; }"
        : "=r"(a) : "l"(p));
    return a;
}
#define SMEM_SWIZZLE_128B(off) ((off) ^ (((off) >> 3) & 0x70))

__device__ __forceinline__ void ldsm_x4(uint32_t& r0, uint32_t& r1,
                                        uint32_t& r2, uint32_t& r3,
                                        uint32_t addr) {
    asm volatile("ldmatrix.sync.aligned.m8n8.x4.shared.b16 {%0,%1,%2,%3}, [%4];"
                 : "=r"(r0), "=r"(r1), "=r"(r2), "=r"(r3) : "r"(addr));
}
__device__ __forceinline__ void ldsm_x4_t(uint32_t& r0, uint32_t& r1,
                                          uint32_t& r2, uint32_t& r3,
                                          uint32_t addr) {
    asm volatile("ldmatrix.sync.aligned.m8n8.x4.trans.shared.b16 {%0,%1,%2,%3}, [%4];"
                 : "=r"(r0), "=r"(r1), "=r"(r2), "=r"(r3) : "r"(addr));
}
__device__ __forceinline__ void mma16816(float* c, const uint32_t* a,
                                         const uint32_t* b) {
    asm volatile(
        "mma.sync.aligned.m16n8k16.row.col.f32.bf16.bf16.f32 "
        "{%0,%1,%2,%3}, {%4,%5,%6,%7}, {%8,%9}, {%0,%1,%2,%3};"
        : "+f"(c[0]), "+f"(c[1]), "+f"(c[2]), "+f"(c[3])
        : "r"(a[0]), "r"(a[1]), "r"(a[2]), "r"(a[3]), "r"(b[0]), "r"(b[1]));
}
__device__ __forceinline__ uint32_t packbf(float lo, float hi) {
    __nv_bfloat162 t = __floats2bfloat162_rn(lo, hi);   // .x -> low 16 bits
    return *reinterpret_cast<uint32_t*>(&t);
}
__device__ __forceinline__ float bfres(float c) {
    return c - __bfloat162float(__float2bfloat16(c));
}
__device__ __forceinline__ void cp16(uint32_t s, const void* g) {
    asm volatile("cp.async.cg.shared.global [%0], [%1], 16;" :: "r"(s), "l"(g));
}
#define CP_COMMIT() asm volatile("cp.async.commit_group;")
#define CP_WAIT(n)  asm volatile("cp.async.wait_group %0;" :: "n"(n))

// ---------------- fused prep: x split + 4 weight transposes + rope table -----
// grid (128, 32, 6), block (32, 8).
__global__ void prep_kernel(const float* __restrict__ x,
                            const float* __restrict__ Wq,
                            const float* __restrict__ Wk,
                            const float* __restrict__ Wv,
                            const float* __restrict__ Wo,
                            const int* __restrict__ offset_ptr,
                            __nv_bfloat16* __restrict__ xhi,
                            __nv_bfloat16* __restrict__ xlo,
                            __nv_bfloat16* __restrict__ wqkvh,
                            __nv_bfloat16* __restrict__ wqkvl,
                            __nv_bfloat16* __restrict__ woh,
                            __nv_bfloat16* __restrict__ wol,
                            float2* __restrict__ ropeTab) {
    const int z = blockIdx.z;
    const int tx = threadIdx.x, ty = threadIdx.y;

    if (z == 4) {   // split x
        int i = (blockIdx.y * 128 + blockIdx.x) * 256 + ty * 32 + tx;
        float4 v = reinterpret_cast<const float4*>(x)[i];
        uint32_t* hp = reinterpret_cast<uint32_t*>(xhi) + 2 * i;
        uint32_t* lp = reinterpret_cast<uint32_t*>(xlo) + 2 * i;
        hp[0] = packbf(v.x, v.y); hp[1] = packbf(v.z, v.w);
        lp[0] = packbf(bfres(v.x), bfres(v.y));
        lp[1] = packbf(bfres(v.z), bfres(v.w));
        return;
    }
    if (z == 5) {   // rope table: 2048 x 32 entries
        int bid = blockIdx.y * 128 + blockIdx.x;
        if (bid >= 256) return;
        int i = bid * 256 + ty * 32 + tx;      // 0..65535
        int s = i >> 5, j = i & 31;
        float pos = (float)(s + offset_ptr[0]);
        float inv = powf(10000.0f, -(float)j / 32.0f);
        float ang = pos * inv;
        ropeTab[i] = make_float2(cosf(ang), sinf(ang));
        return;
    }

    const float* W;
    __nv_bfloat16 *hi, *lo;
    int N;
    if (z == 0)      { W = Wq; N = DMODEL; hi = wqkvh; lo = wqkvl; }
    else if (z == 1) { W = Wk; N = DKV;
                       hi = wqkvh + (size_t)DMODEL * KDIM;
                       lo = wqkvl + (size_t)DMODEL * KDIM; }
    else if (z == 2) { W = Wv; N = DKV;
                       hi = wqkvh + (size_t)(DMODEL + DKV) * KDIM;
                       lo = wqkvl + (size_t)(DMODEL + DKV) * KDIM; }
    else             { W = Wo; N = DMODEL; hi = woh; lo = wol; }

    int nb = blockIdx.x * 32;
    if (nb >= N) return;
    int kb = blockIdx.y * 32;

    __shared__ float tile[32][33];
    for (int i = ty; i < 32; i += 8)
        tile[i][tx] = W[(size_t)(kb + i) * N + nb + tx];
    __syncthreads();
    for (int i = ty; i < 32; i += 8) {
        float v = tile[tx][i];
        __nv_bfloat16 h = __float2bfloat16(v);
        __nv_bfloat16 l = __float2bfloat16(v - __bfloat162float(h));
        size_t o = (size_t)(nb + i) * KDIM + kb + tx;
        hi[o] = h;
        lo[o] = l;
    }
}

// ---------------- shared GEMM mainloop (macro) --------------------------------
// CHUNK=64 (128B rows, SW128), 2-stage cp.async, register-double-buffered frags.
#define CHUNK 64
#define NCH   (KDIM / CHUNK)          // 16
#define STG_BYTES 65536               // 4 arrays x 16KB per stage
#define GEMM_SMEM_BYTES (2 * STG_BYTES + 1024)

#define GQ_LOAD_CHUNK(ch_, stg_) do {                                          \
        const int k0_ = (ch_) * CHUNK;                                         \
        uint32_t sb0_ = smem_u32(sm + (stg_) * STG_BYTES);                     \
        _Pragma("unroll")                                                      \
        for (int ii = 0; ii < 4; ii++) {                                       \
            int idx_ = t + ii * 256;                                           \
            int row_ = idx_ >> 3;                                              \
            int c_ = idx_ & 7;                                                 \
            uint32_t sw_ = SMEM_SWIZZLE_128B((uint32_t)(row_ * 128 + c_ * 16));\
            size_t ao_ = (size_t)(rowBase + row_) * KDIM + k0_ + c_ * 8;       \
            size_t bo_ = (size_t)(colBase + row_) * KDIM + k0_ + c_ * 8;       \
            cp16(sb0_ + sw_, Ahi + ao_);                                       \
            cp16(sb0_ + 16384 + sw_, Alo + ao_);                               \
            cp16(sb0_ + 32768 + sw_, Bhi + bo_);                               \
            cp16(sb0_ + 49152 + sw_, Blo + bo_);                               \
        }                                                                      \
    } while (0)

#define GQ_LOAD_FRAGS(set_, s_) do {                                           \
        _Pragma("unroll")                                                      \
        for (int mb = 0; mb < 2; mb++) {                                       \
            int row = warp_m * 32 + mb * 16 + a_row;                           \
            uint32_t sw = SMEM_SWIZZLE_128B(                                   \
                (uint32_t)(row * 128 + a_colB + (s_) * 32));                   \
            ldsm_x4(fa_hi[set_][mb][0], fa_hi[set_][mb][1],                    \
                    fa_hi[set_][mb][2], fa_hi[set_][mb][3], aHi + sw);         \
            ldsm_x4(fa_lo[set_][mb][0], fa_lo[set_][mb][1],                    \
                    fa_lo[set_][mb][2], fa_lo[set_][mb][3], aLo + sw);         \
        }                                                                      \
        _Pragma("unroll")                                                      \
        for (int p = 0; p < 4; p++) {                                          \
            int row = warp_n * 64 + p * 16 + b_rowl;                           \
            uint32_t sw = SMEM_SWIZZLE_128B(                                   \
                (uint32_t)(row * 128 + b_colB + (s_) * 32));                   \
            ldsm_x4(fb_hi[set_][2 * p][0], fb_hi[set_][2 * p][1],              \
                    fb_hi[set_][2 * p + 1][0], fb_hi[set_][2 * p + 1][1],      \
                    bHi + sw);                                                 \
            ldsm_x4(fb_lo[set_][2 * p][0], fb_lo[set_][2 * p][1],              \
                    fb_lo[set_][2 * p + 1][0], fb_lo[set_][2 * p + 1][1],      \
                    bLo + sw);                                                 \
        }                                                                      \
    } while (0)

#define GQ_MMA(set_) do {                                                      \
        _Pragma("unroll")                                                      \
        for (int nb = 0; nb < 8; nb++) {                                       \
            _Pragma("unroll")                                                  \
            for (int mb = 0; mb < 2; mb++) {                                   \
                mma16816(acc[mb][nb], fa_hi[set_][mb], fb_hi[set_][nb]);       \
                mma16816(acc[mb][nb], fa_hi[set_][mb], fb_lo[set_][nb]);       \
                mma16816(acc[mb][nb], fa_lo[set_][mb], fb_hi[set_][nb]);       \
            }                                                                  \
        }                                                                      \
    } while (0)

#define GEMM_MAINLOOP(Ahi, Alo, Bhi, Blo)                                      \
    uint32_t base = (smem_u32(dsm) + 1023u) & ~1023u;                          \
    char* sm = dsm + (base - smem_u32(dsm));                                   \
    float acc[2][8][4];                                                        \
    _Pragma("unroll")                                                          \
    for (int mb = 0; mb < 2; mb++)                                             \
        _Pragma("unroll")                                                      \
        for (int nb = 0; nb < 8; nb++)                                         \
            _Pragma("unroll")                                                  \
            for (int q = 0; q < 4; q++) acc[mb][nb][q] = 0.f;                  \
    const int a_row = lid & 15;                                                \
    const int a_colB = (lid >> 4) * 16;                                        \
    const int b_rowl = ((lid >> 4) << 3) + (lid & 7);                          \
    const int b_colB = ((lid >> 3) & 1) * 16;                                  \
    uint32_t fa_hi[2][2][4], fa_lo[2][2][4];                                   \
    uint32_t fb_hi[2][8][2], fb_lo[2][8][2];                                   \
    GQ_LOAD_CHUNK(0, 0);                                                       \
    CP_COMMIT();                                                               \
    for (int ch = 0; ch < NCH; ch++) {                                         \
        CP_WAIT(0);                                                            \
        __syncthreads();                                                       \
        uint32_t stg0 = smem_u32(sm + (ch & 1) * STG_BYTES);                   \
        uint32_t aHi = stg0;                                                   \
        uint32_t aLo = stg0 + 16384;                                           \
        uint32_t bHi = stg0 + 32768;                                           \
        uint32_t bLo = stg0 + 49152;                                           \
        GQ_LOAD_FRAGS(0, 0);                                                   \
        if (ch + 1 < NCH) {                                                    \
            GQ_LOAD_CHUNK(ch + 1, (ch + 1) & 1);                               \
            CP_COMMIT();                                                       \
        }                                                                      \
        _Pragma("unroll")                                                      \
        for (int s = 0; s < 4; s++) {                                          \
            if (s < 3) GQ_LOAD_FRAGS((s + 1) & 1, s + 1);                      \
            GQ_MMA(s & 1);                                                     \
        }                                                                      \
    }

// ---------------- GEMM with plain fp32 epilogue (O projection) ---------------
__global__ __launch_bounds__(256, 1) void gemm_mma3(
    const __nv_bfloat16* __restrict__ Ahi, const __nv_bfloat16* __restrict__ Alo,
    const __nv_bfloat16* __restrict__ Bhi, const __nv_bfloat16* __restrict__ Blo,
    float* __restrict__ C, int Ncols) {
    extern __shared__ char dsm[];
    const int t = threadIdx.x;
    const int wid = t >> 5;
    const int lid = t & 31;
    const int warp_m = wid & 3;
    const int warp_n = wid >> 2;
    const int rowBase = blockIdx.y * 128;
    const int colBase = blockIdx.x * 128;

    GEMM_MAINLOOP(Ahi, Alo, Bhi, Blo)

    const int g = lid >> 2;
    const int q = lid & 3;
#pragma unroll
    for (int mb = 0; mb < 2; mb++) {
#pragma unroll
        for (int nb = 0; nb < 8; nb++) {
            int row = rowBase + warp_m * 32 + mb * 16 + g;
            int col = colBase + warp_n * 64 + nb * 8 + q * 2;
            *reinterpret_cast<float2*>(&C[(size_t)row * Ncols + col]) =
                make_float2(acc[mb][nb][0], acc[mb][nb][1]);
            *reinterpret_cast<float2*>(&C[(size_t)(row + 8) * Ncols + col]) =
                make_float2(acc[mb][nb][2], acc[mb][nb][3]);
        }
    }
}

// ---------------- QKV GEMM with fused RoPE + hi/lo split epilogue ------------
__global__ __launch_bounds__(256, 1) void gemm_qkv(
    const __nv_bfloat16* __restrict__ Ahi, const __nv_bfloat16* __restrict__ Alo,
    const __nv_bfloat16* __restrict__ Bhi, const __nv_bfloat16* __restrict__ Blo,
    __nv_bfloat16* __restrict__ qhi, __nv_bfloat16* __restrict__ qlo,
    __nv_bfloat16* __restrict__ khi, __nv_bfloat16* __restrict__ klo,
    __nv_bfloat16* __restrict__ vhi, __nv_bfloat16* __restrict__ vlo,
    const float2* __restrict__ ropeTab) {
    extern __shared__ char dsm[];
    const int t = threadIdx.x;
    const int wid = t >> 5;
    const int lid = t & 31;
    const int warp_m = wid & 3;
    const int warp_n = wid >> 2;
    const int rowBase = blockIdx.y * 128;
    const int colBase = blockIdx.x * 128;

    GEMM_MAINLOOP(Ahi, Alo, Bhi, Blo)

    const int g2 = lid >> 2;
    const int qd2 = (lid & 3) * 2;
    const int col0 = colBase + warp_n * 64;   // 64-aligned -> one head

    if (col0 < DMODEL + DKV) {
        const bool isQ = col0 < DMODEL;
        const float sc = isQ ? 0.125f : 1.0f;   // 1/sqrt(64) folded into Q
        __nv_bfloat16* Hhi = isQ ? qhi : khi;
        __nv_bfloat16* Hlo = isQ ? qlo : klo;
        const int ncols = isQ ? DMODEL : DKV;
        const int cbase = isQ ? col0 : col0 - DMODEL;
#pragma unroll
        for (int mb = 0; mb < 2; mb++) {
            int r0 = rowBase + warp_m * 32 + mb * 16 + g2;
            int s0 = r0 & (SEQ - 1);
            int s1 = (r0 + 8) & (SEQ - 1);
#pragma unroll
            for (int nb = 0; nb < 4; nb++) {
                int j0 = nb * 8 + qd2;
                float2 c00 = ropeTab[s0 * 32 + j0];
                float2 c01 = ropeTab[s0 * 32 + j0 + 1];
                float2 c10 = ropeTab[s1 * 32 + j0];
                float2 c11 = ropeTab[s1 * 32 + j0 + 1];
                float a0 = acc[mb][nb][0], a1 = acc[mb][nb][1];
                float a2 = acc[mb][nb][2], a3 = acc[mb][nb][3];
                float b0 = acc[mb][nb + 4][0], b1 = acc[mb][nb + 4][1];
                float b2 = acc[mb][nb + 4][2], b3 = acc[mb][nb + 4][3];
                float q0 = (a0 * c00.x - b0 * c00.y) * sc;
                float q1 = (a1 * c01.x - b1 * c01.y) * sc;
                float q2 = (a2 * c10.x - b2 * c10.y) * sc;
                float q3 = (a3 * c11.x - b3 * c11.y) * sc;
                float u0 = (b0 * c00.x + a0 * c00.y) * sc;
                float u1 = (b1 * c01.x + a1 * c01.y) * sc;
                float u2 = (b2 * c10.x + a2 * c10.y) * sc;
                float u3 = (b3 * c11.x + a3 * c11.y) * sc;
                size_t o0 = (size_t)r0 * ncols + cbase + j0;
                size_t o1 = (size_t)(r0 + 8) * ncols + cbase + j0;
                *reinterpret_cast<uint32_t*>(Hhi + o0) = packbf(q0, q1);
                *reinterpret_cast<uint32_t*>(Hlo + o0) = packbf(bfres(q0), bfres(q1));
                *reinterpret_cast<uint32_t*>(Hhi + o1) = packbf(q2, q3);
                *reinterpret_cast<uint32_t*>(Hlo + o1) = packbf(bfres(q2), bfres(q3));
                *reinterpret_cast<uint32_t*>(Hhi + o0 + 32) = packbf(u0, u1);
                *reinterpret_cast<uint32_t*>(Hlo + o0 + 32) = packbf(bfres(u0), bfres(u1));
                *reinterpret_cast<uint32_t*>(Hhi + o1 + 32) = packbf(u2, u3);
                *reinterpret_cast<uint32_t*>(Hlo + o1 + 32) = packbf(bfres(u2), bfres(u3));
            }
        }
    } else {
        // V: plain hi/lo split
#pragma unroll
        for (int mb = 0; mb < 2; mb++) {
            int r0 = rowBase + warp_m * 32 + mb * 16 + g2;
#pragma unroll
            for (int nb = 0; nb < 8; nb++) {
                int col = col0 - DMODEL - DKV + nb * 8 + qd2;
                float v0 = acc[mb][nb][0], v1 = acc[mb][nb][1];
                float v2 = acc[mb][nb][2], v3 = acc[mb][nb][3];
                size_t o0 = (size_t)r0 * DKV + col;
                size_t o1 = (size_t)(r0 + 8) * DKV + col;
                *reinterpret_cast<uint32_t*>(vhi + o0) = packbf(v0, v1);
                *reinterpret_cast<uint32_t*>(vlo + o0) = packbf(bfres(v0), bfres(v1));
                *reinterpret_cast<uint32_t*>(vhi + o1) = packbf(v2, v3);
                *reinterpret_cast<uint32_t*>(vlo + o1) = packbf(bfres(v2), bfres(v3));
            }
        }
    }
}

// ---------------- tensor-core flash attention (causal, GQA) ------------------
#define KV_STG 32768
#define ATTN2_SMEM (32768 + 2 * KV_STG + 1024)

__global__ __launch_bounds__(256, 1) void attn_mma(
    const __nv_bfloat16* __restrict__ Qhi, const __nv_bfloat16* __restrict__ Qlo,
    const __nv_bfloat16* __restrict__ Khi, const __nv_bfloat16* __restrict__ Klo,
    const __nv_bfloat16* __restrict__ Vhi, const __nv_bfloat16* __restrict__ Vlo,
    __nv_bfloat16* __restrict__ Ohi, __nv_bfloat16* __restrict__ Olo) {
    extern __shared__ char dsm[];
    uint32_t base = (smem_u32(dsm) + 1023u) & ~1023u;
    char* sm = dsm + (base - smem_u32(dsm));
    char* sQhi = sm;            // 16KB
    char* sQlo = sm + 16384;    // 16KB

    const int qt = (int)gridDim.x - 1 - (int)blockIdx.x;   // heavy CTAs first
    const int h  = blockIdx.y;
    const int b  = blockIdx.z;
    const int hkv = h >> 2;
    const int t  = threadIdx.x;
    const int wid = t >> 5;
    const int lid = t & 31;
    const int g = lid >> 2;
    const int qd = lid & 3;
    const int q0 = qt * 128;

    const size_t kvbase = ((size_t)b * SEQ) * DKV + (size_t)hkv * HDIM;
    const int ntiles = 2 * qt + 2;

#define LOADKV(kt_, stg_) do {                                                  \
        const int k0_ = (kt_) * 64;                                            \
        uint32_t sb0_ = smem_u32(sm + 32768 + (stg_) * KV_STG);                 \
        _Pragma("unroll")                                                       \
        for (int ii = 0; ii < 2; ii++) {                                        \
            int idx_ = t + ii * 256;                                            \
            int row_ = idx_ >> 3;                                               \
            int ch_ = idx_ & 7;                                                 \
            uint32_t sw_ = SMEM_SWIZZLE_128B((uint32_t)(row_ * 128 + ch_ * 16));\
            size_t gl_ = kvbase + (size_t)(k0_ + row_) * DKV + ch_ * 8;         \
            cp16(sb0_ + sw_, Khi + gl_);                                        \
            cp16(sb0_ + 8192 + sw_, Klo + gl_);                                 \
            cp16(sb0_ + 16384 + sw_, Vhi + gl_);                                \
            cp16(sb0_ + 24576 + sw_, Vlo + gl_);                                \
        }                                                                       \
    } while (0)

    // group A: Q hi/lo tiles via cp.async
    {
        const __nv_bfloat16* Qh = Qhi + ((size_t)(b * SEQ + q0)) * DMODEL + h * HDIM;
        const __nv_bfloat16* Ql = Qlo + ((size_t)(b * SEQ + q0)) * DMODEL + h * HDIM;
#pragma unroll
        for (int ii = 0; ii < 4; ii++) {
            int idx = t + ii * 256;        // 0..1023
            int row = idx >> 3;
            int ch = idx & 7;
            uint32_t sw = SMEM_SWIZZLE_128B((uint32_t)(row * 128 + ch * 16));
            size_t gl = (size_t)row * DMODEL + ch * 8;
            cp16(smem_u32(sQhi) + sw, Qh + gl);
            cp16(smem_u32(sQlo) + sw, Ql + gl);
        }
        CP_COMMIT();
    }
    // group B: KV tile 0
    LOADKV(0, 0);
    CP_COMMIT();

    CP_WAIT(1);        // Q tiles complete
    __syncthreads();

    // ---- Q fragments in registers
    uint32_t qh[4][4], ql[4][4];
    {
        int arow = wid * 16 + (lid & 15);
        int acolB = (lid >> 4) * 16;
#pragma unroll
        for (int s = 0; s < 4; s++) {
            uint32_t sw = SMEM_SWIZZLE_128B((uint32_t)(arow * 128 + acolB + s * 32));
            ldsm_x4(qh[s][0], qh[s][1], qh[s][2], qh[s][3], smem_u32(sQhi) + sw);
            ldsm_x4(ql[s][0], ql[s][1], ql[s][2], ql[s][3], smem_u32(sQlo) + sw);
        }
    }

    float o[8][4];
#pragma unroll
    for (int nb = 0; nb < 8; nb++)
#pragma unroll
        for (int q = 0; q < 4; q++) o[nb][q] = 0.f;
    float m0 = -1e30f, m1 = -1e30f, l0 = 0.f, l1 = 0.f;

    for (int kt = 0; kt < ntiles; kt++) {
        const int k0 = kt * 64;
        if (kt + 1 < ntiles) {
            LOADKV(kt + 1, (kt + 1) & 1);
            CP_COMMIT();
            CP_WAIT(1);
        } else {
            CP_WAIT(0);
        }
        __syncthreads();

        uint32_t kvb = smem_u32(sm + 32768 + (kt & 1) * KV_STG);
        uint32_t sKhi_ = kvb;
        uint32_t sKlo_ = kvb + 8192;
        uint32_t sVhi_ = kvb + 16384;
        uint32_t sVlo_ = kvb + 24576;

        // ---- S = Q K^T (3-term split)
        float sacc[8][4];
#pragma unroll
        for (int nb = 0; nb < 8; nb++)
#pragma unroll
            for (int q = 0; q < 4; q++) sacc[nb][q] = 0.f;

        {
            int brow = ((lid >> 4) << 3) + (lid & 7);
            int bcolB = ((lid >> 3) & 1) * 16;
#pragma unroll
            for (int s = 0; s < 4; s++) {
                uint32_t kh[8][2], kl[8][2];
#pragma unroll
                for (int p = 0; p < 4; p++) {
                    uint32_t sw = SMEM_SWIZZLE_128B(
                        (uint32_t)((p * 16 + brow) * 128 + bcolB + s * 32));
                    ldsm_x4(kh[2 * p][0], kh[2 * p][1], kh[2 * p + 1][0],
                            kh[2 * p + 1][1], sKhi_ + sw);
                    ldsm_x4(kl[2 * p][0], kl[2 * p][1], kl[2 * p + 1][0],
                            kl[2 * p + 1][1], sKlo_ + sw);
                }
#pragma unroll
                for (int nb = 0; nb < 8; nb++) {
                    mma16816(sacc[nb], qh[s], kh[nb]);
                    mma16816(sacc[nb], qh[s], kl[nb]);
                    mma16816(sacc[nb], ql[s], kh[nb]);
                }
            }
        }

        // ---- causal mask (only diagonal tiles)
        if (kt >= 2 * qt) {
            int rowa = q0 + wid * 16 + g;
#pragma unroll
            for (int nb = 0; nb < 8; nb++) {
                int col = k0 + nb * 8 + qd * 2;
                if (col > rowa)     sacc[nb][0] = -1e30f;
                if (col + 1 > rowa) sacc[nb][1] = -1e30f;
                if (col > rowa + 8)     sacc[nb][2] = -1e30f;
                if (col + 1 > rowa + 8) sacc[nb][3] = -1e30f;
            }
        }

        // ---- online softmax
        {
            float mx0 = -1e30f, mx1 = -1e30f;
#pragma unroll
            for (int nb = 0; nb < 8; nb++) {
                mx0 = fmaxf(mx0, fmaxf(sacc[nb][0], sacc[nb][1]));
                mx1 = fmaxf(mx1, fmaxf(sacc[nb][2], sacc[nb][3]));
            }
            mx0 = fmaxf(mx0, __shfl_xor_sync(0xffffffff, mx0, 1));
            mx0 = fmaxf(mx0, __shfl_xor_sync(0xffffffff, mx0, 2));
            mx1 = fmaxf(mx1, __shfl_xor_sync(0xffffffff, mx1, 1));
            mx1 = fmaxf(mx1, __shfl_xor_sync(0xffffffff, mx1, 2));
            float mn0 = fmaxf(m0, mx0), mn1 = fmaxf(m1, mx1);
            float al0 = __expf(m0 - mn0), al1 = __expf(m1 - mn1);
            m0 = mn0; m1 = mn1;
            l0 *= al0; l1 *= al1;
            float la0 = 0.f, la1 = 0.f;
#pragma unroll
            for (int nb = 0; nb < 8; nb++) {
                sacc[nb][0] = __expf(sacc[nb][0] - mn0);
                sacc[nb][1] = __expf(sacc[nb][1] - mn0);
                sacc[nb][2] = __expf(sacc[nb][2] - mn1);
                sacc[nb][3] = __expf(sacc[nb][3] - mn1);
                la0 += sacc[nb][0] + sacc[nb][1];
                la1 += sacc[nb][2] + sacc[nb][3];
                o[nb][0] *= al0; o[nb][1] *= al0;
                o[nb][2] *= al1; o[nb][3] *= al1;
            }
            l0 += la0; l1 += la1;
        }

        // ---- pack P hi/lo as A-fragments
        uint32_t ph[4][4], pl[4][4];
#pragma unroll
        for (int j = 0; j < 4; j++) {
            float* c = sacc[2 * j];
            float* d = sacc[2 * j + 1];
            ph[j][0] = packbf(c[0], c[1]);
            ph[j][1] = packbf(c[2], c[3]);
            ph[j][2] = packbf(d[0], d[1]);
            ph[j][3] = packbf(d[2], d[3]);
            pl[j][0] = packbf(bfres(c[0]), bfres(c[1]));
            pl[j][1] = packbf(bfres(c[2]), bfres(c[3]));
            pl[j][2] = packbf(bfres(d[0]), bfres(d[1]));
            pl[j][3] = packbf(bfres(d[2]), bfres(d[3]));
        }

        // ---- O += P V (3-term split), V via ldmatrix.trans
        {
            int vrow = (lid & 15);
            int vcolB = (lid >> 4) * 16;
#pragma unroll
            for (int j = 0; j < 4; j++) {
                uint32_t vh[8][2], vl[8][2];
#pragma unroll
                for (int dj = 0; dj < 4; dj++) {
                    uint32_t sw = SMEM_SWIZZLE_128B(
                        (uint32_t)((j * 16 + vrow) * 128 + dj * 32 + vcolB));
                    ldsm_x4_t(vh[2 * dj][0], vh[2 * dj][1], vh[2 * dj + 1][0],
                              vh[2 * dj + 1][1], sVhi_ + sw);
                    ldsm_x4_t(vl[2 * dj][0], vl[2 * dj][1], vl[2 * dj + 1][0],
                              vl[2 * dj + 1][1], sVlo_ + sw);
                }
#pragma unroll
                for (int nb = 0; nb < 8; nb++) {
                    mma16816(o[nb], ph[j], vh[nb]);
                    mma16816(o[nb], ph[j], vl[nb]);
                    mma16816(o[nb], pl[j], vh[nb]);
                }
            }
        }
        __syncthreads();
    }
#undef LOADKV

    // ---- finalize: normalize, write bf16 hi/lo (fused split)
    l0 += __shfl_xor_sync(0xffffffff, l0, 1);
    l0 += __shfl_xor_sync(0xffffffff, l0, 2);
    l1 += __shfl_xor_sync(0xffffffff, l1, 1);
    l1 += __shfl_xor_sync(0xffffffff, l1, 2);
    float inv0 = 1.0f / l0, inv1 = 1.0f / l1;

    int rowa = q0 + wid * 16 + g;
    size_t oa = ((size_t)(b * SEQ + rowa)) * DMODEL + h * HDIM;
    size_t ob = ((size_t)(b * SEQ + rowa + 8)) * DMODEL + h * HDIM;
#pragma unroll
    for (int nb = 0; nb < 8; nb++) {
        int col = nb * 8 + qd * 2;
        float a0 = o[nb][0] * inv0, a1 = o[nb][1] * inv0;
        float b0 = o[nb][2] * inv1, b1 = o[nb][3] * inv1;
        *reinterpret_cast<uint32_t*>(Ohi + oa + col) = packbf(a0, a1);
        *reinterpret_cast<uint32_t*>(Olo + oa + col) = packbf(bfres(a0), bfres(a1));
        *reinterpret_cast<uint32_t*>(Ohi + ob + col) = packbf(b0, b1);
        *reinterpret_cast<uint32_t*>(Olo + ob + col) = packbf(bfres(b0), bfres(b1));
    }
}

// ---------------- launch ------------------------------------------------------
extern "C" void kernel_launch(void* const* d_in, const int* in_sizes, int n_in,
                              void* d_out, int out_size) {
    (void)in_sizes; (void)n_in; (void)out_size;
    const float* x  = (const float*)d_in[0];
    const float* Wq = (const float*)d_in[1];
    const float* Wk = (const float*)d_in[2];
    const float* Wv = (const float*)d_in[3];
    const float* Wo = (const float*)d_in[4];
    const int* poff = (const int*)d_in[5];
    float* out = (float*)d_out;

    __nv_bfloat16 *xhi, *xlo, *qhi, *qlo, *khi, *klo, *vhi, *vlo;
    __nv_bfloat16 *wqkvh, *wqkvl, *woh, *wol;
    float2* rtab;
    cudaGetSymbolAddress((void**)&xhi, g_xhi);
    cudaGetSymbolAddress((void**)&xlo, g_xlo);
    cudaGetSymbolAddress((void**)&qhi, g_Qhi);
    cudaGetSymbolAddress((void**)&qlo, g_Qlo);
    cudaGetSymbolAddress((void**)&khi, g_Khi);
    cudaGetSymbolAddress((void**)&klo, g_Klo);
    cudaGetSymbolAddress((void**)&vhi, g_Vhi);
    cudaGetSymbolAddress((void**)&vlo, g_Vlo);
    cudaGetSymbolAddress((void**)&wqkvh, g_wqkv_hi);
    cudaGetSymbolAddress((void**)&wqkvl, g_wqkv_lo);
    cudaGetSymbolAddress((void**)&woh, g_wo_hi);
    cudaGetSymbolAddress((void**)&wol, g_wo_lo);
    cudaGetSymbolAddress((void**)&rtab, g_rope);

    cudaFuncSetAttribute(gemm_mma3, cudaFuncAttributeMaxDynamicSharedMemorySize,
                         GEMM_SMEM_BYTES);
    cudaFuncSetAttribute(gemm_qkv, cudaFuncAttributeMaxDynamicSharedMemorySize,
                         GEMM_SMEM_BYTES);
    cudaFuncSetAttribute(attn_mma, cudaFuncAttributeMaxDynamicSharedMemorySize,
                         ATTN2_SMEM);

    // fused prep: x split + weight transposes + rope table (one launch)
    prep_kernel<<<dim3(128, 32, 6), dim3(32, 8)>>>(
        x, Wq, Wk, Wv, Wo, poff, xhi, xlo, wqkvh, wqkvl, woh, wol, rtab);

    // fused QKV projection + RoPE + hi/lo quantization (one launch)
    gemm_qkv<<<dim3(NQKV / 128, ROWS / 128), 256, GEMM_SMEM_BYTES>>>(
        xhi, xlo, wqkvh, wqkvl, qhi, qlo, khi, klo, vhi, vlo, rtab);

    // attention -> writes hi/lo directly into xhi/xlo
    attn_mma<<<dim3(SEQ / 128, NHEADS, BATCH), 256, ATTN2_SMEM>>>(
        qhi, qlo, khi, klo, vhi, vlo, xhi, xlo);

    // O projection
    gemm_mma3<<<dim3(DMODEL / 128, ROWS / 128), 256, GEMM_SMEM_BYTES>>>(
        xhi, xlo, woh, wol, out, DMODEL);
}

// round 10
// speedup vs baseline: 4.0444x; 1.0045x over previous
#include <cuda_runtime.h>
#include <cuda_bf16.h>
#include <math.h>
#include <cstdint>

// Problem constants
#define BATCH 2
#define SEQ   2048
#define DMODEL 1024
#define NHEADS 16
#define NKV    4
#define HDIM   64
#define ROWS   (BATCH * SEQ)          // 4096
#define DKV    (NKV * HDIM)           // 256
#define KDIM   1024
#define NQKV   (DMODEL + 2 * DKV)     // 1536

// ---------------- scratch (static __device__, no allocation) ----------------
__device__ __nv_bfloat16 g_xhi[ROWS * DMODEL];     // x split; reused for attn out
__device__ __nv_bfloat16 g_xlo[ROWS * DMODEL];
__device__ __nv_bfloat16 g_Qhi[ROWS * DMODEL];
__device__ __nv_bfloat16 g_Qlo[ROWS * DMODEL];
__device__ __nv_bfloat16 g_Khi[ROWS * DKV];
__device__ __nv_bfloat16 g_Klo[ROWS * DKV];
__device__ __nv_bfloat16 g_Vhi[ROWS * DKV];
__device__ __nv_bfloat16 g_Vlo[ROWS * DKV];
__device__ __nv_bfloat16 g_wqkv_hi[NQKV * KDIM];   // transposed [N,K], Q|K|V rows
__device__ __nv_bfloat16 g_wqkv_lo[NQKV * KDIM];
__device__ __nv_bfloat16 g_wo_hi[DMODEL * KDIM];
__device__ __nv_bfloat16 g_wo_lo[DMODEL * KDIM];
__device__ float2 g_rope[SEQ * 32];                // (cos, sin) per (s, j)

__device__ __forceinline__ uint32_t smem_u32(const void* p) {
    uint32_t a;
    asm("{ .reg .u64 t; cvta.to.shared.u64 t, %1; cvt.u32.u64 %0, t; }"
        : "=r"(a) : "l"(p));
    return a;
}
#define SMEM_SWIZZLE_128B(off) ((off) ^ (((off) >> 3) & 0x70))

__device__ __forceinline__ void ldsm_x4(uint32_t& r0, uint32_t& r1,
                                        uint32_t& r2, uint32_t& r3,
                                        uint32_t addr) {
    asm volatile("ldmatrix.sync.aligned.m8n8.x4.shared.b16 {%0,%1,%2,%3}, [%4];"
                 : "=r"(r0), "=r"(r1), "=r"(r2), "=r"(r3) : "r"(addr));
}
__device__ __forceinline__ void ldsm_x4_t(uint32_t& r0, uint32_t& r1,
                                          uint32_t& r2, uint32_t& r3,
                                          uint32_t addr) {
    asm volatile("ldmatrix.sync.aligned.m8n8.x4.trans.shared.b16 {%0,%1,%2,%3}, [%4];"
                 : "=r"(r0), "=r"(r1), "=r"(r2), "=r"(r3) : "r"(addr));
}
__device__ __forceinline__ void mma16816(float* c, const uint32_t* a,
                                         const uint32_t* b) {
    asm volatile(
        "mma.sync.aligned.m16n8k16.row.col.f32.bf16.bf16.f32 "
        "{%0,%1,%2,%3}, {%4,%5,%6,%7}, {%8,%9}, {%0,%1,%2,%3};"
        : "+f"(c[0]), "+f"(c[1]), "+f"(c[2]), "+f"(c[3])
        : "r"(a[0]), "r"(a[1]), "r"(a[2]), "r"(a[3]), "r"(b[0]), "r"(b[1]));
}
__device__ __forceinline__ uint32_t packbf(float lo, float hi) {
    __nv_bfloat162 t = __floats2bfloat162_rn(lo, hi);   // .x -> low 16 bits
    return *reinterpret_cast<uint32_t*>(&t);
}
__device__ __forceinline__ float bfres(float c) {
    return c - __bfloat162float(__float2bfloat16(c));
}
__device__ __forceinline__ void cp16(uint32_t s, const void* g) {
    asm volatile("cp.async.cg.shared.global [%0], [%1], 16;" :: "r"(s), "l"(g));
}
#define CP_COMMIT() asm volatile("cp.async.commit_group;")
#define CP_WAIT(n)  asm volatile("cp.async.wait_group %0;" :: "n"(n))

// ---------------- fused prep: x split + 4 weight transposes + rope table -----
__global__ void prep_kernel(const float* __restrict__ x,
                            const float* __restrict__ Wq,
                            const float* __restrict__ Wk,
                            const float* __restrict__ Wv,
                            const float* __restrict__ Wo,
                            const int* __restrict__ offset_ptr,
                            __nv_bfloat16* __restrict__ xhi,
                            __nv_bfloat16* __restrict__ xlo,
                            __nv_bfloat16* __restrict__ wqkvh,
                            __nv_bfloat16* __restrict__ wqkvl,
                            __nv_bfloat16* __restrict__ woh,
                            __nv_bfloat16* __restrict__ wol,
                            float2* __restrict__ ropeTab) {
    const int z = blockIdx.z;
    const int tx = threadIdx.x, ty = threadIdx.y;

    if (z == 4) {   // split x
        int i = (blockIdx.y * 128 + blockIdx.x) * 256 + ty * 32 + tx;
        float4 v = reinterpret_cast<const float4*>(x)[i];
        uint32_t* hp = reinterpret_cast<uint32_t*>(xhi) + 2 * i;
        uint32_t* lp = reinterpret_cast<uint32_t*>(xlo) + 2 * i;
        hp[0] = packbf(v.x, v.y); hp[1] = packbf(v.z, v.w);
        lp[0] = packbf(bfres(v.x), bfres(v.y));
        lp[1] = packbf(bfres(v.z), bfres(v.w));
        return;
    }
    if (z == 5) {   // rope table: 2048 x 32 entries
        int bid = blockIdx.y * 128 + blockIdx.x;
        if (bid >= 256) return;
        int i = bid * 256 + ty * 32 + tx;      // 0..65535
        int s = i >> 5, j = i & 31;
        float pos = (float)(s + offset_ptr[0]);
        float inv = powf(10000.0f, -(float)j / 32.0f);
        float ang = pos * inv;
        ropeTab[i] = make_float2(cosf(ang), sinf(ang));
        return;
    }

    const float* W;
    __nv_bfloat16 *hi, *lo;
    int N;
    if (z == 0)      { W = Wq; N = DMODEL; hi = wqkvh; lo = wqkvl; }
    else if (z == 1) { W = Wk; N = DKV;
                       hi = wqkvh + (size_t)DMODEL * KDIM;
                       lo = wqkvl + (size_t)DMODEL * KDIM; }
    else if (z == 2) { W = Wv; N = DKV;
                       hi = wqkvh + (size_t)(DMODEL + DKV) * KDIM;
                       lo = wqkvl + (size_t)(DMODEL + DKV) * KDIM; }
    else             { W = Wo; N = DMODEL; hi = woh; lo = wol; }

    int nb = blockIdx.x * 32;
    if (nb >= N) return;
    int kb = blockIdx.y * 32;

    __shared__ float tile[32][33];
    for (int i = ty; i < 32; i += 8)
        tile[i][tx] = W[(size_t)(kb + i) * N + nb + tx];
    __syncthreads();
    for (int i = ty; i < 32; i += 8) {
        float v = tile[tx][i];
        __nv_bfloat16 h = __float2bfloat16(v);
        __nv_bfloat16 l = __float2bfloat16(v - __bfloat162float(h));
        size_t o = (size_t)(nb + i) * KDIM + kb + tx;
        hi[o] = h;
        lo[o] = l;
    }
}

// ---------------- shared GEMM mainloop (macro) --------------------------------
// CHUNK=64 (128B rows, SW128), 2-stage cp.async, register-double-buffered frags.
// MMA issue is TERM-MAJOR: all hi*hi, then all hi*lo, then all lo*hi -> no
// back-to-back RAW chains on the same accumulator.
#define CHUNK 64
#define NCH   (KDIM / CHUNK)          // 16
#define STG_BYTES 65536               // 4 arrays x 16KB per stage
#define GEMM_SMEM_BYTES (2 * STG_BYTES + 1024)

#define GQ_LOAD_CHUNK(ch_, stg_) do {                                          \
        const int k0_ = (ch_) * CHUNK;                                         \
        uint32_t sb0_ = smem_u32(sm + (stg_) * STG_BYTES);                     \
        _Pragma("unroll")                                                      \
        for (int ii = 0; ii < 4; ii++) {                                       \
            int idx_ = t + ii * 256;                                           \
            int row_ = idx_ >> 3;                                              \
            int c_ = idx_ & 7;                                                 \
            uint32_t sw_ = SMEM_SWIZZLE_128B((uint32_t)(row_ * 128 + c_ * 16));\
            size_t ao_ = (size_t)(rowBase + row_) * KDIM + k0_ + c_ * 8;       \
            size_t bo_ = (size_t)(colBase + row_) * KDIM + k0_ + c_ * 8;       \
            cp16(sb0_ + sw_, Ahi + ao_);                                       \
            cp16(sb0_ + 16384 + sw_, Alo + ao_);                               \
            cp16(sb0_ + 32768 + sw_, Bhi + bo_);                               \
            cp16(sb0_ + 49152 + sw_, Blo + bo_);                               \
        }                                                                      \
    } while (0)

#define GQ_LOAD_FRAGS(set_, s_) do {                                           \
        _Pragma("unroll")                                                      \
        for (int mb = 0; mb < 2; mb++) {                                       \
            int row = warp_m * 32 + mb * 16 + a_row;                           \
            uint32_t sw = SMEM_SWIZZLE_128B(                                   \
                (uint32_t)(row * 128 + a_colB + (s_) * 32));                   \
            ldsm_x4(fa_hi[set_][mb][0], fa_hi[set_][mb][1],                    \
                    fa_hi[set_][mb][2], fa_hi[set_][mb][3], aHi + sw);         \
            ldsm_x4(fa_lo[set_][mb][0], fa_lo[set_][mb][1],                    \
                    fa_lo[set_][mb][2], fa_lo[set_][mb][3], aLo + sw);         \
        }                                                                      \
        _Pragma("unroll")                                                      \
        for (int p = 0; p < 4; p++) {                                          \
            int row = warp_n * 64 + p * 16 + b_rowl;                           \
            uint32_t sw = SMEM_SWIZZLE_128B(                                   \
                (uint32_t)(row * 128 + b_colB + (s_) * 32));                   \
            ldsm_x4(fb_hi[set_][2 * p][0], fb_hi[set_][2 * p][1],              \
                    fb_hi[set_][2 * p + 1][0], fb_hi[set_][2 * p + 1][1],      \
                    bHi + sw);                                                 \
            ldsm_x4(fb_lo[set_][2 * p][0], fb_lo[set_][2 * p][1],              \
                    fb_lo[set_][2 * p + 1][0], fb_lo[set_][2 * p + 1][1],      \
                    bLo + sw);                                                 \
        }                                                                      \
    } while (0)

#define GQ_MMA(set_) do {                                                      \
        _Pragma("unroll")                                                      \
        for (int nb = 0; nb < 8; nb++)                                         \
            _Pragma("unroll")                                                  \
            for (int mb = 0; mb < 2; mb++)                                     \
                mma16816(acc[mb][nb], fa_hi[set_][mb], fb_hi[set_][nb]);       \
        _Pragma("unroll")                                                      \
        for (int nb = 0; nb < 8; nb++)                                         \
            _Pragma("unroll")                                                  \
            for (int mb = 0; mb < 2; mb++)                                     \
                mma16816(acc[mb][nb], fa_hi[set_][mb], fb_lo[set_][nb]);       \
        _Pragma("unroll")                                                      \
        for (int nb = 0; nb < 8; nb++)                                         \
            _Pragma("unroll")                                                  \
            for (int mb = 0; mb < 2; mb++)                                     \
                mma16816(acc[mb][nb], fa_lo[set_][mb], fb_hi[set_][nb]);       \
    } while (0)

#define GEMM_MAINLOOP(Ahi, Alo, Bhi, Blo)                                      \
    uint32_t base = (smem_u32(dsm) + 1023u) & ~1023u;                          \
    char* sm = dsm + (base - smem_u32(dsm));                                   \
    float acc[2][8][4];                                                        \
    _Pragma("unroll")                                                          \
    for (int mb = 0; mb < 2; mb++)                                             \
        _Pragma("unroll")                                                      \
        for (int nb = 0; nb < 8; nb++)                                         \
            _Pragma("unroll")                                                  \
            for (int q = 0; q < 4; q++) acc[mb][nb][q] = 0.f;                  \
    const int a_row = lid & 15;                                                \
    const int a_colB = (lid >> 4) * 16;                                        \
    const int b_rowl = ((lid >> 4) << 3) + (lid & 7);                          \
    const int b_colB = ((lid >> 3) & 1) * 16;                                  \
    uint32_t fa_hi[2][2][4], fa_lo[2][2][4];                                   \
    uint32_t fb_hi[2][8][2], fb_lo[2][8][2];                                   \
    GQ_LOAD_CHUNK(0, 0);                                                       \
    CP_COMMIT();                                                               \
    for (int ch = 0; ch < NCH; ch++) {                                         \
        CP_WAIT(0);                                                            \
        __syncthreads();                                                       \
        uint32_t stg0 = smem_u32(sm + (ch & 1) * STG_BYTES);                   \
        uint32_t aHi = stg0;                                                   \
        uint32_t aLo = stg0 + 16384;                                           \
        uint32_t bHi = stg0 + 32768;                                           \
        uint32_t bLo = stg0 + 49152;                                           \
        GQ_LOAD_FRAGS(0, 0);                                                   \
        if (ch + 1 < NCH) {                                                    \
            GQ_LOAD_CHUNK(ch + 1, (ch + 1) & 1);                               \
            CP_COMMIT();                                                       \
        }                                                                      \
        _Pragma("unroll")                                                      \
        for (int s = 0; s < 4; s++) {                                          \
            if (s < 3) GQ_LOAD_FRAGS((s + 1) & 1, s + 1);                      \
            GQ_MMA(s & 1);                                                     \
        }                                                                      \
    }

// ---------------- GEMM with plain fp32 epilogue (O projection) ---------------
__global__ __launch_bounds__(256, 1) void gemm_mma3(
    const __nv_bfloat16* __restrict__ Ahi, const __nv_bfloat16* __restrict__ Alo,
    const __nv_bfloat16* __restrict__ Bhi, const __nv_bfloat16* __restrict__ Blo,
    float* __restrict__ C, int Ncols) {
    extern __shared__ char dsm[];
    const int t = threadIdx.x;
    const int wid = t >> 5;
    const int lid = t & 31;
    const int warp_m = wid & 3;
    const int warp_n = wid >> 2;
    const int rowBase = blockIdx.y * 128;
    const int colBase = blockIdx.x * 128;

    GEMM_MAINLOOP(Ahi, Alo, Bhi, Blo)

    const int g = lid >> 2;
    const int q = lid & 3;
#pragma unroll
    for (int mb = 0; mb < 2; mb++) {
#pragma unroll
        for (int nb = 0; nb < 8; nb++) {
            int row = rowBase + warp_m * 32 + mb * 16 + g;
            int col = colBase + warp_n * 64 + nb * 8 + q * 2;
            *reinterpret_cast<float2*>(&C[(size_t)row * Ncols + col]) =
                make_float2(acc[mb][nb][0], acc[mb][nb][1]);
            *reinterpret_cast<float2*>(&C[(size_t)(row + 8) * Ncols + col]) =
                make_float2(acc[mb][nb][2], acc[mb][nb][3]);
        }
    }
}

// ---------------- QKV GEMM with fused RoPE + hi/lo split epilogue ------------
__global__ __launch_bounds__(256, 1) void gemm_qkv(
    const __nv_bfloat16* __restrict__ Ahi, const __nv_bfloat16* __restrict__ Alo,
    const __nv_bfloat16* __restrict__ Bhi, const __nv_bfloat16* __restrict__ Blo,
    __nv_bfloat16* __restrict__ qhi, __nv_bfloat16* __restrict__ qlo,
    __nv_bfloat16* __restrict__ khi, __nv_bfloat16* __restrict__ klo,
    __nv_bfloat16* __restrict__ vhi, __nv_bfloat16* __restrict__ vlo,
    const float2* __restrict__ ropeTab) {
    extern __shared__ char dsm[];
    const int t = threadIdx.x;
    const int wid = t >> 5;
    const int lid = t & 31;
    const int warp_m = wid & 3;
    const int warp_n = wid >> 2;
    const int rowBase = blockIdx.y * 128;
    const int colBase = blockIdx.x * 128;

    GEMM_MAINLOOP(Ahi, Alo, Bhi, Blo)

    const int g2 = lid >> 2;
    const int qd2 = (lid & 3) * 2;
    const int col0 = colBase + warp_n * 64;   // 64-aligned -> one head

    if (col0 < DMODEL + DKV) {
        const bool isQ = col0 < DMODEL;
        const float sc = isQ ? 0.125f : 1.0f;   // 1/sqrt(64) folded into Q
        __nv_bfloat16* Hhi = isQ ? qhi : khi;
        __nv_bfloat16* Hlo = isQ ? qlo : klo;
        const int ncols = isQ ? DMODEL : DKV;
        const int cbase = isQ ? col0 : col0 - DMODEL;
#pragma unroll
        for (int mb = 0; mb < 2; mb++) {
            int r0 = rowBase + warp_m * 32 + mb * 16 + g2;
            int s0 = r0 & (SEQ - 1);
            int s1 = (r0 + 8) & (SEQ - 1);
#pragma unroll
            for (int nb = 0; nb < 4; nb++) {
                int j0 = nb * 8 + qd2;
                float2 c00 = ropeTab[s0 * 32 + j0];
                float2 c01 = ropeTab[s0 * 32 + j0 + 1];
                float2 c10 = ropeTab[s1 * 32 + j0];
                float2 c11 = ropeTab[s1 * 32 + j0 + 1];
                float a0 = acc[mb][nb][0], a1 = acc[mb][nb][1];
                float a2 = acc[mb][nb][2], a3 = acc[mb][nb][3];
                float b0 = acc[mb][nb + 4][0], b1 = acc[mb][nb + 4][1];
                float b2 = acc[mb][nb + 4][2], b3 = acc[mb][nb + 4][3];
                float q0 = (a0 * c00.x - b0 * c00.y) * sc;
                float q1 = (a1 * c01.x - b1 * c01.y) * sc;
                float q2 = (a2 * c10.x - b2 * c10.y) * sc;
                float q3 = (a3 * c11.x - b3 * c11.y) * sc;
                float u0 = (b0 * c00.x + a0 * c00.y) * sc;
                float u1 = (b1 * c01.x + a1 * c01.y) * sc;
                float u2 = (b2 * c10.x + a2 * c10.y) * sc;
                float u3 = (b3 * c11.x + a3 * c11.y) * sc;
                size_t o0 = (size_t)r0 * ncols + cbase + j0;
                size_t o1 = (size_t)(r0 + 8) * ncols + cbase + j0;
                *reinterpret_cast<uint32_t*>(Hhi + o0) = packbf(q0, q1);
                *reinterpret_cast<uint32_t*>(Hlo + o0) = packbf(bfres(q0), bfres(q1));
                *reinterpret_cast<uint32_t*>(Hhi + o1) = packbf(q2, q3);
                *reinterpret_cast<uint32_t*>(Hlo + o1) = packbf(bfres(q2), bfres(q3));
                *reinterpret_cast<uint32_t*>(Hhi + o0 + 32) = packbf(u0, u1);
                *reinterpret_cast<uint32_t*>(Hlo + o0 + 32) = packbf(bfres(u0), bfres(u1));
                *reinterpret_cast<uint32_t*>(Hhi + o1 + 32) = packbf(u2, u3);
                *reinterpret_cast<uint32_t*>(Hlo + o1 + 32) = packbf(bfres(u2), bfres(u3));
            }
        }
    } else {
        // V: plain hi/lo split
#pragma unroll
        for (int mb = 0; mb < 2; mb++) {
            int r0 = rowBase + warp_m * 32 + mb * 16 + g2;
#pragma unroll
            for (int nb = 0; nb < 8; nb++) {
                int col = col0 - DMODEL - DKV + nb * 8 + qd2;
                float v0 = acc[mb][nb][0], v1 = acc[mb][nb][1];
                float v2 = acc[mb][nb][2], v3 = acc[mb][nb][3];
                size_t o0 = (size_t)r0 * DKV + col;
                size_t o1 = (size_t)(r0 + 8) * DKV + col;
                *reinterpret_cast<uint32_t*>(vhi + o0) = packbf(v0, v1);
                *reinterpret_cast<uint32_t*>(vlo + o0) = packbf(bfres(v0), bfres(v1));
                *reinterpret_cast<uint32_t*>(vhi + o1) = packbf(v2, v3);
                *reinterpret_cast<uint32_t*>(vlo + o1) = packbf(bfres(v2), bfres(v3));
            }
        }
    }
}

// ---------------- tensor-core flash attention (causal, GQA) ------------------
#define KV_STG 32768
#define ATTN2_SMEM (32768 + 2 * KV_STG + 1024)

__global__ __launch_bounds__(256, 1) void attn_mma(
    const __nv_bfloat16* __restrict__ Qhi, const __nv_bfloat16* __restrict__ Qlo,
    const __nv_bfloat16* __restrict__ Khi, const __nv_bfloat16* __restrict__ Klo,
    const __nv_bfloat16* __restrict__ Vhi, const __nv_bfloat16* __restrict__ Vlo,
    __nv_bfloat16* __restrict__ Ohi, __nv_bfloat16* __restrict__ Olo) {
    extern __shared__ char dsm[];
    uint32_t base = (smem_u32(dsm) + 1023u) & ~1023u;
    char* sm = dsm + (base - smem_u32(dsm));
    char* sQhi = sm;            // 16KB
    char* sQlo = sm + 16384;    // 16KB

    const int qt = (int)gridDim.x - 1 - (int)blockIdx.x;   // heavy CTAs first
    const int h  = blockIdx.y;
    const int b  = blockIdx.z;
    const int hkv = h >> 2;
    const int t  = threadIdx.x;
    const int wid = t >> 5;
    const int lid = t & 31;
    const int g = lid >> 2;
    const int qd = lid & 3;
    const int q0 = qt * 128;

    const size_t kvbase = ((size_t)b * SEQ) * DKV + (size_t)hkv * HDIM;
    const int ntiles = 2 * qt + 2;

#define LOADKV(kt_, stg_) do {                                                  \
        const int k0_ = (kt_) * 64;                                            \
        uint32_t sb0_ = smem_u32(sm + 32768 + (stg_) * KV_STG);                 \
        _Pragma("unroll")                                                       \
        for (int ii = 0; ii < 2; ii++) {                                        \
            int idx_ = t + ii * 256;                                            \
            int row_ = idx_ >> 3;                                               \
            int ch_ = idx_ & 7;                                                 \
            uint32_t sw_ = SMEM_SWIZZLE_128B((uint32_t)(row_ * 128 + ch_ * 16));\
            size_t gl_ = kvbase + (size_t)(k0_ + row_) * DKV + ch_ * 8;         \
            cp16(sb0_ + sw_, Khi + gl_);                                        \
            cp16(sb0_ + 8192 + sw_, Klo + gl_);                                 \
            cp16(sb0_ + 16384 + sw_, Vhi + gl_);                                \
            cp16(sb0_ + 24576 + sw_, Vlo + gl_);                                \
        }                                                                       \
    } while (0)

    // group A: Q hi/lo tiles via cp.async
    {
        const __nv_bfloat16* Qh = Qhi + ((size_t)(b * SEQ + q0)) * DMODEL + h * HDIM;
        const __nv_bfloat16* Ql = Qlo + ((size_t)(b * SEQ + q0)) * DMODEL + h * HDIM;
#pragma unroll
        for (int ii = 0; ii < 4; ii++) {
            int idx = t + ii * 256;        // 0..1023
            int row = idx >> 3;
            int ch = idx & 7;
            uint32_t sw = SMEM_SWIZZLE_128B((uint32_t)(row * 128 + ch * 16));
            size_t gl = (size_t)row * DMODEL + ch * 8;
            cp16(smem_u32(sQhi) + sw, Qh + gl);
            cp16(smem_u32(sQlo) + sw, Ql + gl);
        }
        CP_COMMIT();
    }
    // group B: KV tile 0
    LOADKV(0, 0);
    CP_COMMIT();

    CP_WAIT(1);        // Q tiles complete
    __syncthreads();

    // ---- Q fragments in registers
    uint32_t qh[4][4], ql[4][4];
    {
        int arow = wid * 16 + (lid & 15);
        int acolB = (lid >> 4) * 16;
#pragma unroll
        for (int s = 0; s < 4; s++) {
            uint32_t sw = SMEM_SWIZZLE_128B((uint32_t)(arow * 128 + acolB + s * 32));
            ldsm_x4(qh[s][0], qh[s][1], qh[s][2], qh[s][3], smem_u32(sQhi) + sw);
            ldsm_x4(ql[s][0], ql[s][1], ql[s][2], ql[s][3], smem_u32(sQlo) + sw);
        }
    }

    float o[8][4];
#pragma unroll
    for (int nb = 0; nb < 8; nb++)
#pragma unroll
        for (int q = 0; q < 4; q++) o[nb][q] = 0.f;
    float m0 = -1e30f, m1 = -1e30f, l0 = 0.f, l1 = 0.f;

    for (int kt = 0; kt < ntiles; kt++) {
        const int k0 = kt * 64;
        if (kt + 1 < ntiles) {
            LOADKV(kt + 1, (kt + 1) & 1);
            CP_COMMIT();
            CP_WAIT(1);
        } else {
            CP_WAIT(0);
        }
        __syncthreads();

        uint32_t kvb = smem_u32(sm + 32768 + (kt & 1) * KV_STG);
        uint32_t sKhi_ = kvb;
        uint32_t sKlo_ = kvb + 8192;
        uint32_t sVhi_ = kvb + 16384;
        uint32_t sVlo_ = kvb + 24576;

        // ---- S = Q K^T (3-term split, term-major issue)
        float sacc[8][4];
#pragma unroll
        for (int nb = 0; nb < 8; nb++)
#pragma unroll
            for (int q = 0; q < 4; q++) sacc[nb][q] = 0.f;

        {
            int brow = ((lid >> 4) << 3) + (lid & 7);
            int bcolB = ((lid >> 3) & 1) * 16;
#pragma unroll
            for (int s = 0; s < 4; s++) {
                uint32_t kh[8][2], kl[8][2];
#pragma unroll
                for (int p = 0; p < 4; p++) {
                    uint32_t sw = SMEM_SWIZZLE_128B(
                        (uint32_t)((p * 16 + brow) * 128 + bcolB + s * 32));
                    ldsm_x4(kh[2 * p][0], kh[2 * p][1], kh[2 * p + 1][0],
                            kh[2 * p + 1][1], sKhi_ + sw);
                    ldsm_x4(kl[2 * p][0], kl[2 * p][1], kl[2 * p + 1][0],
                            kl[2 * p + 1][1], sKlo_ + sw);
                }
#pragma unroll
                for (int nb = 0; nb < 8; nb++)
                    mma16816(sacc[nb], qh[s], kh[nb]);
#pragma unroll
                for (int nb = 0; nb < 8; nb++)
                    mma16816(sacc[nb], qh[s], kl[nb]);
#pragma unroll
                for (int nb = 0; nb < 8; nb++)
                    mma16816(sacc[nb], ql[s], kh[nb]);
            }
        }

        // ---- causal mask (only diagonal tiles)
        if (kt >= 2 * qt) {
            int rowa = q0 + wid * 16 + g;
#pragma unroll
            for (int nb = 0; nb < 8; nb++) {
                int col = k0 + nb * 8 + qd * 2;
                if (col > rowa)     sacc[nb][0] = -1e30f;
                if (col + 1 > rowa) sacc[nb][1] = -1e30f;
                if (col > rowa + 8)     sacc[nb][2] = -1e30f;
                if (col + 1 > rowa + 8) sacc[nb][3] = -1e30f;
            }
        }

        // ---- online softmax
        {
            float mx0 = -1e30f, mx1 = -1e30f;
#pragma unroll
            for (int nb = 0; nb < 8; nb++) {
                mx0 = fmaxf(mx0, fmaxf(sacc[nb][0], sacc[nb][1]));
                mx1 = fmaxf(mx1, fmaxf(sacc[nb][2], sacc[nb][3]));
            }
            mx0 = fmaxf(mx0, __shfl_xor_sync(0xffffffff, mx0, 1));
            mx0 = fmaxf(mx0, __shfl_xor_sync(0xffffffff, mx0, 2));
            mx1 = fmaxf(mx1, __shfl_xor_sync(0xffffffff, mx1, 1));
            mx1 = fmaxf(mx1, __shfl_xor_sync(0xffffffff, mx1, 2));
            float mn0 = fmaxf(m0, mx0), mn1 = fmaxf(m1, mx1);
            float al0 = __expf(m0 - mn0), al1 = __expf(m1 - mn1);
            m0 = mn0; m1 = mn1;
            l0 *= al0; l1 *= al1;
            float la0 = 0.f, la1 = 0.f;
#pragma unroll
            for (int nb = 0; nb < 8; nb++) {
                sacc[nb][0] = __expf(sacc[nb][0] - mn0);
                sacc[nb][1] = __expf(sacc[nb][1] - mn0);
                sacc[nb][2] = __expf(sacc[nb][2] - mn1);
                sacc[nb][3] = __expf(sacc[nb][3] - mn1);
                la0 += sacc[nb][0] + sacc[nb][1];
                la1 += sacc[nb][2] + sacc[nb][3];
                o[nb][0] *= al0; o[nb][1] *= al0;
                o[nb][2] *= al1; o[nb][3] *= al1;
            }
            l0 += la0; l1 += la1;
        }

        // ---- pack P hi/lo as A-fragments
        uint32_t ph[4][4], pl[4][4];
#pragma unroll
        for (int j = 0; j < 4; j++) {
            float* c = sacc[2 * j];
            float* d = sacc[2 * j + 1];
            ph[j][0] = packbf(c[0], c[1]);
            ph[j][1] = packbf(c[2], c[3]);
            ph[j][2] = packbf(d[0], d[1]);
            ph[j][3] = packbf(d[2], d[3]);
            pl[j][0] = packbf(bfres(c[0]), bfres(c[1]));
            pl[j][1] = packbf(bfres(c[2]), bfres(c[3]));
            pl[j][2] = packbf(bfres(d[0]), bfres(d[1]));
            pl[j][3] = packbf(bfres(d[2]), bfres(d[3]));
        }

        // ---- O += P V (3-term split, term-major issue), V via ldmatrix.trans
        {
            int vrow = (lid & 15);
            int vcolB = (lid >> 4) * 16;
#pragma unroll
            for (int j = 0; j < 4; j++) {
                uint32_t vh[8][2], vl[8][2];
#pragma unroll
                for (int dj = 0; dj < 4; dj++) {
                    uint32_t sw = SMEM_SWIZZLE_128B(
                        (uint32_t)((j * 16 + vrow) * 128 + dj * 32 + vcolB));
                    ldsm_x4_t(vh[2 * dj][0], vh[2 * dj][1], vh[2 * dj + 1][0],
                              vh[2 * dj + 1][1], sVhi_ + sw);
                    ldsm_x4_t(vl[2 * dj][0], vl[2 * dj][1], vl[2 * dj + 1][0],
                              vl[2 * dj + 1][1], sVlo_ + sw);
                }
#pragma unroll
                for (int nb = 0; nb < 8; nb++)
                    mma16816(o[nb], ph[j], vh[nb]);
#pragma unroll
                for (int nb = 0; nb < 8; nb++)
                    mma16816(o[nb], ph[j], vl[nb]);
#pragma unroll
                for (int nb = 0; nb < 8; nb++)
                    mma16816(o[nb], pl[j], vh[nb]);
            }
        }
        __syncthreads();
    }
#undef LOADKV

    // ---- finalize: normalize, write bf16 hi/lo (fused split)
    l0 += __shfl_xor_sync(0xffffffff, l0, 1);
    l0 += __shfl_xor_sync(0xffffffff, l0, 2);
    l1 += __shfl_xor_sync(0xffffffff, l1, 1);
    l1 += __shfl_xor_sync(0xffffffff, l1, 2);
    float inv0 = 1.0f / l0, inv1 = 1.0f / l1;

    int rowa = q0 + wid * 16 + g;
    size_t oa = ((size_t)(b * SEQ + rowa)) * DMODEL + h * HDIM;
    size_t ob = ((size_t)(b * SEQ + rowa + 8)) * DMODEL + h * HDIM;
#pragma unroll
    for (int nb = 0; nb < 8; nb++) {
        int col = nb * 8 + qd * 2;
        float a0 = o[nb][0] * inv0, a1 = o[nb][1] * inv0;
        float b0 = o[nb][2] * inv1, b1 = o[nb][3] * inv1;
        *reinterpret_cast<uint32_t*>(Ohi + oa + col) = packbf(a0, a1);
        *reinterpret_cast<uint32_t*>(Olo + oa + col) = packbf(bfres(a0), bfres(a1));
        *reinterpret_cast<uint32_t*>(Ohi + ob + col) = packbf(b0, b1);
        *reinterpret_cast<uint32_t*>(Olo + ob + col) = packbf(bfres(b0), bfres(b1));
    }
}

// ---------------- launch ------------------------------------------------------
extern "C" void kernel_launch(void* const* d_in, const int* in_sizes, int n_in,
                              void* d_out, int out_size) {
    (void)in_sizes; (void)n_in; (void)out_size;
    const float* x  = (const float*)d_in[0];
    const float* Wq = (const float*)d_in[1];
    const float* Wk = (const float*)d_in[2];
    const float* Wv = (const float*)d_in[3];
    const float* Wo = (const float*)d_in[4];
    const int* poff = (const int*)d_in[5];
    float* out = (float*)d_out;

    __nv_bfloat16 *xhi, *xlo, *qhi, *qlo, *khi, *klo, *vhi, *vlo;
    __nv_bfloat16 *wqkvh, *wqkvl, *woh, *wol;
    float2* rtab;
    cudaGetSymbolAddress((void**)&xhi, g_xhi);
    cudaGetSymbolAddress((void**)&xlo, g_xlo);
    cudaGetSymbolAddress((void**)&qhi, g_Qhi);
    cudaGetSymbolAddress((void**)&qlo, g_Qlo);
    cudaGetSymbolAddress((void**)&khi, g_Khi);
    cudaGetSymbolAddress((void**)&klo, g_Klo);
    cudaGetSymbolAddress((void**)&vhi, g_Vhi);
    cudaGetSymbolAddress((void**)&vlo, g_Vlo);
    cudaGetSymbolAddress((void**)&wqkvh, g_wqkv_hi);
    cudaGetSymbolAddress((void**)&wqkvl, g_wqkv_lo);
    cudaGetSymbolAddress((void**)&woh, g_wo_hi);
    cudaGetSymbolAddress((void**)&wol, g_wo_lo);
    cudaGetSymbolAddress((void**)&rtab, g_rope);

    cudaFuncSetAttribute(gemm_mma3, cudaFuncAttributeMaxDynamicSharedMemorySize,
                         GEMM_SMEM_BYTES);
    cudaFuncSetAttribute(gemm_qkv, cudaFuncAttributeMaxDynamicSharedMemorySize,
                         GEMM_SMEM_BYTES);
    cudaFuncSetAttribute(attn_mma, cudaFuncAttributeMaxDynamicSharedMemorySize,
                         ATTN2_SMEM);

    // fused prep: x split + weight transposes + rope table (one launch)
    prep_kernel<<<dim3(128, 32, 6), dim3(32, 8)>>>(
        x, Wq, Wk, Wv, Wo, poff, xhi, xlo, wqkvh, wqkvl, woh, wol, rtab);

    // fused QKV projection + RoPE + hi/lo quantization (one launch)
    gemm_qkv<<<dim3(NQKV / 128, ROWS / 128), 256, GEMM_SMEM_BYTES>>>(
        xhi, xlo, wqkvh, wqkvl, qhi, qlo, khi, klo, vhi, vlo, rtab);

    // attention -> writes hi/lo directly into xhi/xlo
    attn_mma<<<dim3(SEQ / 128, NHEADS, BATCH), 256, ATTN2_SMEM>>>(
        qhi, qlo, khi, klo, vhi, vlo, xhi, xlo);

    // O projection
    gemm_mma3<<<dim3(DMODEL / 128, ROWS / 128), 256, GEMM_SMEM_BYTES>>>(
        xhi, xlo, woh, wol, out, DMODEL);
}

// round 11
// speedup vs baseline: 4.0569x; 1.0031x over previous
#include <cuda_runtime.h>
#include <cuda_bf16.h>
#include <math.h>
#include <cstdint>

// Problem constants
#define BATCH 2
#define SEQ   2048
#define DMODEL 1024
#define NHEADS 16
#define NKV    4
#define HDIM   64
#define ROWS   (BATCH * SEQ)          // 4096
#define DKV    (NKV * HDIM)           // 256
#define KDIM   1024
#define NQKV   (DMODEL + 2 * DKV)     // 1536

// ---------------- scratch (static __device__, no allocation) ----------------
__device__ __nv_bfloat16 g_xhi[ROWS * DMODEL];     // x split; reused for attn out
__device__ __nv_bfloat16 g_xlo[ROWS * DMODEL];
__device__ __nv_bfloat16 g_Qhi[ROWS * DMODEL];
__device__ __nv_bfloat16 g_Qlo[ROWS * DMODEL];
__device__ __nv_bfloat16 g_Khi[ROWS * DKV];
__device__ __nv_bfloat16 g_Klo[ROWS * DKV];
__device__ __nv_bfloat16 g_Vhi[ROWS * DKV];
__device__ __nv_bfloat16 g_Vlo[ROWS * DKV];
__device__ __nv_bfloat16 g_wqkv_hi[NQKV * KDIM];   // transposed [N,K], Q|K|V rows
__device__ __nv_bfloat16 g_wqkv_lo[NQKV * KDIM];
__device__ __nv_bfloat16 g_wo_hi[DMODEL * KDIM];
__device__ __nv_bfloat16 g_wo_lo[DMODEL * KDIM];
__device__ float2 g_rope[SEQ * 32];                // (cos, sin) per (s, j)

__device__ __forceinline__ uint32_t smem_u32(const void* p) {
    uint32_t a;
    asm("{ .reg .u64 t; cvta.to.shared.u64 t, %1; cvt.u32.u64 %0, t; }"
        : "=r"(a) : "l"(p));
    return a;
}
#define SMEM_SWIZZLE_128B(off) ((off) ^ (((off) >> 3) & 0x70))

__device__ __forceinline__ void ldsm_x4(uint32_t& r0, uint32_t& r1,
                                        uint32_t& r2, uint32_t& r3,
                                        uint32_t addr) {
    asm volatile("ldmatrix.sync.aligned.m8n8.x4.shared.b16 {%0,%1,%2,%3}, [%4];"
                 : "=r"(r0), "=r"(r1), "=r"(r2), "=r"(r3) : "r"(addr));
}
__device__ __forceinline__ void ldsm_x4_t(uint32_t& r0, uint32_t& r1,
                                          uint32_t& r2, uint32_t& r3,
                                          uint32_t addr) {
    asm volatile("ldmatrix.sync.aligned.m8n8.x4.trans.shared.b16 {%0,%1,%2,%3}, [%4];"
                 : "=r"(r0), "=r"(r1), "=r"(r2), "=r"(r3) : "r"(addr));
}
__device__ __forceinline__ void mma16816(float* c, const uint32_t* a,
                                         const uint32_t* b) {
    asm volatile(
        "mma.sync.aligned.m16n8k16.row.col.f32.bf16.bf16.f32 "
        "{%0,%1,%2,%3}, {%4,%5,%6,%7}, {%8,%9}, {%0,%1,%2,%3};"
        : "+f"(c[0]), "+f"(c[1]), "+f"(c[2]), "+f"(c[3])
        : "r"(a[0]), "r"(a[1]), "r"(a[2]), "r"(a[3]), "r"(b[0]), "r"(b[1]));
}
__device__ __forceinline__ uint32_t packbf(float lo, float hi) {
    __nv_bfloat162 t = __floats2bfloat162_rn(lo, hi);   // .x -> low 16 bits
    return *reinterpret_cast<uint32_t*>(&t);
}
__device__ __forceinline__ float bfres(float c) {
    return c - __bfloat162float(__float2bfloat16(c));
}
__device__ __forceinline__ void cp16(uint32_t s, const void* g) {
    asm volatile("cp.async.cg.shared.global [%0], [%1], 16;" :: "r"(s), "l"(g));
}
#define CP_COMMIT() asm volatile("cp.async.commit_group;")
#define CP_WAIT(n)  asm volatile("cp.async.wait_group %0;" :: "n"(n))

// ---------------- fused prep: x split + 4 weight transposes + rope table -----
__global__ void prep_kernel(const float* __restrict__ x,
                            const float* __restrict__ Wq,
                            const float* __restrict__ Wk,
                            const float* __restrict__ Wv,
                            const float* __restrict__ Wo,
                            const int* __restrict__ offset_ptr,
                            __nv_bfloat16* __restrict__ xhi,
                            __nv_bfloat16* __restrict__ xlo,
                            __nv_bfloat16* __restrict__ wqkvh,
                            __nv_bfloat16* __restrict__ wqkvl,
                            __nv_bfloat16* __restrict__ woh,
                            __nv_bfloat16* __restrict__ wol,
                            float2* __restrict__ ropeTab) {
    const int z = blockIdx.z;
    const int tx = threadIdx.x, ty = threadIdx.y;

    if (z == 4) {   // split x
        int i = (blockIdx.y * 128 + blockIdx.x) * 256 + ty * 32 + tx;
        float4 v = reinterpret_cast<const float4*>(x)[i];
        uint32_t* hp = reinterpret_cast<uint32_t*>(xhi) + 2 * i;
        uint32_t* lp = reinterpret_cast<uint32_t*>(xlo) + 2 * i;
        hp[0] = packbf(v.x, v.y); hp[1] = packbf(v.z, v.w);
        lp[0] = packbf(bfres(v.x), bfres(v.y));
        lp[1] = packbf(bfres(v.z), bfres(v.w));
        return;
    }
    if (z == 5) {   // rope table: 2048 x 32 entries
        int bid = blockIdx.y * 128 + blockIdx.x;
        if (bid >= 256) return;
        int i = bid * 256 + ty * 32 + tx;      // 0..65535
        int s = i >> 5, j = i & 31;
        float pos = (float)(s + offset_ptr[0]);
        float inv = powf(10000.0f, -(float)j / 32.0f);
        float ang = pos * inv;
        ropeTab[i] = make_float2(cosf(ang), sinf(ang));
        return;
    }

    const float* W;
    __nv_bfloat16 *hi, *lo;
    int N;
    if (z == 0)      { W = Wq; N = DMODEL; hi = wqkvh; lo = wqkvl; }
    else if (z == 1) { W = Wk; N = DKV;
                       hi = wqkvh + (size_t)DMODEL * KDIM;
                       lo = wqkvl + (size_t)DMODEL * KDIM; }
    else if (z == 2) { W = Wv; N = DKV;
                       hi = wqkvh + (size_t)(DMODEL + DKV) * KDIM;
                       lo = wqkvl + (size_t)(DMODEL + DKV) * KDIM; }
    else             { W = Wo; N = DMODEL; hi = woh; lo = wol; }

    int nb = blockIdx.x * 32;
    if (nb >= N) return;
    int kb = blockIdx.y * 32;

    __shared__ float tile[32][33];
    for (int i = ty; i < 32; i += 8)
        tile[i][tx] = W[(size_t)(kb + i) * N + nb + tx];
    __syncthreads();
    for (int i = ty; i < 32; i += 8) {
        float v = tile[tx][i];
        __nv_bfloat16 h = __float2bfloat16(v);
        __nv_bfloat16 l = __float2bfloat16(v - __bfloat162float(h));
        size_t o = (size_t)(nb + i) * KDIM + kb + tx;
        hi[o] = h;
        lo[o] = l;
    }
}

// ---------------- shared GEMM mainloop (macro) --------------------------------
// 512 threads, 16 warps in 4m x 4n grid, warp tile 32x32.
// CHUNK=64 (128B rows, SW128), 2-stage cp.async, single-buffered fragments,
// term-major MMA issue. 4 warps/SMSP for latency hiding.
#define CHUNK 64
#define NCH   (KDIM / CHUNK)          // 16
#define STG_BYTES 65536               // 4 arrays x 16KB per stage
#define GEMM_SMEM_BYTES (2 * STG_BYTES + 1024)

#define GQ_LOAD_CHUNK(ch_, stg_) do {                                          \
        const int k0_ = (ch_) * CHUNK;                                         \
        uint32_t sb0_ = smem_u32(sm + (stg_) * STG_BYTES);                     \
        _Pragma("unroll")                                                      \
        for (int ii = 0; ii < 2; ii++) {                                       \
            int idx_ = t + ii * 512;                                           \
            int row_ = idx_ >> 3;                                              \
            int c_ = idx_ & 7;                                                 \
            uint32_t sw_ = SMEM_SWIZZLE_128B((uint32_t)(row_ * 128 + c_ * 16));\
            size_t ao_ = (size_t)(rowBase + row_) * KDIM + k0_ + c_ * 8;       \
            size_t bo_ = (size_t)(colBase + row_) * KDIM + k0_ + c_ * 8;       \
            cp16(sb0_ + sw_, Ahi + ao_);                                       \
            cp16(sb0_ + 16384 + sw_, Alo + ao_);                               \
            cp16(sb0_ + 32768 + sw_, Bhi + bo_);                               \
            cp16(sb0_ + 49152 + sw_, Blo + bo_);                               \
        }                                                                      \
    } while (0)

#define GQ_LOAD_FRAGS(s_) do {                                                 \
        _Pragma("unroll")                                                      \
        for (int mb = 0; mb < 2; mb++) {                                       \
            int row = warp_m * 32 + mb * 16 + a_row;                           \
            uint32_t sw = SMEM_SWIZZLE_128B(                                   \
                (uint32_t)(row * 128 + a_colB + (s_) * 32));                   \
            ldsm_x4(fa_hi[mb][0], fa_hi[mb][1], fa_hi[mb][2], fa_hi[mb][3],    \
                    aHi + sw);                                                 \
            ldsm_x4(fa_lo[mb][0], fa_lo[mb][1], fa_lo[mb][2], fa_lo[mb][3],    \
                    aLo + sw);                                                 \
        }                                                                      \
        _Pragma("unroll")                                                      \
        for (int p = 0; p < 2; p++) {                                          \
            int row = warp_n * 32 + p * 16 + b_rowl;                           \
            uint32_t sw = SMEM_SWIZZLE_128B(                                   \
                (uint32_t)(row * 128 + b_colB + (s_) * 32));                   \
            ldsm_x4(fb_hi[2 * p][0], fb_hi[2 * p][1],                          \
                    fb_hi[2 * p + 1][0], fb_hi[2 * p + 1][1], bHi + sw);       \
            ldsm_x4(fb_lo[2 * p][0], fb_lo[2 * p][1],                          \
                    fb_lo[2 * p + 1][0], fb_lo[2 * p + 1][1], bLo + sw);       \
        }                                                                      \
    } while (0)

#define GQ_MMA() do {                                                          \
        _Pragma("unroll")                                                      \
        for (int nb = 0; nb < 4; nb++)                                         \
            _Pragma("unroll")                                                  \
            for (int mb = 0; mb < 2; mb++)                                     \
                mma16816(acc[mb][nb], fa_hi[mb], fb_hi[nb]);                   \
        _Pragma("unroll")                                                      \
        for (int nb = 0; nb < 4; nb++)                                         \
            _Pragma("unroll")                                                  \
            for (int mb = 0; mb < 2; mb++)                                     \
                mma16816(acc[mb][nb], fa_hi[mb], fb_lo[nb]);                   \
        _Pragma("unroll")                                                      \
        for (int nb = 0; nb < 4; nb++)                                         \
            _Pragma("unroll")                                                  \
            for (int mb = 0; mb < 2; mb++)                                     \
                mma16816(acc[mb][nb], fa_lo[mb], fb_hi[nb]);                   \
    } while (0)

#define GEMM_MAINLOOP(Ahi, Alo, Bhi, Blo)                                      \
    uint32_t base = (smem_u32(dsm) + 1023u) & ~1023u;                          \
    char* sm = dsm + (base - smem_u32(dsm));                                   \
    float acc[2][4][4];                                                        \
    _Pragma("unroll")                                                          \
    for (int mb = 0; mb < 2; mb++)                                             \
        _Pragma("unroll")                                                      \
        for (int nb = 0; nb < 4; nb++)                                         \
            _Pragma("unroll")                                                  \
            for (int q = 0; q < 4; q++) acc[mb][nb][q] = 0.f;                  \
    const int a_row = lid & 15;                                                \
    const int a_colB = (lid >> 4) * 16;                                        \
    const int b_rowl = ((lid >> 4) << 3) + (lid & 7);                          \
    const int b_colB = ((lid >> 3) & 1) * 16;                                  \
    uint32_t fa_hi[2][4], fa_lo[2][4];                                         \
    uint32_t fb_hi[4][2], fb_lo[4][2];                                         \
    GQ_LOAD_CHUNK(0, 0);                                                       \
    CP_COMMIT();                                                               \
    for (int ch = 0; ch < NCH; ch++) {                                         \
        CP_WAIT(0);                                                            \
        __syncthreads();                                                       \
        uint32_t stg0 = smem_u32(sm + (ch & 1) * STG_BYTES);                   \
        uint32_t aHi = stg0;                                                   \
        uint32_t aLo = stg0 + 16384;                                           \
        uint32_t bHi = stg0 + 32768;                                           \
        uint32_t bLo = stg0 + 49152;                                           \
        _Pragma("unroll")                                                      \
        for (int s = 0; s < 4; s++) {                                          \
            GQ_LOAD_FRAGS(s);                                                  \
            if (s == 0 && ch + 1 < NCH) {                                      \
                GQ_LOAD_CHUNK(ch + 1, (ch + 1) & 1);                           \
                CP_COMMIT();                                                   \
            }                                                                  \
            GQ_MMA();                                                          \
        }                                                                      \
    }

// ---------------- GEMM with plain fp32 epilogue (O projection) ---------------
__global__ __launch_bounds__(512, 1) void gemm_mma3(
    const __nv_bfloat16* __restrict__ Ahi, const __nv_bfloat16* __restrict__ Alo,
    const __nv_bfloat16* __restrict__ Bhi, const __nv_bfloat16* __restrict__ Blo,
    float* __restrict__ C, int Ncols) {
    extern __shared__ char dsm[];
    const int t = threadIdx.x;
    const int wid = t >> 5;
    const int lid = t & 31;
    const int warp_m = wid & 3;
    const int warp_n = wid >> 2;
    const int rowBase = blockIdx.y * 128;
    const int colBase = blockIdx.x * 128;

    GEMM_MAINLOOP(Ahi, Alo, Bhi, Blo)

    const int g = lid >> 2;
    const int q = lid & 3;
#pragma unroll
    for (int mb = 0; mb < 2; mb++) {
#pragma unroll
        for (int nb = 0; nb < 4; nb++) {
            int row = rowBase + warp_m * 32 + mb * 16 + g;
            int col = colBase + warp_n * 32 + nb * 8 + q * 2;
            *reinterpret_cast<float2*>(&C[(size_t)row * Ncols + col]) =
                make_float2(acc[mb][nb][0], acc[mb][nb][1]);
            *reinterpret_cast<float2*>(&C[(size_t)(row + 8) * Ncols + col]) =
                make_float2(acc[mb][nb][2], acc[mb][nb][3]);
        }
    }
}

// ---------------- QKV GEMM with fused RoPE + hi/lo split epilogue ------------
// Q/K epilogue: acc -> smem f32 tile (XOR-swizzled) -> cooperative RoPE+split.
// V epilogue: direct from registers.
__global__ __launch_bounds__(512, 1) void gemm_qkv(
    const __nv_bfloat16* __restrict__ Ahi, const __nv_bfloat16* __restrict__ Alo,
    const __nv_bfloat16* __restrict__ Bhi, const __nv_bfloat16* __restrict__ Blo,
    __nv_bfloat16* __restrict__ qhi, __nv_bfloat16* __restrict__ qlo,
    __nv_bfloat16* __restrict__ khi, __nv_bfloat16* __restrict__ klo,
    __nv_bfloat16* __restrict__ vhi, __nv_bfloat16* __restrict__ vlo,
    const float2* __restrict__ ropeTab) {
    extern __shared__ char dsm[];
    const int t = threadIdx.x;
    const int wid = t >> 5;
    const int lid = t & 31;
    const int warp_m = wid & 3;
    const int warp_n = wid >> 2;
    const int rowBase = blockIdx.y * 128;
    const int colBase = blockIdx.x * 128;

    GEMM_MAINLOOP(Ahi, Alo, Bhi, Blo)

    const int g2 = lid >> 2;
    const int qd2 = (lid & 3) * 2;

    if (colBase >= DMODEL + DKV) {
        // V: plain hi/lo split, direct from registers
        const int cb = colBase - DMODEL - DKV;
#pragma unroll
        for (int mb = 0; mb < 2; mb++) {
            int r0 = rowBase + warp_m * 32 + mb * 16 + g2;
#pragma unroll
            for (int nb = 0; nb < 4; nb++) {
                int col = cb + warp_n * 32 + nb * 8 + qd2;
                float v0 = acc[mb][nb][0], v1 = acc[mb][nb][1];
                float v2 = acc[mb][nb][2], v3 = acc[mb][nb][3];
                size_t o0 = (size_t)r0 * DKV + col;
                size_t o1 = (size_t)(r0 + 8) * DKV + col;
                *reinterpret_cast<uint32_t*>(vhi + o0) = packbf(v0, v1);
                *reinterpret_cast<uint32_t*>(vlo + o0) = packbf(bfres(v0), bfres(v1));
                *reinterpret_cast<uint32_t*>(vhi + o1) = packbf(v2, v3);
                *reinterpret_cast<uint32_t*>(vlo + o1) = packbf(bfres(v2), bfres(v3));
            }
        }
        return;
    }

    // Q/K: bounce accumulators through smem (stage-0, 64KB) for cross-warp RoPE
    float* stile = reinterpret_cast<float*>(sm);   // [128][128], XOR swizzle
    __syncthreads();   // all warps done with final-chunk fragment reads
#pragma unroll
    for (int mb = 0; mb < 2; mb++) {
#pragma unroll
        for (int nb = 0; nb < 4; nb++) {
            int rl0 = warp_m * 32 + mb * 16 + g2;
            int cw = warp_n * 32 + nb * 8 + qd2;
            uint32_t w0 = rl0 * 128 + (cw ^ ((rl0 & 7) << 3));
            uint32_t w1 = (rl0 + 8) * 128 + (cw ^ (((rl0 + 8) & 7) << 3));
            *reinterpret_cast<float2*>(stile + w0) =
                make_float2(acc[mb][nb][0], acc[mb][nb][1]);
            *reinterpret_cast<float2*>(stile + w1) =
                make_float2(acc[mb][nb][2], acc[mb][nb][3]);
        }
    }
    __syncthreads();

    const bool isQ = colBase < DMODEL;
    const float sc = isQ ? 0.125f : 1.0f;   // 1/sqrt(64) folded into Q
    __nv_bfloat16* Hhi = isQ ? qhi : khi;
    __nv_bfloat16* Hlo = isQ ? qlo : klo;
    const int ncols = isQ ? DMODEL : DKV;
    const int cbase = isQ ? colBase : colBase - DMODEL;

    // 128 rows x 2 heads x 16 j-pairs = 4096 items, 512 threads -> 8 iters
#pragma unroll
    for (int it = 0; it < 8; it++) {
        int i = t + it * 512;
        int j2 = i & 15;
        int head = (i >> 4) & 1;
        int rl = i >> 5;                 // local row 0..127
        int j = 2 * j2;
        int c1 = head * 64 + j;
        uint32_t xr = (uint32_t)((rl & 7) << 3);
        float2 ab0 = *reinterpret_cast<float2*>(stile + rl * 128 + (c1 ^ xr));
        float2 ab1 = *reinterpret_cast<float2*>(stile + rl * 128 + ((c1 + 32) ^ xr));
        int grow = rowBase + rl;
        int srow = grow & (SEQ - 1);
        float2 cs0 = ropeTab[srow * 32 + j];
        float2 cs1 = ropeTab[srow * 32 + j + 1];
        float a0 = ab0.x, a1 = ab0.y, b0 = ab1.x, b1 = ab1.y;
        float q0 = (a0 * cs0.x - b0 * cs0.y) * sc;
        float q1 = (a1 * cs1.x - b1 * cs1.y) * sc;
        float u0 = (b0 * cs0.x + a0 * cs0.y) * sc;
        float u1 = (b1 * cs1.x + a1 * cs1.y) * sc;
        size_t o = (size_t)grow * ncols + cbase + c1;
        *reinterpret_cast<uint32_t*>(Hhi + o) = packbf(q0, q1);
        *reinterpret_cast<uint32_t*>(Hlo + o) = packbf(bfres(q0), bfres(q1));
        *reinterpret_cast<uint32_t*>(Hhi + o + 32) = packbf(u0, u1);
        *reinterpret_cast<uint32_t*>(Hlo + o + 32) = packbf(bfres(u0), bfres(u1));
    }
}

// ---------------- tensor-core flash attention (causal, GQA) ------------------
#define KV_STG 32768
#define ATTN2_SMEM (32768 + 2 * KV_STG + 1024)

__global__ __launch_bounds__(256, 1) void attn_mma(
    const __nv_bfloat16* __restrict__ Qhi, const __nv_bfloat16* __restrict__ Qlo,
    const __nv_bfloat16* __restrict__ Khi, const __nv_bfloat16* __restrict__ Klo,
    const __nv_bfloat16* __restrict__ Vhi, const __nv_bfloat16* __restrict__ Vlo,
    __nv_bfloat16* __restrict__ Ohi, __nv_bfloat16* __restrict__ Olo) {
    extern __shared__ char dsm[];
    uint32_t base = (smem_u32(dsm) + 1023u) & ~1023u;
    char* sm = dsm + (base - smem_u32(dsm));
    char* sQhi = sm;            // 16KB
    char* sQlo = sm + 16384;    // 16KB

    const int qt = (int)gridDim.x - 1 - (int)blockIdx.x;   // heavy CTAs first
    const int h  = blockIdx.y;
    const int b  = blockIdx.z;
    const int hkv = h >> 2;
    const int t  = threadIdx.x;
    const int wid = t >> 5;
    const int lid = t & 31;
    const int g = lid >> 2;
    const int qd = lid & 3;
    const int q0 = qt * 128;

    const size_t kvbase = ((size_t)b * SEQ) * DKV + (size_t)hkv * HDIM;
    const int ntiles = 2 * qt + 2;

#define LOADKV(kt_, stg_) do {                                                  \
        const int k0_ = (kt_) * 64;                                            \
        uint32_t sb0_ = smem_u32(sm + 32768 + (stg_) * KV_STG);                 \
        _Pragma("unroll")                                                       \
        for (int ii = 0; ii < 2; ii++) {                                        \
            int idx_ = t + ii * 256;                                            \
            int row_ = idx_ >> 3;                                               \
            int ch_ = idx_ & 7;                                                 \
            uint32_t sw_ = SMEM_SWIZZLE_128B((uint32_t)(row_ * 128 + ch_ * 16));\
            size_t gl_ = kvbase + (size_t)(k0_ + row_) * DKV + ch_ * 8;         \
            cp16(sb0_ + sw_, Khi + gl_);                                        \
            cp16(sb0_ + 8192 + sw_, Klo + gl_);                                 \
            cp16(sb0_ + 16384 + sw_, Vhi + gl_);                                \
            cp16(sb0_ + 24576 + sw_, Vlo + gl_);                                \
        }                                                                       \
    } while (0)

    // group A: Q hi/lo tiles via cp.async
    {
        const __nv_bfloat16* Qh = Qhi + ((size_t)(b * SEQ + q0)) * DMODEL + h * HDIM;
        const __nv_bfloat16* Ql = Qlo + ((size_t)(b * SEQ + q0)) * DMODEL + h * HDIM;
#pragma unroll
        for (int ii = 0; ii < 4; ii++) {
            int idx = t + ii * 256;        // 0..1023
            int row = idx >> 3;
            int ch = idx & 7;
            uint32_t sw = SMEM_SWIZZLE_128B((uint32_t)(row * 128 + ch * 16));
            size_t gl = (size_t)row * DMODEL + ch * 8;
            cp16(smem_u32(sQhi) + sw, Qh + gl);
            cp16(smem_u32(sQlo) + sw, Ql + gl);
        }
        CP_COMMIT();
    }
    // group B: KV tile 0
    LOADKV(0, 0);
    CP_COMMIT();

    CP_WAIT(1);        // Q tiles complete
    __syncthreads();

    // ---- Q fragments in registers
    uint32_t qh[4][4], ql[4][4];
    {
        int arow = wid * 16 + (lid & 15);
        int acolB = (lid >> 4) * 16;
#pragma unroll
        for (int s = 0; s < 4; s++) {
            uint32_t sw = SMEM_SWIZZLE_128B((uint32_t)(arow * 128 + acolB + s * 32));
            ldsm_x4(qh[s][0], qh[s][1], qh[s][2], qh[s][3], smem_u32(sQhi) + sw);
            ldsm_x4(ql[s][0], ql[s][1], ql[s][2], ql[s][3], smem_u32(sQlo) + sw);
        }
    }

    float o[8][4];
#pragma unroll
    for (int nb = 0; nb < 8; nb++)
#pragma unroll
        for (int q = 0; q < 4; q++) o[nb][q] = 0.f;
    float m0 = -1e30f, m1 = -1e30f, l0 = 0.f, l1 = 0.f;

    for (int kt = 0; kt < ntiles; kt++) {
        const int k0 = kt * 64;
        if (kt + 1 < ntiles) {
            LOADKV(kt + 1, (kt + 1) & 1);
            CP_COMMIT();
            CP_WAIT(1);
        } else {
            CP_WAIT(0);
        }
        __syncthreads();

        uint32_t kvb = smem_u32(sm + 32768 + (kt & 1) * KV_STG);
        uint32_t sKhi_ = kvb;
        uint32_t sKlo_ = kvb + 8192;
        uint32_t sVhi_ = kvb + 16384;
        uint32_t sVlo_ = kvb + 24576;

        // ---- S = Q K^T (3-term split, term-major issue)
        float sacc[8][4];
#pragma unroll
        for (int nb = 0; nb < 8; nb++)
#pragma unroll
            for (int q = 0; q < 4; q++) sacc[nb][q] = 0.f;

        {
            int brow = ((lid >> 4) << 3) + (lid & 7);
            int bcolB = ((lid >> 3) & 1) * 16;
#pragma unroll
            for (int s = 0; s < 4; s++) {
                uint32_t kh[8][2], kl[8][2];
#pragma unroll
                for (int p = 0; p < 4; p++) {
                    uint32_t sw = SMEM_SWIZZLE_128B(
                        (uint32_t)((p * 16 + brow) * 128 + bcolB + s * 32));
                    ldsm_x4(kh[2 * p][0], kh[2 * p][1], kh[2 * p + 1][0],
                            kh[2 * p + 1][1], sKhi_ + sw);
                    ldsm_x4(kl[2 * p][0], kl[2 * p][1], kl[2 * p + 1][0],
                            kl[2 * p + 1][1], sKlo_ + sw);
                }
#pragma unroll
                for (int nb = 0; nb < 8; nb++)
                    mma16816(sacc[nb], qh[s], kh[nb]);
#pragma unroll
                for (int nb = 0; nb < 8; nb++)
                    mma16816(sacc[nb], qh[s], kl[nb]);
#pragma unroll
                for (int nb = 0; nb < 8; nb++)
                    mma16816(sacc[nb], ql[s], kh[nb]);
            }
        }

        // ---- causal mask (only diagonal tiles)
        if (kt >= 2 * qt) {
            int rowa = q0 + wid * 16 + g;
#pragma unroll
            for (int nb = 0; nb < 8; nb++) {
                int col = k0 + nb * 8 + qd * 2;
                if (col > rowa)     sacc[nb][0] = -1e30f;
                if (col + 1 > rowa) sacc[nb][1] = -1e30f;
                if (col > rowa + 8)     sacc[nb][2] = -1e30f;
                if (col + 1 > rowa + 8) sacc[nb][3] = -1e30f;
            }
        }

        // ---- online softmax
        {
            float mx0 = -1e30f, mx1 = -1e30f;
#pragma unroll
            for (int nb = 0; nb < 8; nb++) {
                mx0 = fmaxf(mx0, fmaxf(sacc[nb][0], sacc[nb][1]));
                mx1 = fmaxf(mx1, fmaxf(sacc[nb][2], sacc[nb][3]));
            }
            mx0 = fmaxf(mx0, __shfl_xor_sync(0xffffffff, mx0, 1));
            mx0 = fmaxf(mx0, __shfl_xor_sync(0xffffffff, mx0, 2));
            mx1 = fmaxf(mx1, __shfl_xor_sync(0xffffffff, mx1, 1));
            mx1 = fmaxf(mx1, __shfl_xor_sync(0xffffffff, mx1, 2));
            float mn0 = fmaxf(m0, mx0), mn1 = fmaxf(m1, mx1);
            float al0 = __expf(m0 - mn0), al1 = __expf(m1 - mn1);
            m0 = mn0; m1 = mn1;
            l0 *= al0; l1 *= al1;
            float la0 = 0.f, la1 = 0.f;
#pragma unroll
            for (int nb = 0; nb < 8; nb++) {
                sacc[nb][0] = __expf(sacc[nb][0] - mn0);
                sacc[nb][1] = __expf(sacc[nb][1] - mn0);
                sacc[nb][2] = __expf(sacc[nb][2] - mn1);
                sacc[nb][3] = __expf(sacc[nb][3] - mn1);
                la0 += sacc[nb][0] + sacc[nb][1];
                la1 += sacc[nb][2] + sacc[nb][3];
                o[nb][0] *= al0; o[nb][1] *= al0;
                o[nb][2] *= al1; o[nb][3] *= al1;
            }
            l0 += la0; l1 += la1;
        }

        // ---- pack P hi/lo as A-fragments
        uint32_t ph[4][4], pl[4][4];
#pragma unroll
        for (int j = 0; j < 4; j++) {
            float* c = sacc[2 * j];
            float* d = sacc[2 * j + 1];
            ph[j][0] = packbf(c[0], c[1]);
            ph[j][1] = packbf(c[2], c[3]);
            ph[j][2] = packbf(d[0], d[1]);
            ph[j][3] = packbf(d[2], d[3]);
            pl[j][0] = packbf(bfres(c[0]), bfres(c[1]));
            pl[j][1] = packbf(bfres(c[2]), bfres(c[3]));
            pl[j][2] = packbf(bfres(d[0]), bfres(d[1]));
            pl[j][3] = packbf(bfres(d[2]), bfres(d[3]));
        }

        // ---- O += P V (3-term split, term-major issue), V via ldmatrix.trans
        {
            int vrow = (lid & 15);
            int vcolB = (lid >> 4) * 16;
#pragma unroll
            for (int j = 0; j < 4; j++) {
                uint32_t vh[8][2], vl[8][2];
#pragma unroll
                for (int dj = 0; dj < 4; dj++) {
                    uint32_t sw = SMEM_SWIZZLE_128B(
                        (uint32_t)((j * 16 + vrow) * 128 + dj * 32 + vcolB));
                    ldsm_x4_t(vh[2 * dj][0], vh[2 * dj][1], vh[2 * dj + 1][0],
                              vh[2 * dj + 1][1], sVhi_ + sw);
                    ldsm_x4_t(vl[2 * dj][0], vl[2 * dj][1], vl[2 * dj + 1][0],
                              vl[2 * dj + 1][1], sVlo_ + sw);
                }
#pragma unroll
                for (int nb = 0; nb < 8; nb++)
                    mma16816(o[nb], ph[j], vh[nb]);
#pragma unroll
                for (int nb = 0; nb < 8; nb++)
                    mma16816(o[nb], ph[j], vl[nb]);
#pragma unroll
                for (int nb = 0; nb < 8; nb++)
                    mma16816(o[nb], pl[j], vh[nb]);
            }
        }
        __syncthreads();
    }
#undef LOADKV

    // ---- finalize: normalize, write bf16 hi/lo (fused split)
    l0 += __shfl_xor_sync(0xffffffff, l0, 1);
    l0 += __shfl_xor_sync(0xffffffff, l0, 2);
    l1 += __shfl_xor_sync(0xffffffff, l1, 1);
    l1 += __shfl_xor_sync(0xffffffff, l1, 2);
    float inv0 = 1.0f / l0, inv1 = 1.0f / l1;

    int rowa = q0 + wid * 16 + g;
    size_t oa = ((size_t)(b * SEQ + rowa)) * DMODEL + h * HDIM;
    size_t ob = ((size_t)(b * SEQ + rowa + 8)) * DMODEL + h * HDIM;
#pragma unroll
    for (int nb = 0; nb < 8; nb++) {
        int col = nb * 8 + qd * 2;
        float a0 = o[nb][0] * inv0, a1 = o[nb][1] * inv0;
        float b0 = o[nb][2] * inv1, b1 = o[nb][3] * inv1;
        *reinterpret_cast<uint32_t*>(Ohi + oa + col) = packbf(a0, a1);
        *reinterpret_cast<uint32_t*>(Olo + oa + col) = packbf(bfres(a0), bfres(a1));
        *reinterpret_cast<uint32_t*>(Ohi + ob + col) = packbf(b0, b1);
        *reinterpret_cast<uint32_t*>(Olo + ob + col) = packbf(bfres(b0), bfres(b1));
    }
}

// ---------------- launch ------------------------------------------------------
extern "C" void kernel_launch(void* const* d_in, const int* in_sizes, int n_in,
                              void* d_out, int out_size) {
    (void)in_sizes; (void)n_in; (void)out_size;
    const float* x  = (const float*)d_in[0];
    const float* Wq = (const float*)d_in[1];
    const float* Wk = (const float*)d_in[2];
    const float* Wv = (const float*)d_in[3];
    const float* Wo = (const float*)d_in[4];
    const int* poff = (const int*)d_in[5];
    float* out = (float*)d_out;

    __nv_bfloat16 *xhi, *xlo, *qhi, *qlo, *khi, *klo, *vhi, *vlo;
    __nv_bfloat16 *wqkvh, *wqkvl, *woh, *wol;
    float2* rtab;
    cudaGetSymbolAddress((void**)&xhi, g_xhi);
    cudaGetSymbolAddress((void**)&xlo, g_xlo);
    cudaGetSymbolAddress((void**)&qhi, g_Qhi);
    cudaGetSymbolAddress((void**)&qlo, g_Qlo);
    cudaGetSymbolAddress((void**)&khi, g_Khi);
    cudaGetSymbolAddress((void**)&klo, g_Klo);
    cudaGetSymbolAddress((void**)&vhi, g_Vhi);
    cudaGetSymbolAddress((void**)&vlo, g_Vlo);
    cudaGetSymbolAddress((void**)&wqkvh, g_wqkv_hi);
    cudaGetSymbolAddress((void**)&wqkvl, g_wqkv_lo);
    cudaGetSymbolAddress((void**)&woh, g_wo_hi);
    cudaGetSymbolAddress((void**)&wol, g_wo_lo);
    cudaGetSymbolAddress((void**)&rtab, g_rope);

    cudaFuncSetAttribute(gemm_mma3, cudaFuncAttributeMaxDynamicSharedMemorySize,
                         GEMM_SMEM_BYTES);
    cudaFuncSetAttribute(gemm_qkv, cudaFuncAttributeMaxDynamicSharedMemorySize,
                         GEMM_SMEM_BYTES);
    cudaFuncSetAttribute(attn_mma, cudaFuncAttributeMaxDynamicSharedMemorySize,
                         ATTN2_SMEM);

    // fused prep: x split + weight transposes + rope table (one launch)
    prep_kernel<<<dim3(128, 32, 6), dim3(32, 8)>>>(
        x, Wq, Wk, Wv, Wo, poff, xhi, xlo, wqkvh, wqkvl, woh, wol, rtab);

    // fused QKV projection + RoPE + hi/lo quantization (one launch, 512 thr)
    gemm_qkv<<<dim3(NQKV / 128, ROWS / 128), 512, GEMM_SMEM_BYTES>>>(
        xhi, xlo, wqkvh, wqkvl, qhi, qlo, khi, klo, vhi, vlo, rtab);

    // attention -> writes hi/lo directly into xhi/xlo
    attn_mma<<<dim3(SEQ / 128, NHEADS, BATCH), 256, ATTN2_SMEM>>>(
        qhi, qlo, khi, klo, vhi, vlo, xhi, xlo);

    // O projection (512 thr)
    gemm_mma3<<<dim3(DMODEL / 128, ROWS / 128), 512, GEMM_SMEM_BYTES>>>(
        xhi, xlo, woh, wol, out, DMODEL);
}

// round 12
// speedup vs baseline: 5.0352x; 1.2411x over previous
#include <cuda_runtime.h>
#include <cuda_fp16.h>
#include <math.h>
#include <cstdint>

// Problem constants
#define BATCH 2
#define SEQ   2048
#define DMODEL 1024
#define NHEADS 16
#define NKV    4
#define HDIM   64
#define ROWS   (BATCH * SEQ)          // 4096
#define DKV    (NKV * HDIM)           // 256
#define KDIM   1024
#define NQKV   (DMODEL + 2 * DKV)     // 1536

// ---------------- scratch (static __device__, no allocation) ----------------
__device__ __half g_xhi[ROWS * DMODEL];     // x split; reused for attn out
__device__ __half g_xlo[ROWS * DMODEL];
__device__ __half g_Qhi[ROWS * DMODEL];
__device__ __half g_Qlo[ROWS * DMODEL];
__device__ __half g_Khi[ROWS * DKV];
__device__ __half g_Klo[ROWS * DKV];
__device__ __half g_Vhi[ROWS * DKV];
__device__ __half g_wqkv[NQKV * KDIM];      // transposed [N,K], fp16 (hi only)
__device__ __half g_wo[DMODEL * KDIM];
__device__ float2 g_rope[SEQ * 32];         // (cos, sin) per (s, j)

__device__ __forceinline__ uint32_t smem_u32(const void* p) {
    uint32_t a;
    asm("{ .reg .u64 t; cvta.to.shared.u64 t, %1; cvt.u32.u64 %0, t; }"
        : "=r"(a) : "l"(p));
    return a;
}
#define SMEM_SWIZZLE_128B(off) ((off) ^ (((off) >> 3) & 0x70))

__device__ __forceinline__ void ldsm_x4(uint32_t& r0, uint32_t& r1,
                                        uint32_t& r2, uint32_t& r3,
                                        uint32_t addr) {
    asm volatile("ldmatrix.sync.aligned.m8n8.x4.shared.b16 {%0,%1,%2,%3}, [%4];"
                 : "=r"(r0), "=r"(r1), "=r"(r2), "=r"(r3) : "r"(addr));
}
__device__ __forceinline__ void ldsm_x4_t(uint32_t& r0, uint32_t& r1,
                                          uint32_t& r2, uint32_t& r3,
                                          uint32_t addr) {
    asm volatile("ldmatrix.sync.aligned.m8n8.x4.trans.shared.b16 {%0,%1,%2,%3}, [%4];"
                 : "=r"(r0), "=r"(r1), "=r"(r2), "=r"(r3) : "r"(addr));
}
__device__ __forceinline__ void mma16816(float* c, const uint32_t* a,
                                         const uint32_t* b) {
    asm volatile(
        "mma.sync.aligned.m16n8k16.row.col.f32.f16.f16.f32 "
        "{%0,%1,%2,%3}, {%4,%5,%6,%7}, {%8,%9}, {%0,%1,%2,%3};"
        : "+f"(c[0]), "+f"(c[1]), "+f"(c[2]), "+f"(c[3])
        : "r"(a[0]), "r"(a[1]), "r"(a[2]), "r"(a[3]), "r"(b[0]), "r"(b[1]));
}
__device__ __forceinline__ uint32_t packhf(float lo, float hi) {
    __half2 t = __floats2half2_rn(lo, hi);   // .x -> low 16 bits
    return *reinterpret_cast<uint32_t*>(&t);
}
__device__ __forceinline__ float hres(float c) {
    return c - __half2float(__float2half_rn(c));
}
__device__ __forceinline__ void cp16(uint32_t s, const void* g) {
    asm volatile("cp.async.cg.shared.global [%0], [%1], 16;" :: "r"(s), "l"(g));
}
#define CP_COMMIT() asm volatile("cp.async.commit_group;")
#define CP_WAIT(n)  asm volatile("cp.async.wait_group %0;" :: "n"(n))

// ---------------- fused prep: x split + 4 weight transposes + rope table -----
__global__ void prep_kernel(const float* __restrict__ x,
                            const float* __restrict__ Wq,
                            const float* __restrict__ Wk,
                            const float* __restrict__ Wv,
                            const float* __restrict__ Wo,
                            const int* __restrict__ offset_ptr,
                            __half* __restrict__ xhi,
                            __half* __restrict__ xlo,
                            __half* __restrict__ wqkv,
                            __half* __restrict__ wo,
                            float2* __restrict__ ropeTab) {
    const int z = blockIdx.z;
    const int tx = threadIdx.x, ty = threadIdx.y;

    if (z == 4) {   // split x
        int i = (blockIdx.y * 128 + blockIdx.x) * 256 + ty * 32 + tx;
        float4 v = reinterpret_cast<const float4*>(x)[i];
        uint32_t* hp = reinterpret_cast<uint32_t*>(xhi) + 2 * i;
        uint32_t* lp = reinterpret_cast<uint32_t*>(xlo) + 2 * i;
        hp[0] = packhf(v.x, v.y); hp[1] = packhf(v.z, v.w);
        lp[0] = packhf(hres(v.x), hres(v.y));
        lp[1] = packhf(hres(v.z), hres(v.w));
        return;
    }
    if (z == 5) {   // rope table: 2048 x 32 entries
        int bid = blockIdx.y * 128 + blockIdx.x;
        if (bid >= 256) return;
        int i = bid * 256 + ty * 32 + tx;      // 0..65535
        int s = i >> 5, j = i & 31;
        float pos = (float)(s + offset_ptr[0]);
        float inv = powf(10000.0f, -(float)j / 32.0f);
        float ang = pos * inv;
        ropeTab[i] = make_float2(cosf(ang), sinf(ang));
        return;
    }

    const float* W;
    __half* hi;
    int N;
    if (z == 0)      { W = Wq; N = DMODEL; hi = wqkv; }
    else if (z == 1) { W = Wk; N = DKV; hi = wqkv + (size_t)DMODEL * KDIM; }
    else if (z == 2) { W = Wv; N = DKV; hi = wqkv + (size_t)(DMODEL + DKV) * KDIM; }
    else             { W = Wo; N = DMODEL; hi = wo; }

    int nb = blockIdx.x * 32;
    if (nb >= N) return;
    int kb = blockIdx.y * 32;

    __shared__ float tile[32][33];
    for (int i = ty; i < 32; i += 8)
        tile[i][tx] = W[(size_t)(kb + i) * N + nb + tx];
    __syncthreads();
    for (int i = ty; i < 32; i += 8) {
        float v = tile[tx][i];
        hi[(size_t)(nb + i) * KDIM + kb + tx] = __float2half_rn(v);
    }
}

// ---------------- shared GEMM mainloop (macro) --------------------------------
// 512 threads, 16 warps in 4m x 4n grid, warp tile 32x32.
// fp16 2-term: C = Ahi*B + Alo*B (B single fp16). 3 smem arrays per stage.
#define CHUNK 64
#define NCH   (KDIM / CHUNK)          // 16
#define STG_BYTES 49152               // Ahi 16K | Alo 16K | B 16K
#define GEMM_SMEM_BYTES (2 * STG_BYTES + 1024)

#define GQ_LOAD_CHUNK(ch_, stg_) do {                                          \
        const int k0_ = (ch_) * CHUNK;                                         \
        uint32_t sb0_ = smem_u32(sm + (stg_) * STG_BYTES);                     \
        _Pragma("unroll")                                                      \
        for (int ii = 0; ii < 2; ii++) {                                       \
            int idx_ = t + ii * 512;                                           \
            int row_ = idx_ >> 3;                                              \
            int c_ = idx_ & 7;                                                 \
            uint32_t sw_ = SMEM_SWIZZLE_128B((uint32_t)(row_ * 128 + c_ * 16));\
            size_t ao_ = (size_t)(rowBase + row_) * KDIM + k0_ + c_ * 8;       \
            size_t bo_ = (size_t)(colBase + row_) * KDIM + k0_ + c_ * 8;       \
            cp16(sb0_ + sw_, Ahi + ao_);                                       \
            cp16(sb0_ + 16384 + sw_, Alo + ao_);                               \
            cp16(sb0_ + 32768 + sw_, Bw + bo_);                                \
        }                                                                      \
    } while (0)

#define GQ_LOAD_FRAGS(s_) do {                                                 \
        _Pragma("unroll")                                                      \
        for (int mb = 0; mb < 2; mb++) {                                       \
            int row = warp_m * 32 + mb * 16 + a_row;                           \
            uint32_t sw = SMEM_SWIZZLE_128B(                                   \
                (uint32_t)(row * 128 + a_colB + (s_) * 32));                   \
            ldsm_x4(fa_hi[mb][0], fa_hi[mb][1], fa_hi[mb][2], fa_hi[mb][3],    \
                    aHi + sw);                                                 \
            ldsm_x4(fa_lo[mb][0], fa_lo[mb][1], fa_lo[mb][2], fa_lo[mb][3],    \
                    aLo + sw);                                                 \
        }                                                                      \
        _Pragma("unroll")                                                      \
        for (int p = 0; p < 2; p++) {                                          \
            int row = warp_n * 32 + p * 16 + b_rowl;                           \
            uint32_t sw = SMEM_SWIZZLE_128B(                                   \
                (uint32_t)(row * 128 + b_colB + (s_) * 32));                   \
            ldsm_x4(fb[2 * p][0], fb[2 * p][1],                                \
                    fb[2 * p + 1][0], fb[2 * p + 1][1], bW + sw);              \
        }                                                                      \
    } while (0)

#define GQ_MMA() do {                                                          \
        _Pragma("unroll")                                                      \
        for (int nb = 0; nb < 4; nb++)                                         \
            _Pragma("unroll")                                                  \
            for (int mb = 0; mb < 2; mb++)                                     \
                mma16816(acc[mb][nb], fa_hi[mb], fb[nb]);                      \
        _Pragma("unroll")                                                      \
        for (int nb = 0; nb < 4; nb++)                                         \
            _Pragma("unroll")                                                  \
            for (int mb = 0; mb < 2; mb++)                                     \
                mma16816(acc[mb][nb], fa_lo[mb], fb[nb]);                      \
    } while (0)

#define GEMM_MAINLOOP(Ahi, Alo, Bw)                                            \
    uint32_t base = (smem_u32(dsm) + 1023u) & ~1023u;                          \
    char* sm = dsm + (base - smem_u32(dsm));                                   \
    float acc[2][4][4];                                                        \
    _Pragma("unroll")                                                          \
    for (int mb = 0; mb < 2; mb++)                                             \
        _Pragma("unroll")                                                      \
        for (int nb = 0; nb < 4; nb++)                                         \
            _Pragma("unroll")                                                  \
            for (int q = 0; q < 4; q++) acc[mb][nb][q] = 0.f;                  \
    const int a_row = lid & 15;                                                \
    const int a_colB = (lid >> 4) * 16;                                        \
    const int b_rowl = ((lid >> 4) << 3) + (lid & 7);                          \
    const int b_colB = ((lid >> 3) & 1) * 16;                                  \
    uint32_t fa_hi[2][4], fa_lo[2][4];                                         \
    uint32_t fb[4][2];                                                         \
    GQ_LOAD_CHUNK(0, 0);                                                       \
    CP_COMMIT();                                                               \
    for (int ch = 0; ch < NCH; ch++) {                                         \
        CP_WAIT(0);                                                            \
        __syncthreads();                                                       \
        uint32_t stg0 = smem_u32(sm + (ch & 1) * STG_BYTES);                   \
        uint32_t aHi = stg0;                                                   \
        uint32_t aLo = stg0 + 16384;                                           \
        uint32_t bW = stg0 + 32768;                                            \
        _Pragma("unroll")                                                      \
        for (int s = 0; s < 4; s++) {                                          \
            GQ_LOAD_FRAGS(s);                                                  \
            if (s == 0 && ch + 1 < NCH) {                                      \
                GQ_LOAD_CHUNK(ch + 1, (ch + 1) & 1);                           \
                CP_COMMIT();                                                   \
            }                                                                  \
            GQ_MMA();                                                          \
        }                                                                      \
    }

// ---------------- GEMM with plain fp32 epilogue (O projection) ---------------
__global__ __launch_bounds__(512, 1) void gemm_mma3(
    const __half* __restrict__ Ahi, const __half* __restrict__ Alo,
    const __half* __restrict__ Bw,
    float* __restrict__ C, int Ncols) {
    extern __shared__ char dsm[];
    const int t = threadIdx.x;
    const int wid = t >> 5;
    const int lid = t & 31;
    const int warp_m = wid & 3;
    const int warp_n = wid >> 2;
    const int rowBase = blockIdx.y * 128;
    const int colBase = blockIdx.x * 128;

    GEMM_MAINLOOP(Ahi, Alo, Bw)

    const int g = lid >> 2;
    const int q = lid & 3;
#pragma unroll
    for (int mb = 0; mb < 2; mb++) {
#pragma unroll
        for (int nb = 0; nb < 4; nb++) {
            int row = rowBase + warp_m * 32 + mb * 16 + g;
            int col = colBase + warp_n * 32 + nb * 8 + q * 2;
            *reinterpret_cast<float2*>(&C[(size_t)row * Ncols + col]) =
                make_float2(acc[mb][nb][0], acc[mb][nb][1]);
            *reinterpret_cast<float2*>(&C[(size_t)(row + 8) * Ncols + col]) =
                make_float2(acc[mb][nb][2], acc[mb][nb][3]);
        }
    }
}

// ---------------- QKV GEMM with fused RoPE + hi/lo split epilogue ------------
__global__ __launch_bounds__(512, 1) void gemm_qkv(
    const __half* __restrict__ Ahi, const __half* __restrict__ Alo,
    const __half* __restrict__ Bw,
    __half* __restrict__ qhi, __half* __restrict__ qlo,
    __half* __restrict__ khi, __half* __restrict__ klo,
    __half* __restrict__ vhi,
    const float2* __restrict__ ropeTab) {
    extern __shared__ char dsm[];
    const int t = threadIdx.x;
    const int wid = t >> 5;
    const int lid = t & 31;
    const int warp_m = wid & 3;
    const int warp_n = wid >> 2;
    const int rowBase = blockIdx.y * 128;
    const int colBase = blockIdx.x * 128;

    GEMM_MAINLOOP(Ahi, Alo, Bw)

    const int g2 = lid >> 2;
    const int qd2 = (lid & 3) * 2;

    if (colBase >= DMODEL + DKV) {
        // V: plain fp16, direct from registers
        const int cb = colBase - DMODEL - DKV;
#pragma unroll
        for (int mb = 0; mb < 2; mb++) {
            int r0 = rowBase + warp_m * 32 + mb * 16 + g2;
#pragma unroll
            for (int nb = 0; nb < 4; nb++) {
                int col = cb + warp_n * 32 + nb * 8 + qd2;
                size_t o0 = (size_t)r0 * DKV + col;
                size_t o1 = (size_t)(r0 + 8) * DKV + col;
                *reinterpret_cast<uint32_t*>(vhi + o0) =
                    packhf(acc[mb][nb][0], acc[mb][nb][1]);
                *reinterpret_cast<uint32_t*>(vhi + o1) =
                    packhf(acc[mb][nb][2], acc[mb][nb][3]);
            }
        }
        return;
    }

    // Q/K: bounce accumulators through smem (stage-0) for cross-warp RoPE
    float* stile = reinterpret_cast<float*>(sm);   // [128][128], XOR swizzle
    __syncthreads();   // all warps done with final-chunk fragment reads
#pragma unroll
    for (int mb = 0; mb < 2; mb++) {
#pragma unroll
        for (int nb = 0; nb < 4; nb++) {
            int rl0 = warp_m * 32 + mb * 16 + g2;
            int cw = warp_n * 32 + nb * 8 + qd2;
            uint32_t w0 = rl0 * 128 + (cw ^ ((rl0 & 7) << 3));
            uint32_t w1 = (rl0 + 8) * 128 + (cw ^ (((rl0 + 8) & 7) << 3));
            *reinterpret_cast<float2*>(stile + w0) =
                make_float2(acc[mb][nb][0], acc[mb][nb][1]);
            *reinterpret_cast<float2*>(stile + w1) =
                make_float2(acc[mb][nb][2], acc[mb][nb][3]);
        }
    }
    __syncthreads();

    const bool isQ = colBase < DMODEL;
    const float sc = isQ ? 0.125f : 1.0f;   // 1/sqrt(64) folded into Q
    __half* Hhi = isQ ? qhi : khi;
    __half* Hlo = isQ ? qlo : klo;
    const int ncols = isQ ? DMODEL : DKV;
    const int cbase = isQ ? colBase : colBase - DMODEL;

    // 128 rows x 2 heads x 16 j-pairs = 4096 items, 512 threads -> 8 iters
#pragma unroll
    for (int it = 0; it < 8; it++) {
        int i = t + it * 512;
        int j2 = i & 15;
        int head = (i >> 4) & 1;
        int rl = i >> 5;                 // local row 0..127
        int j = 2 * j2;
        int c1 = head * 64 + j;
        uint32_t xr = (uint32_t)((rl & 7) << 3);
        float2 ab0 = *reinterpret_cast<float2*>(stile + rl * 128 + (c1 ^ xr));
        float2 ab1 = *reinterpret_cast<float2*>(stile + rl * 128 + ((c1 + 32) ^ xr));
        int grow = rowBase + rl;
        int srow = grow & (SEQ - 1);
        float2 cs0 = ropeTab[srow * 32 + j];
        float2 cs1 = ropeTab[srow * 32 + j + 1];
        float a0 = ab0.x, a1 = ab0.y, b0 = ab1.x, b1 = ab1.y;
        float q0 = (a0 * cs0.x - b0 * cs0.y) * sc;
        float q1 = (a1 * cs1.x - b1 * cs1.y) * sc;
        float u0 = (b0 * cs0.x + a0 * cs0.y) * sc;
        float u1 = (b1 * cs1.x + a1 * cs1.y) * sc;
        size_t o = (size_t)grow * ncols + cbase + c1;
        *reinterpret_cast<uint32_t*>(Hhi + o) = packhf(q0, q1);
        *reinterpret_cast<uint32_t*>(Hlo + o) = packhf(hres(q0), hres(q1));
        *reinterpret_cast<uint32_t*>(Hhi + o + 32) = packhf(u0, u1);
        *reinterpret_cast<uint32_t*>(Hlo + o + 32) = packhf(hres(u0), hres(u1));
    }
}

// ---------------- tensor-core flash attention (causal, GQA) ------------------
// S = 3-term fp16 (Q hi/lo x K hi/lo), PV = 2-term (P hi/lo x V fp16).
#define KV_STG 24576                  // Khi 8K | Klo 8K | Vhi 8K
#define ATTN2_SMEM (32768 + 2 * KV_STG + 1024)

__global__ __launch_bounds__(256, 1) void attn_mma(
    const __half* __restrict__ Qhi, const __half* __restrict__ Qlo,
    const __half* __restrict__ Khi, const __half* __restrict__ Klo,
    const __half* __restrict__ Vhi,
    __half* __restrict__ Ohi, __half* __restrict__ Olo) {
    extern __shared__ char dsm[];
    uint32_t base = (smem_u32(dsm) + 1023u) & ~1023u;
    char* sm = dsm + (base - smem_u32(dsm));
    char* sQhi = sm;            // 16KB
    char* sQlo = sm + 16384;    // 16KB

    const int qt = (int)gridDim.x - 1 - (int)blockIdx.x;   // heavy CTAs first
    const int h  = blockIdx.y;
    const int b  = blockIdx.z;
    const int hkv = h >> 2;
    const int t  = threadIdx.x;
    const int wid = t >> 5;
    const int lid = t & 31;
    const int g = lid >> 2;
    const int qd = lid & 3;
    const int q0 = qt * 128;

    const size_t kvbase = ((size_t)b * SEQ) * DKV + (size_t)hkv * HDIM;
    const int ntiles = 2 * qt + 2;

#define LOADKV(kt_, stg_) do {                                                  \
        const int k0_ = (kt_) * 64;                                            \
        uint32_t sb0_ = smem_u32(sm + 32768 + (stg_) * KV_STG);                 \
        _Pragma("unroll")                                                       \
        for (int ii = 0; ii < 2; ii++) {                                        \
            int idx_ = t + ii * 256;                                            \
            int row_ = idx_ >> 3;                                               \
            int ch_ = idx_ & 7;                                                 \
            uint32_t sw_ = SMEM_SWIZZLE_128B((uint32_t)(row_ * 128 + ch_ * 16));\
            size_t gl_ = kvbase + (size_t)(k0_ + row_) * DKV + ch_ * 8;         \
            cp16(sb0_ + sw_, Khi + gl_);                                        \
            cp16(sb0_ + 8192 + sw_, Klo + gl_);                                 \
            cp16(sb0_ + 16384 + sw_, Vhi + gl_);                                \
        }                                                                       \
    } while (0)

    // group A: Q hi/lo tiles via cp.async
    {
        const __half* Qh = Qhi + ((size_t)(b * SEQ + q0)) * DMODEL + h * HDIM;
        const __half* Ql = Qlo + ((size_t)(b * SEQ + q0)) * DMODEL + h * HDIM;
#pragma unroll
        for (int ii = 0; ii < 4; ii++) {
            int idx = t + ii * 256;        // 0..1023
            int row = idx >> 3;
            int ch = idx & 7;
            uint32_t sw = SMEM_SWIZZLE_128B((uint32_t)(row * 128 + ch * 16));
            size_t gl = (size_t)row * DMODEL + ch * 8;
            cp16(smem_u32(sQhi) + sw, Qh + gl);
            cp16(smem_u32(sQlo) + sw, Ql + gl);
        }
        CP_COMMIT();
    }
    // group B: KV tile 0
    LOADKV(0, 0);
    CP_COMMIT();

    CP_WAIT(1);        // Q tiles complete
    __syncthreads();

    // ---- Q fragments in registers
    uint32_t qh[4][4], ql[4][4];
    {
        int arow = wid * 16 + (lid & 15);
        int acolB = (lid >> 4) * 16;
#pragma unroll
        for (int s = 0; s < 4; s++) {
            uint32_t sw = SMEM_SWIZZLE_128B((uint32_t)(arow * 128 + acolB + s * 32));
            ldsm_x4(qh[s][0], qh[s][1], qh[s][2], qh[s][3], smem_u32(sQhi) + sw);
            ldsm_x4(ql[s][0], ql[s][1], ql[s][2], ql[s][3], smem_u32(sQlo) + sw);
        }
    }

    float o[8][4];
#pragma unroll
    for (int nb = 0; nb < 8; nb++)
#pragma unroll
        for (int q = 0; q < 4; q++) o[nb][q] = 0.f;
    float m0 = -1e30f, m1 = -1e30f, l0 = 0.f, l1 = 0.f;

    for (int kt = 0; kt < ntiles; kt++) {
        const int k0 = kt * 64;
        if (kt + 1 < ntiles) {
            LOADKV(kt + 1, (kt + 1) & 1);
            CP_COMMIT();
            CP_WAIT(1);
        } else {
            CP_WAIT(0);
        }
        __syncthreads();

        uint32_t kvb = smem_u32(sm + 32768 + (kt & 1) * KV_STG);
        uint32_t sKhi_ = kvb;
        uint32_t sKlo_ = kvb + 8192;
        uint32_t sVhi_ = kvb + 16384;

        // ---- S = Q K^T (3-term fp16, term-major issue)
        float sacc[8][4];
#pragma unroll
        for (int nb = 0; nb < 8; nb++)
#pragma unroll
            for (int q = 0; q < 4; q++) sacc[nb][q] = 0.f;

        {
            int brow = ((lid >> 4) << 3) + (lid & 7);
            int bcolB = ((lid >> 3) & 1) * 16;
#pragma unroll
            for (int s = 0; s < 4; s++) {
                uint32_t kh[8][2], kl[8][2];
#pragma unroll
                for (int p = 0; p < 4; p++) {
                    uint32_t sw = SMEM_SWIZZLE_128B(
                        (uint32_t)((p * 16 + brow) * 128 + bcolB + s * 32));
                    ldsm_x4(kh[2 * p][0], kh[2 * p][1], kh[2 * p + 1][0],
                            kh[2 * p + 1][1], sKhi_ + sw);
                    ldsm_x4(kl[2 * p][0], kl[2 * p][1], kl[2 * p + 1][0],
                            kl[2 * p + 1][1], sKlo_ + sw);
                }
#pragma unroll
                for (int nb = 0; nb < 8; nb++)
                    mma16816(sacc[nb], qh[s], kh[nb]);
#pragma unroll
                for (int nb = 0; nb < 8; nb++)
                    mma16816(sacc[nb], qh[s], kl[nb]);
#pragma unroll
                for (int nb = 0; nb < 8; nb++)
                    mma16816(sacc[nb], ql[s], kh[nb]);
            }
        }

        // ---- causal mask (only diagonal tiles)
        if (kt >= 2 * qt) {
            int rowa = q0 + wid * 16 + g;
#pragma unroll
            for (int nb = 0; nb < 8; nb++) {
                int col = k0 + nb * 8 + qd * 2;
                if (col > rowa)     sacc[nb][0] = -1e30f;
                if (col + 1 > rowa) sacc[nb][1] = -1e30f;
                if (col > rowa + 8)     sacc[nb][2] = -1e30f;
                if (col + 1 > rowa + 8) sacc[nb][3] = -1e30f;
            }
        }

        // ---- online softmax
        {
            float mx0 = -1e30f, mx1 = -1e30f;
#pragma unroll
            for (int nb = 0; nb < 8; nb++) {
                mx0 = fmaxf(mx0, fmaxf(sacc[nb][0], sacc[nb][1]));
                mx1 = fmaxf(mx1, fmaxf(sacc[nb][2], sacc[nb][3]));
            }
            mx0 = fmaxf(mx0, __shfl_xor_sync(0xffffffff, mx0, 1));
            mx0 = fmaxf(mx0, __shfl_xor_sync(0xffffffff, mx0, 2));
            mx1 = fmaxf(mx1, __shfl_xor_sync(0xffffffff, mx1, 1));
            mx1 = fmaxf(mx1, __shfl_xor_sync(0xffffffff, mx1, 2));
            float mn0 = fmaxf(m0, mx0), mn1 = fmaxf(m1, mx1);
            float al0 = __expf(m0 - mn0), al1 = __expf(m1 - mn1);
            m0 = mn0; m1 = mn1;
            l0 *= al0; l1 *= al1;
            float la0 = 0.f, la1 = 0.f;
#pragma unroll
            for (int nb = 0; nb < 8; nb++) {
                sacc[nb][0] = __expf(sacc[nb][0] - mn0);
                sacc[nb][1] = __expf(sacc[nb][1] - mn0);
                sacc[nb][2] = __expf(sacc[nb][2] - mn1);
                sacc[nb][3] = __expf(sacc[nb][3] - mn1);
                la0 += sacc[nb][0] + sacc[nb][1];
                la1 += sacc[nb][2] + sacc[nb][3];
                o[nb][0] *= al0; o[nb][1] *= al0;
                o[nb][2] *= al1; o[nb][3] *= al1;
            }
            l0 += la0; l1 += la1;
        }

        // ---- pack P hi/lo as A-fragments (fp16)
        uint32_t ph[4][4], pl[4][4];
#pragma unroll
        for (int j = 0; j < 4; j++) {
            float* c = sacc[2 * j];
            float* d = sacc[2 * j + 1];
            ph[j][0] = packhf(c[0], c[1]);
            ph[j][1] = packhf(c[2], c[3]);
            ph[j][2] = packhf(d[0], d[1]);
            ph[j][3] = packhf(d[2], d[3]);
            pl[j][0] = packhf(hres(c[0]), hres(c[1]));
            pl[j][1] = packhf(hres(c[2]), hres(c[3]));
            pl[j][2] = packhf(hres(d[0]), hres(d[1]));
            pl[j][3] = packhf(hres(d[2]), hres(d[3]));
        }

        // ---- O += P V (2-term: P hi/lo x V fp16), V via ldmatrix.trans
        {
            int vrow = (lid & 15);
            int vcolB = (lid >> 4) * 16;
#pragma unroll
            for (int j = 0; j < 4; j++) {
                uint32_t vh[8][2];
#pragma unroll
                for (int dj = 0; dj < 4; dj++) {
                    uint32_t sw = SMEM_SWIZZLE_128B(
                        (uint32_t)((j * 16 + vrow) * 128 + dj * 32 + vcolB));
                    ldsm_x4_t(vh[2 * dj][0], vh[2 * dj][1], vh[2 * dj + 1][0],
                              vh[2 * dj + 1][1], sVhi_ + sw);
                }
#pragma unroll
                for (int nb = 0; nb < 8; nb++)
                    mma16816(o[nb], ph[j], vh[nb]);
#pragma unroll
                for (int nb = 0; nb < 8; nb++)
                    mma16816(o[nb], pl[j], vh[nb]);
            }
        }
        __syncthreads();
    }
#undef LOADKV

    // ---- finalize: normalize, write fp16 hi/lo (fused split)
    l0 += __shfl_xor_sync(0xffffffff, l0, 1);
    l0 += __shfl_xor_sync(0xffffffff, l0, 2);
    l1 += __shfl_xor_sync(0xffffffff, l1, 1);
    l1 += __shfl_xor_sync(0xffffffff, l1, 2);
    float inv0 = 1.0f / l0, inv1 = 1.0f / l1;

    int rowa = q0 + wid * 16 + g;
    size_t oa = ((size_t)(b * SEQ + rowa)) * DMODEL + h * HDIM;
    size_t ob = ((size_t)(b * SEQ + rowa + 8)) * DMODEL + h * HDIM;
#pragma unroll
    for (int nb = 0; nb < 8; nb++) {
        int col = nb * 8 + qd * 2;
        float a0 = o[nb][0] * inv0, a1 = o[nb][1] * inv0;
        float b0 = o[nb][2] * inv1, b1 = o[nb][3] * inv1;
        *reinterpret_cast<uint32_t*>(Ohi + oa + col) = packhf(a0, a1);
        *reinterpret_cast<uint32_t*>(Olo + oa + col) = packhf(hres(a0), hres(a1));
        *reinterpret_cast<uint32_t*>(Ohi + ob + col) = packhf(b0, b1);
        *reinterpret_cast<uint32_t*>(Olo + ob + col) = packhf(hres(b0), hres(b1));
    }
}

// ---------------- launch ------------------------------------------------------
extern "C" void kernel_launch(void* const* d_in, const int* in_sizes, int n_in,
                              void* d_out, int out_size) {
    (void)in_sizes; (void)n_in; (void)out_size;
    const float* x  = (const float*)d_in[0];
    const float* Wq = (const float*)d_in[1];
    const float* Wk = (const float*)d_in[2];
    const float* Wv = (const float*)d_in[3];
    const float* Wo = (const float*)d_in[4];
    const int* poff = (const int*)d_in[5];
    float* out = (float*)d_out;

    __half *xhi, *xlo, *qhi, *qlo, *khi, *klo, *vhi, *wqkv, *wo;
    float2* rtab;
    cudaGetSymbolAddress((void**)&xhi, g_xhi);
    cudaGetSymbolAddress((void**)&xlo, g_xlo);
    cudaGetSymbolAddress((void**)&qhi, g_Qhi);
    cudaGetSymbolAddress((void**)&qlo, g_Qlo);
    cudaGetSymbolAddress((void**)&khi, g_Khi);
    cudaGetSymbolAddress((void**)&klo, g_Klo);
    cudaGetSymbolAddress((void**)&vhi, g_Vhi);
    cudaGetSymbolAddress((void**)&wqkv, g_wqkv);
    cudaGetSymbolAddress((void**)&wo, g_wo);
    cudaGetSymbolAddress((void**)&rtab, g_rope);

    cudaFuncSetAttribute(gemm_mma3, cudaFuncAttributeMaxDynamicSharedMemorySize,
                         GEMM_SMEM_BYTES);
    cudaFuncSetAttribute(gemm_qkv, cudaFuncAttributeMaxDynamicSharedMemorySize,
                         GEMM_SMEM_BYTES);
    cudaFuncSetAttribute(attn_mma, cudaFuncAttributeMaxDynamicSharedMemorySize,
                         ATTN2_SMEM);

    // fused prep: x split + weight transposes + rope table (one launch)
    prep_kernel<<<dim3(128, 32, 6), dim3(32, 8)>>>(
        x, Wq, Wk, Wv, Wo, poff, xhi, xlo, wqkv, wo, rtab);

    // fused QKV projection + RoPE + hi/lo quantization (512 thr)
    gemm_qkv<<<dim3(NQKV / 128, ROWS / 128), 512, GEMM_SMEM_BYTES>>>(
        xhi, xlo, wqkv, qhi, qlo, khi, klo, vhi, rtab);

    // attention -> writes hi/lo directly into xhi/xlo
    attn_mma<<<dim3(SEQ / 128, NHEADS, BATCH), 256, ATTN2_SMEM>>>(
        qhi, qlo, khi, klo, vhi, xhi, xlo);

    // O projection (512 thr)
    gemm_mma3<<<dim3(DMODEL / 128, ROWS / 128), 512, GEMM_SMEM_BYTES>>>(
        xhi, xlo, wo, out, DMODEL);
}